// round 11
// baseline (speedup 1.0000x reference)
#include <cuda_runtime.h>
#include <cuda.h>
#include <math.h>
#include <stdint.h>

#define Bsz  8
#define Cdim 256
#define Ntok 4096
#define ROWS (Bsz * Ntok)          // 32768 token rows
#define C4   (4 * Cdim)            // 1024

// ---------------- scratch (static device arrays; no allocation) ----------------
__device__ float g_x1[(size_t)ROWS * Cdim];
__device__ float g_sm[(size_t)ROWS * Cdim];
__device__ float g_u[(size_t)ROWS * Cdim];         // transpose scratch
__device__ float g_cat2[(size_t)ROWS * C4];        // [out | v | mlp], ld=1024
__device__ float g_ctx[(size_t)Bsz * Cdim * Cdim]; // ctxT[d][c]
__device__ float g_mu[ROWS];
__device__ float g_rinv[ROWS];
__device__ float g_Wg[(size_t)Cdim * C4];
__device__ float g_S1[Cdim];
__device__ float g_S2[Cdim];
__device__ float g_stats[4 * ROWS];                // rsum0|rsq0|rsum1|rsq1

#if defined(__CUDA_ARCH_FEAT_SM103_ALL) || defined(__CUDA_ARCH_FEAT_SM100_ALL)
#define HAS_TCGEN05 1
#else
#define HAS_TCGEN05 0
#endif

// ================= helpers ======================================================
__device__ __forceinline__ uint32_t smem_u32(const void* p) {
    return (uint32_t)__cvta_generic_to_shared(p);
}
__device__ __forceinline__ uint32_t elect1() {
    uint32_t pred;
    asm volatile("{\n\t.reg .pred p;\n\telect.sync _|p, 0xFFFFFFFF;\n\tselp.b32 %0, 1, 0, p;\n\t}"
                 : "=r"(pred));
    return pred;
}
__device__ __forceinline__ void mbar_init(uint32_t a, uint32_t cnt) {
    asm volatile("mbarrier.init.shared.b64 [%0], %1;" :: "r"(a), "r"(cnt) : "memory");
}
__device__ __forceinline__ void mbar_wait(uint32_t a, int ph) {
    asm volatile(
        "{\n\t.reg .pred P;\n\t"
        "WL%=:\n\t"
        "mbarrier.try_wait.parity.acquire.cta.shared::cta.b64 P, [%0], %1, 0x989680;\n\t"
        "@P bra.uni WD%=;\n\t"
        "bra.uni WL%=;\n\t"
        "WD%=:\n\t}"
        :: "r"(a), "r"(ph) : "memory");
}
__device__ __forceinline__ void mbar_expect_tx(uint32_t a, uint32_t bytes) {
    asm volatile("mbarrier.arrive.expect_tx.shared.b64 _, [%0], %1;"
                 :: "r"(a), "r"(bytes) : "memory");
}
__device__ __forceinline__ void tma3d(uint32_t dst, const void* map, int x, int y, int z,
                                      uint32_t mbar) {
    asm volatile(
        "cp.async.bulk.tensor.3d.shared::cta.global.tile.mbarrier::complete_tx::bytes "
        "[%0], [%1, {%2, %3, %4}], [%5];"
        :: "r"(dst), "l"(map), "r"(x), "r"(y), "r"(z), "r"(mbar) : "memory");
}
#define SW128B(o) ((o) ^ (((o) >> 3) & 0x70))

static constexpr unsigned long long DESC_SW128 =
    (2ull << 61) | (1ull << 46) | (64ull << 32) | (1ull << 16);
__device__ __forceinline__ uint64_t mk_desc(uint32_t addr) {
    return DESC_SW128 | ((uint64_t)(addr >> 4) & 0x3FFF);
}

__device__ __forceinline__ uint32_t cvt_tf32(float x) {
    uint32_t r;
    asm("cvt.rna.tf32.f32 %0, %1;" : "=r"(r) : "f"(x));
    return r;
}
__device__ __forceinline__ void cp16(float* s, const float* g) {
    uint32_t sa = smem_u32(s);
    asm volatile("cp.async.cg.shared.global [%0], [%1], 16;" :: "r"(sa), "l"(g));
}
__device__ __forceinline__ void cp_commit() { asm volatile("cp.async.commit_group;" ::); }
template <int N>
__device__ __forceinline__ void cp_wait() { asm volatile("cp.async.wait_group %0;" :: "n"(N)); }

__device__ __forceinline__ void mma8(float* c, const uint32_t* a, const uint32_t* b) {
    asm volatile(
        "mma.sync.aligned.m16n8k8.row.col.f32.tf32.tf32.f32 "
        "{%0,%1,%2,%3}, {%4,%5,%6,%7}, {%8,%9}, {%0,%1,%2,%3};"
        : "+f"(c[0]), "+f"(c[1]), "+f"(c[2]), "+f"(c[3])
        : "r"(a[0]), "r"(a[1]), "r"(a[2]), "r"(a[3]), "r"(b[0]), "r"(b[1]));
}

#define LDTM32(d, addr)                                                          \
    asm volatile(                                                                \
        "tcgen05.ld.sync.aligned.32x32b.x32.b32 "                                \
        "{%0, %1, %2, %3, %4, %5, %6, %7, "                                      \
        " %8, %9, %10, %11, %12, %13, %14, %15, "                                \
        " %16, %17, %18, %19, %20, %21, %22, %23, "                              \
        " %24, %25, %26, %27, %28, %29, %30, %31}, [%32];"                       \
        : "=r"(d[0]), "=r"(d[1]), "=r"(d[2]), "=r"(d[3]),                        \
          "=r"(d[4]), "=r"(d[5]), "=r"(d[6]), "=r"(d[7]),                        \
          "=r"(d[8]), "=r"(d[9]), "=r"(d[10]), "=r"(d[11]),                      \
          "=r"(d[12]), "=r"(d[13]), "=r"(d[14]), "=r"(d[15]),                    \
          "=r"(d[16]), "=r"(d[17]), "=r"(d[18]), "=r"(d[19]),                    \
          "=r"(d[20]), "=r"(d[21]), "=r"(d[22]), "=r"(d[23]),                    \
          "=r"(d[24]), "=r"(d[25]), "=r"(d[26]), "=r"(d[27]),                    \
          "=r"(d[28]), "=r"(d[29]), "=r"(d[30]), "=r"(d[31])                     \
        : "r"(addr));                                                            \
    asm volatile("tcgen05.wait::ld.sync.aligned;" ::: "memory")

// ================= unified NT GEMM, CTA tile 128 x NTILE, TMA mainloop =========
// EPI: 0 plain | 4 store+stats | 5 relu+bias+stats |
//      8 qkv fused (x1 + softmax + v-copy + stats) |
//      16 res+LN2 -> vout + next stats | 17 res+LN2 -> transposed outT
#define TS 65                         // epilogue smem tile stride (floats)

__device__ __forceinline__ void nt_stage(const float* __restrict__ A, int lda,
                                         const float* __restrict__ B, int ldb,
                                         int bm, int bn, int k0,
                                         float* as, float* bs, int tid) {
#pragma unroll
    for (int i = 0; i < 4; i++) {
        int idx = tid + i * 256;
        int row = idx >> 3, c4 = (idx & 7) << 2;
        cp16(as + row * 36 + c4, A + (size_t)(bm + row) * lda + k0 + c4);
        cp16(bs + row * 36 + c4, B + (size_t)(bn + row) * ldb + k0 + c4);
    }
    cp_commit();
}

template <int EPI, int NTILE>
__global__ __launch_bounds__(256)
void gemm_t5(const __grid_constant__ CUtensorMap tmA,
             const __grid_constant__ CUtensorMap tmB,
             const float* __restrict__ A, int lda, long long sA,
             const float* __restrict__ B, int ldb, long long sB,
             float* __restrict__ C, int ldc, long long sC, int K,
             const float* __restrict__ bias,
             const float* __restrict__ resid, int ldr,
             const float* __restrict__ mu, const float* __restrict__ rinv,
             const float* __restrict__ S1, const float* __restrict__ S2,
             float* __restrict__ rsum, float* __restrict__ rsq, long long sStat,
             float* __restrict__ smx, float* __restrict__ vout,
             const float* __restrict__ g2, const float* __restrict__ b2,
             float* __restrict__ outT) {
    extern __shared__ char smem[];
    const int tid = threadIdx.x, wid = tid >> 5, lane = tid & 31;
    const int bz = blockIdx.z;
    C += (size_t)bz * sC;
    if (EPI == 4 || EPI == 5) { rsum += (size_t)bz * sStat; rsq += (size_t)bz * sStat; }
    const int bm = blockIdx.y * 128, bn = blockIdx.x * NTILE;
    constexpr int STG = 16384 + NTILE * 128;   // A 16K + B NTILE*128

#if HAS_TCGEN05
    uint32_t sb = smem_u32(smem);
    if (wid == 0) {
        asm volatile("tcgen05.alloc.cta_group::1.sync.aligned.shared::cta.b32 [%0], %1;"
                     :: "r"(sb), "r"(NTILE) : "memory");
        asm volatile("tcgen05.relinquish_alloc_permit.cta_group::1.sync.aligned;");
    }
    // mbars: +8 full0, +16 full1, +24 empty0, +32 empty1
    if (tid == 0) {
        mbar_init(sb + 8, 1); mbar_init(sb + 16, 1);
        mbar_init(sb + 24, 1); mbar_init(sb + 32, 1);
    }
    __syncthreads();
    uint32_t tmem;
    asm volatile("ld.shared.b32 %0, [%1];" : "=r"(tmem) : "r"(sb));

    const int KT = K / 32;
    const uint32_t IDESC = (1u << 4) | (2u << 7) | (2u << 10) | (32u << 17) | (8u << 24);

    if (wid == 0 && elect1()) {
#pragma unroll
        for (int s = 0; s < 2; s++) {
            uint32_t full = sb + 8 + s * 8;
            uint32_t dst = sb + 1024 + s * STG;
            mbar_expect_tx(full, STG);
            tma3d(dst, &tmA, s * 32, bm, bz, full);
            tma3d(dst + 16384, &tmB, s * 32, bn, bz, full);
            if (NTILE == 512)
                tma3d(dst + 16384 + 32768, &tmB, s * 32, bn + 256, bz, full);
        }
        int fph[2] = {0, 0}, eph[2] = {0, 0};
        for (int kt = 0; kt < KT; kt++) {
            int buf = kt & 1;
            mbar_wait(sb + 8 + buf * 8, fph[buf]); fph[buf] ^= 1;
            uint32_t base = sb + 1024 + buf * STG;
            uint64_t ad = mk_desc(base);
            uint64_t bd = mk_desc(base + 16384);
#pragma unroll
            for (int s = 0; s < 4; s++) {
                uint32_t en = (kt > 0 || s > 0) ? 1u : 0u;
                asm volatile(
                    "{\n\t.reg .pred p;\n\tsetp.ne.u32 p, %5, 0;\n\t"
                    "tcgen05.mma.cta_group::1.kind::tf32 [%0], %1, %2, %3, {%4,%4,%4,%4}, p;\n\t}"
                    :: "r"(tmem), "l"(ad + s * 2), "l"(bd + s * 2), "r"(IDESC),
                       "r"(0u), "r"(en) : "memory");
                if (NTILE == 512) {
                    uint64_t bd2 = mk_desc(base + 16384 + 32768);
                    asm volatile(
                        "{\n\t.reg .pred p;\n\tsetp.ne.u32 p, %5, 0;\n\t"
                        "tcgen05.mma.cta_group::1.kind::tf32 [%0], %1, %2, %3, {%4,%4,%4,%4}, p;\n\t}"
                        :: "r"(tmem + 256), "l"(ad + s * 2), "l"(bd2 + s * 2), "r"(IDESC),
                           "r"(0u), "r"(en) : "memory");
                }
            }
            asm volatile(
                "tcgen05.commit.cta_group::1.mbarrier::arrive::one.shared::cluster.b64 [%0];"
                :: "r"(sb + 24 + buf * 8) : "memory");
            if (kt + 2 < KT) {
                mbar_wait(sb + 24 + buf * 8, eph[buf]); eph[buf] ^= 1;
                uint32_t full = sb + 8 + buf * 8;
                mbar_expect_tx(full, STG);
                tma3d(base, &tmA, (kt + 2) * 32, bm, bz, full);
                tma3d(base + 16384, &tmB, (kt + 2) * 32, bn, bz, full);
                if (NTILE == 512)
                    tma3d(base + 16384 + 32768, &tmB, (kt + 2) * 32, bn + 256, bz, full);
            }
        }
    }
    __syncthreads();
    mbar_wait(sb + 24 + ((KT - 1) & 1) * 8, (KT / 2 - 1) & 1);
    asm volatile("tcgen05.fence::after_thread_sync;" ::: "memory");

    const int rl = (wid & 3) * 32 + lane;     // local row 0..127 (TMEM lane)
    const int row = bm + rl;
    const int half = wid >> 2;
    const int cb = half * (NTILE / 2);
    float* s0 = (float*)(smem + 1024);        // [256] sum partials
    float* s1 = s0 + 256;                     // [256] sumsq partials
    float* s2 = s1 + 256;                     // [256] expsum partials
    float* s3 = s2 + 256;                     // [128] per-row scalar (softmax inv)
    float* tile = s3 + 256;                   // [128][TS] staging tile

    if (EPI == 17) {
        // ---- res+LN2 -> transposed out; column-plane stores coalesced (NTILE 256) ----
        float rv = rinv[row], mm = mu[row];
        float ps = 0.f, pq = 0.f;
#pragma unroll
        for (int cc = 0; cc < 4; cc++) {
            uint32_t d[32];
            LDTM32(d, tmem + cb + cc * 32);
#pragma unroll
            for (int j = 0; j < 32; j++) {
                int c = cb + cc * 32 + j;
                float val = fmaf(rv, __uint_as_float(d[j]) - mm * S1[c], S2[c]) +
                            2.f * resid[(size_t)row * ldr + c];
                ps += val; pq += val * val;
            }
        }
        s0[half * 128 + rl] = ps;
        s1[half * 128 + rl] = pq;
        __syncthreads();
        float ts = s0[rl] + s0[128 + rl];
        float tq = s1[rl] + s1[128 + rl];
        float mu2 = ts * (1.f / 256.f);
        float r2 = rsqrtf(tq * (1.f / 256.f) - mu2 * mu2 + 1e-5f);
#pragma unroll
        for (int cc = 0; cc < 4; cc++) {
            uint32_t d[32];
            LDTM32(d, tmem + cb + cc * 32);
#pragma unroll
            for (int j = 0; j < 32; j++) {
                int c = cb + cc * 32 + j;
                float val = fmaf(rv, __uint_as_float(d[j]) - mm * S1[c], S2[c]) +
                            2.f * resid[(size_t)row * ldr + c];
                val = (val - mu2) * r2 * g2[c] + b2[c];
                int b = row >> 12, n = row & 4095;
                outT[((size_t)b * Cdim + c) * Ntok + n] = val;
            }
        }
    } else if (EPI == 8 || EPI == 16) {
        // ---- fused two-pass epilogue with smem-staged coalesced stores (NTILE 256) ----
        float rv = 0.f, mm = 0.f;
        if (EPI == 16) { rv = rinv[row]; mm = mu[row]; }
        float ps = 0.f, pq = 0.f, pe = 0.f;
#pragma unroll
        for (int cc = 0; cc < 4; cc++) {
            uint32_t d[32];
            LDTM32(d, tmem + cb + cc * 32);
#pragma unroll
            for (int j = 0; j < 32; j++) {
                float val = __uint_as_float(d[j]);
                if (EPI == 16) {
                    int c = cb + cc * 32 + j;
                    val = fmaf(rv, val - mm * S1[c], S2[c]) +
                          2.f * resid[(size_t)row * ldr + c];
                }
                ps += val; pq += val * val;
                if (EPI == 8) pe += __expf(val);
            }
        }
        s0[half * 128 + rl] = ps;
        s1[half * 128 + rl] = pq;
        if (EPI == 8) s2[half * 128 + rl] = pe;
        __syncthreads();
        float ts = s0[rl] + s0[128 + rl];
        float tq = s1[rl] + s1[128 + rl];
        float mu2 = 0.f, r2 = 0.f;
        if (EPI == 8) {
            float inv = 1.f / (s2[rl] + s2[128 + rl]);
            if (half == 0) s3[rl] = inv;
        } else {
            mu2 = ts * (1.f / 256.f);
            r2 = rsqrtf(tq * (1.f / 256.f) - mu2 * mu2 + 1e-5f);
        }
        float vs = 0.f, vq = 0.f;
#pragma unroll
        for (int cc = 0; cc < 4; cc++) {
            uint32_t d[32];
            LDTM32(d, tmem + cb + cc * 32);
#pragma unroll
            for (int j = 0; j < 32; j++) {
                float val = __uint_as_float(d[j]);
                if (EPI == 16) {
                    int c = cb + cc * 32 + j;
                    val = fmaf(rv, val - mm * S1[c], S2[c]) +
                          2.f * resid[(size_t)row * ldr + c];
                    val = (val - mu2) * r2 * g2[c] + b2[c];
                    vs += val; vq += val * val;
                }
                tile[rl * TS + half * 32 + j] = val;
            }
            __syncthreads();
#pragma unroll
            for (int it2 = 0; it2 < 4; it2++) {
                int r = it2 * 32 + (tid >> 3);
                int cq = (tid & 7) * 4;
                size_t gr = (size_t)(bm + r);
#pragma unroll
                for (int h = 0; h < 2; h++) {
                    int c = h * 128 + cc * 32 + cq;
                    float4 v4;
                    v4.x = tile[r * TS + h * 32 + cq + 0];
                    v4.y = tile[r * TS + h * 32 + cq + 1];
                    v4.z = tile[r * TS + h * 32 + cq + 2];
                    v4.w = tile[r * TS + h * 32 + cq + 3];
                    if (EPI == 8) {
                        *(float4*)(C + gr * ldc + c) = v4;
                        *(float4*)(vout + gr * C4 + c) = v4;
                        float iv = s3[r];
                        float4 e = make_float4(__expf(v4.x) * iv, __expf(v4.y) * iv,
                                               __expf(v4.z) * iv, __expf(v4.w) * iv);
                        *(float4*)(smx + gr * Cdim + c) = e;
                    } else {
                        *(float4*)(vout + gr * C4 + c) = v4;
                    }
                }
            }
            __syncthreads();
        }
        if (EPI == 16) { atomicAdd(rsum + row, vs); atomicAdd(rsq + row, vq); }
        if (EPI == 8 && half == 0) { atomicAdd(rsum + row, ts); atomicAdd(rsq + row, tq); }
    } else {
        // ---- EPI 0/4/5: streaming via smem-staged coalesced store (any NTILE) ----
        float ssum = 0.f, ssq = 0.f;
#pragma unroll
        for (int cc = 0; cc < NTILE / 64; cc++) {
            uint32_t d[32];
            LDTM32(d, tmem + cb + cc * 32);
#pragma unroll
            for (int j = 0; j < 32; j++) {
                float val = __uint_as_float(d[j]);
                if (EPI & 1) val = fmaxf(val + bias[bn + cb + cc * 32 + j], 0.f);
                if (EPI & 4) { ssum += val; ssq += val * val; }
                tile[rl * TS + half * 32 + j] = val;
            }
            __syncthreads();
#pragma unroll
            for (int it2 = 0; it2 < 4; it2++) {
                int r = it2 * 32 + (tid >> 3);
                int cq = (tid & 7) * 4;
                size_t gr = (size_t)(bm + r);
#pragma unroll
                for (int h = 0; h < 2; h++) {
                    int c = bn + h * (NTILE / 2) + cc * 32 + cq;
                    float4 v4;
                    v4.x = tile[r * TS + h * 32 + cq + 0];
                    v4.y = tile[r * TS + h * 32 + cq + 1];
                    v4.z = tile[r * TS + h * 32 + cq + 2];
                    v4.w = tile[r * TS + h * 32 + cq + 3];
                    *(float4*)(C + gr * ldc + c) = v4;
                }
            }
            __syncthreads();
        }
        if (EPI & 4) {
            atomicAdd(rsum + row, ssum);
            atomicAdd(rsq + row, ssq);
        }
    }
    __syncthreads();
    if (wid == 0) {
        asm volatile("tcgen05.dealloc.cta_group::1.sync.aligned.b32 %0, %1;"
                     :: "r"(tmem), "r"(NTILE));
    }
#else
    // -------- legacy fallback (compile-only on non-'a' targets) --------
    float* fsm = (float*)smem;
    constexpr int ABUF = 128 * 36;
    float* As = fsm;
    float* Bs = fsm + 2 * ABUF;
    const int wm = (wid >> 2) * 64, wn = (wid & 3) * 32;
    const int lq = lane >> 2, lr = lane & 3;
    const float* Ab = A + (size_t)bz * sA;
    const float* Bb = B + (size_t)bz * sB;
    for (int hf = 0; hf < NTILE / 128; hf++) {
        int bnh = bn + hf * 128;
        float acc[4][4][4];
#pragma unroll
        for (int i = 0; i < 4; i++)
#pragma unroll
            for (int j = 0; j < 4; j++)
#pragma unroll
                for (int t = 0; t < 4; t++) acc[i][j][t] = 0.f;
        const int KT = K / 32;
        nt_stage(Ab, lda, Bb, ldb, bm, bnh, 0, As, Bs, tid);
        for (int kt = 0; kt < KT; kt++) {
            int buf = kt & 1;
            if (kt + 1 < KT) {
                nt_stage(Ab, lda, Bb, ldb, bm, bnh, (kt + 1) * 32,
                         As + ((kt + 1) & 1) * ABUF, Bs + ((kt + 1) & 1) * ABUF, tid);
                cp_wait<1>();
            } else cp_wait<0>();
            __syncthreads();
            const float* as = As + buf * ABUF;
            const float* bs = Bs + buf * ABUF;
#pragma unroll
            for (int kk = 0; kk < 4; kk++) {
                const int k0 = kk * 8;
                uint32_t af[4][4], bf[4][2];
#pragma unroll
                for (int i = 0; i < 4; i++) {
                    const float* p = as + (wm + i * 16 + lq) * 36 + k0 + lr;
                    af[i][0] = cvt_tf32(p[0]);
                    af[i][2] = cvt_tf32(p[4]);
                    const float* p8 = p + 8 * 36;
                    af[i][1] = cvt_tf32(p8[0]);
                    af[i][3] = cvt_tf32(p8[4]);
                }
#pragma unroll
                for (int j = 0; j < 4; j++) {
                    const float* p = bs + (wn + j * 8 + lq) * 36 + k0 + lr;
                    bf[j][0] = cvt_tf32(p[0]);
                    bf[j][1] = cvt_tf32(p[4]);
                }
#pragma unroll
                for (int i = 0; i < 4; i++)
#pragma unroll
                    for (int j = 0; j < 4; j++) mma8(acc[i][j], af[i], bf[j]);
            }
            __syncthreads();
        }
#pragma unroll
        for (int i = 0; i < 4; i++)
#pragma unroll
            for (int j = 0; j < 4; j++) {
                int c = bnh + wn + j * 8 + lr * 2;
#pragma unroll
                for (int rr = 0; rr < 2; rr++) {
                    int r2 = bm + wm + i * 16 + lq + rr * 8;
                    float v0 = acc[i][j][rr * 2 + 0], v1 = acc[i][j][rr * 2 + 1];
                    if (EPI & 1) {
                        v0 = fmaxf(v0 + bias[c], 0.f);
                        v1 = fmaxf(v1 + bias[c + 1], 0.f);
                    }
                    if (EPI & 4) {
                        atomicAdd(rsum + r2, v0 + v1);
                        atomicAdd(rsq + r2, v0 * v0 + v1 * v1);
                    }
                    *(float2*)(C + (size_t)r2 * ldc + c) = make_float2(v0, v1);
                }
            }
        __syncthreads();
    }
#endif
}

// ================= legacy tf32 warp-MMA GEMM (TN, split-K, atomic) =============
__device__ __forceinline__ void stage_tn(const float* __restrict__ A, int lda,
                                         const float* __restrict__ B, int ldb,
                                         int bm, int bn, int k0,
                                         float* as, float* bs, int tid) {
#pragma unroll
    for (int i = 0; i < 4; i++) {
        int idx = tid + i * 256;
        int row = idx >> 5, c4 = (idx & 31) << 2;
        cp16(as + row * 136 + c4, A + (size_t)(k0 + row) * lda + bm + c4);
        cp16(bs + row * 136 + c4, B + (size_t)(k0 + row) * ldb + bn + c4);
    }
    cp_commit();
}
template <int SPLITK>
__global__ __launch_bounds__(256, 2)
void gemm_tn(const float* __restrict__ A, int lda, long long sA,
             const float* __restrict__ B, int ldb, long long sB,
             float* __restrict__ C, int ldc, long long sC, int K) {
    extern __shared__ float fsm[];
    constexpr int ABUF = 32 * 136;
    float* As = fsm;
    float* Bs = fsm + 2 * ABUF;
    int bz = blockIdx.z;
    int batch = bz / SPLITK, ks = bz - batch * SPLITK;
    A += (size_t)batch * sA;
    B += (size_t)batch * sB;
    C += (size_t)batch * sC;
    const int kchunk = K / SPLITK, kbase = ks * kchunk;
    const int bm = blockIdx.y * 128, bn = blockIdx.x * 128;
    const int tid = threadIdx.x, wid = tid >> 5, lane = tid & 31;
    const int wm = (wid >> 2) * 64, wn = (wid & 3) * 32;
    const int lq = lane >> 2, lr = lane & 3;
    float acc[4][4][4];
#pragma unroll
    for (int i = 0; i < 4; i++)
#pragma unroll
        for (int j = 0; j < 4; j++)
#pragma unroll
            for (int t = 0; t < 4; t++) acc[i][j][t] = 0.f;
    const int KT = kchunk / 32;
    stage_tn(A, lda, B, ldb, bm, bn, kbase, As, Bs, tid);
    for (int kt = 0; kt < KT; kt++) {
        int buf = kt & 1;
        if (kt + 1 < KT) {
            stage_tn(A, lda, B, ldb, bm, bn, kbase + (kt + 1) * 32,
                     As + ((kt + 1) & 1) * ABUF, Bs + ((kt + 1) & 1) * ABUF, tid);
            cp_wait<1>();
        } else cp_wait<0>();
        __syncthreads();
        const float* as = As + buf * ABUF;
        const float* bs = Bs + buf * ABUF;
#pragma unroll
        for (int kk = 0; kk < 4; kk++) {
            const int k0 = kk * 8;
            uint32_t af[4][4], bf[4][2];
#pragma unroll
            for (int i = 0; i < 4; i++) {
                const float* p = as + (k0 + lr) * 136 + wm + i * 16 + lq;
                af[i][0] = cvt_tf32(p[0]);
                af[i][1] = cvt_tf32(p[8]);
                const float* p4 = p + 4 * 136;
                af[i][2] = cvt_tf32(p4[0]);
                af[i][3] = cvt_tf32(p4[8]);
            }
#pragma unroll
            for (int j = 0; j < 4; j++) {
                const float* p = bs + (k0 + lr) * 136 + wn + j * 8 + lq;
                bf[j][0] = cvt_tf32(p[0]);
                bf[j][1] = cvt_tf32(p[4 * 136]);
            }
#pragma unroll
            for (int i = 0; i < 4; i++)
#pragma unroll
                for (int j = 0; j < 4; j++) mma8(acc[i][j], af[i], bf[j]);
        }
        __syncthreads();
    }
#pragma unroll
    for (int i = 0; i < 4; i++)
#pragma unroll
        for (int j = 0; j < 4; j++) {
            int c = bn + wn + j * 8 + lr * 2;
#pragma unroll
            for (int rr = 0; rr < 2; rr++) {
                int row = bm + wm + i * 16 + lq + rr * 8;
                atomicAdd(C + (size_t)row * ldc + c, acc[i][j][rr * 2 + 0]);
                atomicAdd(C + (size_t)row * ldc + c + 1, acc[i][j][rr * 2 + 1]);
            }
        }
}

// ================= elementwise kernels =========================================
__global__ void transpose_k(const float* __restrict__ in, float* __restrict__ out,
                            int R, int Cc, int ldin, long long sIn, long long sOut) {
    __shared__ float tile[32][33];
    in += (size_t)blockIdx.z * sIn;
    out += (size_t)blockIdx.z * sOut;
    int c0 = blockIdx.x * 32, r0 = blockIdx.y * 32;
    int tx = threadIdx.x, ty = threadIdx.y;
#pragma unroll
    for (int j = 0; j < 32; j += 8)
        tile[ty + j][tx] = in[(size_t)(r0 + ty + j) * ldin + c0 + tx];
    __syncthreads();
#pragma unroll
    for (int j = 0; j < 32; j += 8)
        out[(size_t)(c0 + ty + j) * R + r0 + tx] = tile[tx][ty + j];
}

__global__ void zero_k(float* __restrict__ p, size_t n4) {
    size_t i = (size_t)blockIdx.x * blockDim.x + threadIdx.x;
    if (i < n4) ((float4*)p)[i] = make_float4(0.f, 0.f, 0.f, 0.f);
}

__global__ void prep_k(const float* __restrict__ Wres, const float* __restrict__ g1,
                       const float* __restrict__ beta1) {
    int c = blockIdx.x * 8 + (threadIdx.x >> 5);
    int lane = threadIdx.x & 31;
    const float* wr = Wres + (size_t)c * C4;
    float s1 = 0.f, s2 = 0.f;
    for (int k = lane; k < C4; k += 32) {
        float w = wr[k], g = g1[k];
        g_Wg[(size_t)c * C4 + k] = g * w;
        s1 += g * w;
        s2 += beta1[k] * w;
    }
#pragma unroll
    for (int o = 16; o; o >>= 1) {
        s1 += __shfl_xor_sync(0xffffffffu, s1, o);
        s2 += __shfl_xor_sync(0xffffffffu, s2, o);
    }
    if (lane == 0) { g_S1[c] = s1; g_S2[c] = s2; }
}

__global__ void finalize_k(const float* __restrict__ rsum, const float* __restrict__ rsq) {
    int row = blockIdx.x * 256 + threadIdx.x;
    float mu = rsum[row] * (1.f / 1024.f);
    float var = rsq[row] * (1.f / 1024.f) - mu * mu;
    g_mu[row] = mu;
    g_rinv[row] = rsqrtf(var + 1e-5f);
}

// ================= host launcher ================================================
typedef CUresult (*EncFn)(CUtensorMap*, CUtensorMapDataType, cuuint32_t, void*,
                          const cuuint64_t*, const cuuint64_t*, const cuuint32_t*,
                          const cuuint32_t*, CUtensorMapInterleave, CUtensorMapSwizzle,
                          CUtensorMapL2promotion, CUtensorMapFloatOOBfill);

static void mk_map(EncFn enc, CUtensorMap* m, void* ptr,
                   uint64_t d0, uint64_t d1, uint64_t d2,
                   uint64_t str1B, uint64_t str2B, uint32_t box1) {
    cuuint64_t dims[3] = {d0, d1, d2};
    cuuint64_t strides[2] = {str1B, str2B};
    cuuint32_t box[3] = {32, box1, 1};
    cuuint32_t es[3] = {1, 1, 1};
    enc(m, CU_TENSOR_MAP_DATA_TYPE_FLOAT32, 3, ptr, dims, strides, box, es,
        CU_TENSOR_MAP_INTERLEAVE_NONE, CU_TENSOR_MAP_SWIZZLE_128B,
        CU_TENSOR_MAP_L2_PROMOTION_L2_128B, CU_TENSOR_MAP_FLOAT_OOB_FILL_NONE);
}

extern "C" void kernel_launch(void* const* d_in, const int* in_sizes, int n_in,
                              void* d_out, int out_size) {
    (void)in_sizes; (void)n_in; (void)out_size;
    const float* x     = (const float*)d_in[0];
    const float* Wqkv  = (const float*)d_in[1];
    const float* Wmlp  = (const float*)d_in[2];
    const float* bmlp  = (const float*)d_in[3];
    const float* g1    = (const float*)d_in[4];
    const float* beta1 = (const float*)d_in[5];
    const float* Wres  = (const float*)d_in[6];
    const float* g2    = (const float*)d_in[7];
    const float* beta2 = (const float*)d_in[8];
    float* outp = (float*)d_out;

    float *x1, *sm, *u, *cat2, *ctx, *mu, *rinv, *Wg, *S1, *S2, *stats;
    cudaGetSymbolAddress((void**)&x1, g_x1);
    cudaGetSymbolAddress((void**)&sm, g_sm);
    cudaGetSymbolAddress((void**)&u, g_u);
    cudaGetSymbolAddress((void**)&cat2, g_cat2);
    cudaGetSymbolAddress((void**)&ctx, g_ctx);
    cudaGetSymbolAddress((void**)&mu, g_mu);
    cudaGetSymbolAddress((void**)&rinv, g_rinv);
    cudaGetSymbolAddress((void**)&Wg, g_Wg);
    cudaGetSymbolAddress((void**)&S1, g_S1);
    cudaGetSymbolAddress((void**)&S2, g_S2);
    cudaGetSymbolAddress((void**)&stats, g_stats);
    float* rsum0 = stats;
    float* rsq0  = stats + ROWS;
    float* rsum1 = stats + 2 * ROWS;
    float* rsq1  = stats + 3 * ROWS;

    EncFn enc = nullptr;
    cudaDriverEntryPointQueryResult qr;
    cudaGetDriverEntryPoint("cuTensorMapEncodeTiled", (void**)&enc,
                            cudaEnableDefault, &qr);
    CUtensorMap mU, mWqkv, mSm, mCtx, mCat2, mWmlp, mWg;
    mk_map(enc, &mU, u, 256, 32768, 1, 1024, (uint64_t)32768 * 1024, 128);
    mk_map(enc, &mWqkv, (void*)Wqkv, 256, 256, 1, 1024, 256 * 1024, 256);
    mk_map(enc, &mSm, sm, 256, 4096, 8, 1024, (uint64_t)4096 * 1024, 128);
    mk_map(enc, &mCtx, ctx, 256, 256, 8, 1024, 256 * 1024, 256);
    mk_map(enc, &mCat2, cat2, 1024, 32768, 1, 4096, (uint64_t)32768 * 4096, 128);
    mk_map(enc, &mWmlp, (void*)Wmlp, 512, 512, 1, 2048, 512 * 2048, 256);
    mk_map(enc, &mWg, Wg, 1024, 256, 1, 4096, 256 * 4096, 256);

    const int SM256 = 1024 + 2 * (16384 + 256 * 128);   // 99328
    const int SM512 = 1024 + 2 * (16384 + 512 * 128);   // 164864
    const int smemTN = 4 * 32 * 136 * 4;
    cudaFuncSetAttribute(gemm_t5<8, 256>, cudaFuncAttributeMaxDynamicSharedMemorySize, SM256);
    cudaFuncSetAttribute(gemm_t5<4, 256>, cudaFuncAttributeMaxDynamicSharedMemorySize, SM256);
    cudaFuncSetAttribute(gemm_t5<5, 512>, cudaFuncAttributeMaxDynamicSharedMemorySize, SM512);
    cudaFuncSetAttribute(gemm_t5<16, 256>, cudaFuncAttributeMaxDynamicSharedMemorySize, SM256);
    cudaFuncSetAttribute(gemm_t5<17, 256>, cudaFuncAttributeMaxDynamicSharedMemorySize, SM256);
    cudaFuncSetAttribute(gemm_tn<8>, cudaFuncAttributeMaxDynamicSharedMemorySize, smemTN);

    float* vbuf = cat2 + 256;   // v lives in cat2[:,256:512), ld C4

    dim3 ttb(32, 8);
    transpose_k<<<dim3(Ntok / 32, Cdim / 32, Bsz), ttb>>>(
        x, u, Cdim, Ntok, Ntok, (long long)Cdim * Ntok, (long long)Cdim * Ntok);

    zero_k<<<(4 * ROWS / 4 + 255) / 256, 256>>>(stats, 4 * ROWS / 4);
    prep_k<<<Cdim / 8, 256>>>(Wres, g1, beta1);

    // qkv fused: x1, softmax->sm, v->cat2, LN1 stats (buf0)
    gemm_t5<8, 256><<<dim3(1, ROWS / 128, 1), 256, SM256>>>(
        mU, mWqkv, u, Cdim, 0, Wqkv, Cdim, 0, x1, Cdim, 0, Cdim,
        nullptr, nullptr, 0, nullptr, nullptr, nullptr, nullptr,
        rsum0, rsq0, 0, sm, vbuf, nullptr, nullptr, nullptr);

    for (int it = 0; it < 2; ++it) {
        float* rs = it == 0 ? rsum0 : rsum1;
        float* rq = it == 0 ? rsq0 : rsq1;

        zero_k<<<(Bsz * Cdim * Cdim / 4 + 255) / 256, 256>>>(ctx, (size_t)Bsz * Cdim * Cdim / 4);
        gemm_tn<8><<<dim3(2, 2, Bsz * 8), 256, smemTN>>>(
            vbuf, C4, (long long)Ntok * C4, x1, Cdim, (long long)Ntok * Cdim,
            ctx, Cdim, (long long)Cdim * Cdim, Ntok);

        // out = sm @ ctx -> cat2[:,0:256], + stats
        gemm_t5<4, 256><<<dim3(1, Ntok / 128, Bsz), 256, SM256>>>(
            mSm, mCtx, sm, Cdim, (long long)Ntok * Cdim, ctx, Cdim, (long long)Cdim * Cdim,
            cat2, C4, (long long)Ntok * C4, Cdim,
            nullptr, nullptr, 0, nullptr, nullptr, nullptr, nullptr,
            rs, rq, Ntok, nullptr, nullptr, nullptr, nullptr, nullptr);

        // mlp = relu(cat1 @ Wmlp^T + b) -> cat2[:,512:1024], single 512-wide tile
        gemm_t5<5, 512><<<dim3(1, ROWS / 128, 1), 256, SM512>>>(
            mCat2, mWmlp, cat2, C4, 0, Wmlp, 512, 0, cat2 + 512, C4, 0, 512,
            bmlp, nullptr, 0, nullptr, nullptr, nullptr, nullptr,
            rs, rq, 0, nullptr, nullptr, nullptr, nullptr, nullptr);

        finalize_k<<<ROWS / 256, 256>>>(rs, rq);

        // res + LN2 fused (K=1024)
        if (it == 0) {
            gemm_t5<16, 256><<<dim3(1, ROWS / 128, 1), 256, SM256>>>(
                mCat2, mWg, cat2, C4, 0, Wg, C4, 0, u, Cdim, 0, C4,
                nullptr, x1, Cdim, mu, rinv, S1, S2,
                rsum1, rsq1, 0, nullptr, vbuf, g2, beta2, nullptr);
        } else {
            gemm_t5<17, 256><<<dim3(1, ROWS / 128, 1), 256, SM256>>>(
                mCat2, mWg, cat2, C4, 0, Wg, C4, 0, u, Cdim, 0, C4,
                nullptr, x1, Cdim, mu, rinv, S1, S2,
                nullptr, nullptr, 0, nullptr, nullptr, g2, beta2, outp);
        }
    }
}

// round 12
// speedup vs baseline: 1.0287x; 1.0287x over previous
#include <cuda_runtime.h>
#include <cuda.h>
#include <math.h>
#include <stdint.h>

#define Bsz  8
#define Cdim 256
#define Ntok 4096
#define ROWS (Bsz * Ntok)          // 32768 token rows
#define C4   (4 * Cdim)            // 1024

// ---------------- scratch (static device arrays; no allocation) ----------------
__device__ float g_x1[(size_t)ROWS * Cdim];
__device__ float g_sm[(size_t)ROWS * Cdim];
__device__ float g_u[(size_t)ROWS * Cdim];         // transpose scratch
__device__ float g_cat2[(size_t)ROWS * C4];        // [out | v | mlp], ld=1024
__device__ float g_ctx[(size_t)Bsz * Cdim * Cdim]; // g_ctx[d][c]
__device__ float g_x1t[(size_t)ROWS * Cdim];       // x1T[b][c][n]
__device__ float g_vt[(size_t)ROWS * Cdim];        // vT[b][c][n]
__device__ float g_mu[ROWS];                       // (unused placeholders kept)
__device__ float g_rinv[ROWS];
__device__ float g_Wg[(size_t)Cdim * C4];
__device__ float g_S1[Cdim];
__device__ float g_S2[Cdim];
__device__ float g_stats[4 * ROWS];                // rsum0|rsq0|rsum1|rsq1

#if defined(__CUDA_ARCH_FEAT_SM103_ALL) || defined(__CUDA_ARCH_FEAT_SM100_ALL)
#define HAS_TCGEN05 1
#else
#define HAS_TCGEN05 0
#endif

// ================= helpers ======================================================
__device__ __forceinline__ uint32_t smem_u32(const void* p) {
    return (uint32_t)__cvta_generic_to_shared(p);
}
__device__ __forceinline__ uint32_t elect1() {
    uint32_t pred;
    asm volatile("{\n\t.reg .pred p;\n\telect.sync _|p, 0xFFFFFFFF;\n\tselp.b32 %0, 1, 0, p;\n\t}"
                 : "=r"(pred));
    return pred;
}
__device__ __forceinline__ void mbar_init(uint32_t a, uint32_t cnt) {
    asm volatile("mbarrier.init.shared.b64 [%0], %1;" :: "r"(a), "r"(cnt) : "memory");
}
__device__ __forceinline__ void mbar_wait(uint32_t a, int ph) {
    asm volatile(
        "{\n\t.reg .pred P;\n\t"
        "WL%=:\n\t"
        "mbarrier.try_wait.parity.acquire.cta.shared::cta.b64 P, [%0], %1, 0x989680;\n\t"
        "@P bra.uni WD%=;\n\t"
        "bra.uni WL%=;\n\t"
        "WD%=:\n\t}"
        :: "r"(a), "r"(ph) : "memory");
}
__device__ __forceinline__ void mbar_expect_tx(uint32_t a, uint32_t bytes) {
    asm volatile("mbarrier.arrive.expect_tx.shared.b64 _, [%0], %1;"
                 :: "r"(a), "r"(bytes) : "memory");
}
__device__ __forceinline__ void tma3d(uint32_t dst, const void* map, int x, int y, int z,
                                      uint32_t mbar) {
    asm volatile(
        "cp.async.bulk.tensor.3d.shared::cta.global.tile.mbarrier::complete_tx::bytes "
        "[%0], [%1, {%2, %3, %4}], [%5];"
        :: "r"(dst), "l"(map), "r"(x), "r"(y), "r"(z), "r"(mbar) : "memory");
}
#define SW128B(o) ((o) ^ (((o) >> 3) & 0x70))

static constexpr unsigned long long DESC_SW128 =
    (2ull << 61) | (1ull << 46) | (64ull << 32) | (1ull << 16);
__device__ __forceinline__ uint64_t mk_desc(uint32_t addr) {
    return DESC_SW128 | ((uint64_t)(addr >> 4) & 0x3FFF);
}

__device__ __forceinline__ uint32_t cvt_tf32(float x) {
    uint32_t r;
    asm("cvt.rna.tf32.f32 %0, %1;" : "=r"(r) : "f"(x));
    return r;
}
__device__ __forceinline__ void cp16(float* s, const float* g) {
    uint32_t sa = smem_u32(s);
    asm volatile("cp.async.cg.shared.global [%0], [%1], 16;" :: "r"(sa), "l"(g));
}
__device__ __forceinline__ void cp_commit() { asm volatile("cp.async.commit_group;" ::); }
template <int N>
__device__ __forceinline__ void cp_wait() { asm volatile("cp.async.wait_group %0;" :: "n"(N)); }

__device__ __forceinline__ void mma8(float* c, const uint32_t* a, const uint32_t* b) {
    asm volatile(
        "mma.sync.aligned.m16n8k8.row.col.f32.tf32.tf32.f32 "
        "{%0,%1,%2,%3}, {%4,%5,%6,%7}, {%8,%9}, {%0,%1,%2,%3};"
        : "+f"(c[0]), "+f"(c[1]), "+f"(c[2]), "+f"(c[3])
        : "r"(a[0]), "r"(a[1]), "r"(a[2]), "r"(a[3]), "r"(b[0]), "r"(b[1]));
}

#define LDTM32(d, addr)                                                          \
    asm volatile(                                                                \
        "tcgen05.ld.sync.aligned.32x32b.x32.b32 "                                \
        "{%0, %1, %2, %3, %4, %5, %6, %7, "                                      \
        " %8, %9, %10, %11, %12, %13, %14, %15, "                                \
        " %16, %17, %18, %19, %20, %21, %22, %23, "                              \
        " %24, %25, %26, %27, %28, %29, %30, %31}, [%32];"                       \
        : "=r"(d[0]), "=r"(d[1]), "=r"(d[2]), "=r"(d[3]),                        \
          "=r"(d[4]), "=r"(d[5]), "=r"(d[6]), "=r"(d[7]),                        \
          "=r"(d[8]), "=r"(d[9]), "=r"(d[10]), "=r"(d[11]),                      \
          "=r"(d[12]), "=r"(d[13]), "=r"(d[14]), "=r"(d[15]),                    \
          "=r"(d[16]), "=r"(d[17]), "=r"(d[18]), "=r"(d[19]),                    \
          "=r"(d[20]), "=r"(d[21]), "=r"(d[22]), "=r"(d[23]),                    \
          "=r"(d[24]), "=r"(d[25]), "=r"(d[26]), "=r"(d[27]),                    \
          "=r"(d[28]), "=r"(d[29]), "=r"(d[30]), "=r"(d[31])                     \
        : "r"(addr));                                                            \
    asm volatile("tcgen05.wait::ld.sync.aligned;" ::: "memory")

// ================= unified NT GEMM, CTA tile 128x256, TMA mainloop =============
// EPI: 0 plain | 4 store+stats | 5 relu+bias+stats |
//      8 qkv fused (x1 + softmax + v-copy + stats) |
//      16 res+LN2 -> vout + next stats | 17 res+LN2 -> transposed outT |
//      32 atomic-accumulate (split-K)
// For EPI 16/17: `mu` arg carries rsum, `rinv` arg carries rsq (stats finalized inline).
#define STG_BYTES 49152               // A 16K + B 32K
#define T5_SMEM (1024 + 2 * STG_BYTES)
#define TS 65                         // epilogue smem tile stride (floats)

__device__ __forceinline__ void nt_stage(const float* __restrict__ A, int lda,
                                         const float* __restrict__ B, int ldb,
                                         int bm, int bn, int k0,
                                         float* as, float* bs, int tid) {
#pragma unroll
    for (int i = 0; i < 4; i++) {
        int idx = tid + i * 256;
        int row = idx >> 3, c4 = (idx & 7) << 2;
        cp16(as + row * 36 + c4, A + (size_t)(bm + row) * lda + k0 + c4);
        cp16(bs + row * 36 + c4, B + (size_t)(bn + row) * ldb + k0 + c4);
    }
    cp_commit();
}

template <int EPI, int SPLITK>
__global__ __launch_bounds__(256)
void gemm_t5(const __grid_constant__ CUtensorMap tmA,
             const __grid_constant__ CUtensorMap tmB,
             const float* __restrict__ A, int lda, long long sA,
             const float* __restrict__ B, int ldb, long long sB,
             float* __restrict__ C, int ldc, long long sC, int K,
             const float* __restrict__ bias,
             const float* __restrict__ resid, int ldr,
             const float* __restrict__ mu, const float* __restrict__ rinv,
             const float* __restrict__ S1, const float* __restrict__ S2,
             float* __restrict__ rsum, float* __restrict__ rsq, long long sStat,
             float* __restrict__ smx, float* __restrict__ vout,
             const float* __restrict__ g2, const float* __restrict__ b2,
             float* __restrict__ outT) {
    extern __shared__ char smem[];
    const int tid = threadIdx.x, wid = tid >> 5, lane = tid & 31;
    const int bz = blockIdx.z;
    const int batch = bz / SPLITK, ks = bz - batch * SPLITK;
    const int kchunk = K / SPLITK, kxoff = ks * kchunk;
    C += (size_t)batch * sC;
    if (EPI == 4 || EPI == 5) { rsum += (size_t)batch * sStat; rsq += (size_t)batch * sStat; }
    const int bm = blockIdx.y * 128, bn = blockIdx.x * 256;

#if HAS_TCGEN05
    uint32_t sb = smem_u32(smem);
    if (wid == 0) {
        asm volatile("tcgen05.alloc.cta_group::1.sync.aligned.shared::cta.b32 [%0], %1;"
                     :: "r"(sb), "r"(256) : "memory");
        asm volatile("tcgen05.relinquish_alloc_permit.cta_group::1.sync.aligned;");
    }
    // mbars: +8 full0, +16 full1, +24 empty0, +32 empty1
    if (tid == 0) {
        mbar_init(sb + 8, 1); mbar_init(sb + 16, 1);
        mbar_init(sb + 24, 1); mbar_init(sb + 32, 1);
    }
    __syncthreads();
    uint32_t tmem;
    asm volatile("ld.shared.b32 %0, [%1];" : "=r"(tmem) : "r"(sb));

    const int KT = kchunk / 32;
    const uint32_t IDESC = (1u << 4) | (2u << 7) | (2u << 10) | (32u << 17) | (8u << 24);

    if (wid == 0 && elect1()) {
#pragma unroll
        for (int s = 0; s < 2; s++) {
            uint32_t full = sb + 8 + s * 8;
            uint32_t dst = sb + 1024 + s * STG_BYTES;
            mbar_expect_tx(full, STG_BYTES);
            tma3d(dst, &tmA, kxoff + s * 32, bm, batch, full);
            tma3d(dst + 16384, &tmB, kxoff + s * 32, bn, batch, full);
        }
        int fph[2] = {0, 0}, eph[2] = {0, 0};
        for (int kt = 0; kt < KT; kt++) {
            int buf = kt & 1;
            mbar_wait(sb + 8 + buf * 8, fph[buf]); fph[buf] ^= 1;
            uint32_t base = sb + 1024 + buf * STG_BYTES;
            uint64_t ad = mk_desc(base);
            uint64_t bd = mk_desc(base + 16384);
#pragma unroll
            for (int s = 0; s < 4; s++) {
                uint32_t en = (kt > 0 || s > 0) ? 1u : 0u;
                asm volatile(
                    "{\n\t.reg .pred p;\n\tsetp.ne.u32 p, %5, 0;\n\t"
                    "tcgen05.mma.cta_group::1.kind::tf32 [%0], %1, %2, %3, {%4,%4,%4,%4}, p;\n\t}"
                    :: "r"(tmem), "l"(ad + s * 2), "l"(bd + s * 2), "r"(IDESC),
                       "r"(0u), "r"(en) : "memory");
            }
            asm volatile(
                "tcgen05.commit.cta_group::1.mbarrier::arrive::one.shared::cluster.b64 [%0];"
                :: "r"(sb + 24 + buf * 8) : "memory");
            if (kt + 2 < KT) {
                mbar_wait(sb + 24 + buf * 8, eph[buf]); eph[buf] ^= 1;
                uint32_t full = sb + 8 + buf * 8;
                mbar_expect_tx(full, STG_BYTES);
                tma3d(base, &tmA, kxoff + (kt + 2) * 32, bm, batch, full);
                tma3d(base + 16384, &tmB, kxoff + (kt + 2) * 32, bn, batch, full);
            }
        }
    }
    __syncthreads();
    mbar_wait(sb + 24 + ((KT - 1) & 1) * 8, (KT / 2 - 1) & 1);
    asm volatile("tcgen05.fence::after_thread_sync;" ::: "memory");

    const int rl = (wid & 3) * 32 + lane;     // local row 0..127 (TMEM lane)
    const int row = bm + rl;
    const int half = wid >> 2;
    const int cb = half * 128;
    float* s0 = (float*)(smem + 1024);        // [256] sum partials
    float* s1 = s0 + 256;                     // [256] sumsq partials
    float* s2 = s1 + 256;                     // [256] expsum partials
    float* s3 = s2 + 256;                     // [128] per-row scalar (softmax inv)
    float* tile = s3 + 256;                   // [128][TS] staging tile

    if (EPI == 17) {
        // ---- res+LN2 -> transposed out; stats finalized inline ----
        float mm = mu[row] * (1.f / 1024.f);
        float rv = rsqrtf(rinv[row] * (1.f / 1024.f) - mm * mm + 1e-5f);
        float ps = 0.f, pq = 0.f;
#pragma unroll
        for (int cc = 0; cc < 4; cc++) {
            uint32_t d[32];
            LDTM32(d, tmem + cb + cc * 32);
#pragma unroll
            for (int j = 0; j < 32; j++) {
                int c = cb + cc * 32 + j;
                float val = fmaf(rv, __uint_as_float(d[j]) - mm * S1[c], S2[c]) +
                            2.f * resid[(size_t)row * ldr + c];
                ps += val; pq += val * val;
            }
        }
        s0[half * 128 + rl] = ps;
        s1[half * 128 + rl] = pq;
        __syncthreads();
        float ts = s0[rl] + s0[128 + rl];
        float tq = s1[rl] + s1[128 + rl];
        float mu2 = ts * (1.f / 256.f);
        float r2 = rsqrtf(tq * (1.f / 256.f) - mu2 * mu2 + 1e-5f);
#pragma unroll
        for (int cc = 0; cc < 4; cc++) {
            uint32_t d[32];
            LDTM32(d, tmem + cb + cc * 32);
#pragma unroll
            for (int j = 0; j < 32; j++) {
                int c = cb + cc * 32 + j;
                float val = fmaf(rv, __uint_as_float(d[j]) - mm * S1[c], S2[c]) +
                            2.f * resid[(size_t)row * ldr + c];
                val = (val - mu2) * r2 * g2[c] + b2[c];
                int b = row >> 12, n = row & 4095;
                outT[((size_t)b * Cdim + c) * Ntok + n] = val;
            }
        }
    } else if (EPI == 8 || EPI == 16) {
        // ---- fused two-pass epilogue with smem-staged coalesced stores ----
        float rv = 0.f, mm = 0.f;
        if (EPI == 16) {
            mm = mu[row] * (1.f / 1024.f);
            rv = rsqrtf(rinv[row] * (1.f / 1024.f) - mm * mm + 1e-5f);
        }
        float ps = 0.f, pq = 0.f, pe = 0.f;
#pragma unroll
        for (int cc = 0; cc < 4; cc++) {
            uint32_t d[32];
            LDTM32(d, tmem + cb + cc * 32);
#pragma unroll
            for (int j = 0; j < 32; j++) {
                float val = __uint_as_float(d[j]);
                if (EPI == 16) {
                    int c = cb + cc * 32 + j;
                    val = fmaf(rv, val - mm * S1[c], S2[c]) +
                          2.f * resid[(size_t)row * ldr + c];
                }
                ps += val; pq += val * val;
                if (EPI == 8) pe += __expf(val);
            }
        }
        s0[half * 128 + rl] = ps;
        s1[half * 128 + rl] = pq;
        if (EPI == 8) s2[half * 128 + rl] = pe;
        __syncthreads();
        float ts = s0[rl] + s0[128 + rl];
        float tq = s1[rl] + s1[128 + rl];
        float mu2 = 0.f, r2 = 0.f;
        if (EPI == 8) {
            float inv = 1.f / (s2[rl] + s2[128 + rl]);
            if (half == 0) s3[rl] = inv;
        } else {
            mu2 = ts * (1.f / 256.f);
            r2 = rsqrtf(tq * (1.f / 256.f) - mu2 * mu2 + 1e-5f);
        }
        float vs = 0.f, vq = 0.f;
#pragma unroll
        for (int cc = 0; cc < 4; cc++) {
            uint32_t d[32];
            LDTM32(d, tmem + cb + cc * 32);
#pragma unroll
            for (int j = 0; j < 32; j++) {
                float val = __uint_as_float(d[j]);
                if (EPI == 16) {
                    int c = cb + cc * 32 + j;
                    val = fmaf(rv, val - mm * S1[c], S2[c]) +
                          2.f * resid[(size_t)row * ldr + c];
                    val = (val - mu2) * r2 * g2[c] + b2[c];
                    vs += val; vq += val * val;
                }
                tile[rl * TS + half * 32 + j] = val;
            }
            __syncthreads();
#pragma unroll
            for (int it2 = 0; it2 < 4; it2++) {
                int r = it2 * 32 + (tid >> 3);
                int cq = (tid & 7) * 4;
                size_t gr = (size_t)(bm + r);
#pragma unroll
                for (int h = 0; h < 2; h++) {
                    int c = h * 128 + cc * 32 + cq;
                    float4 v4;
                    v4.x = tile[r * TS + h * 32 + cq + 0];
                    v4.y = tile[r * TS + h * 32 + cq + 1];
                    v4.z = tile[r * TS + h * 32 + cq + 2];
                    v4.w = tile[r * TS + h * 32 + cq + 3];
                    if (EPI == 8) {
                        *(float4*)(C + gr * ldc + c) = v4;
                        *(float4*)(vout + gr * C4 + c) = v4;
                        float iv = s3[r];
                        float4 e = make_float4(__expf(v4.x) * iv, __expf(v4.y) * iv,
                                               __expf(v4.z) * iv, __expf(v4.w) * iv);
                        *(float4*)(smx + gr * Cdim + c) = e;
                    } else {
                        *(float4*)(vout + gr * C4 + c) = v4;
                    }
                }
            }
            __syncthreads();
        }
        if (EPI == 16) { atomicAdd(rsum + row, vs); atomicAdd(rsq + row, vq); }
        if (EPI == 8 && half == 0) { atomicAdd(rsum + row, ts); atomicAdd(rsq + row, tq); }
    } else if (EPI == 32) {
        // ---- split-K accumulate: staged + coalesced atomicAdd ----
#pragma unroll
        for (int cc = 0; cc < 4; cc++) {
            uint32_t d[32];
            LDTM32(d, tmem + cb + cc * 32);
#pragma unroll
            for (int j = 0; j < 32; j++)
                tile[rl * TS + half * 32 + j] = __uint_as_float(d[j]);
            __syncthreads();
#pragma unroll
            for (int it2 = 0; it2 < 4; it2++) {
                int r = it2 * 32 + (tid >> 3);
                int cq = (tid & 7) * 4;
                size_t gr = (size_t)(bm + r);
#pragma unroll
                for (int h = 0; h < 2; h++) {
                    int c = bn + h * 128 + cc * 32 + cq;
                    float* dst = C + gr * ldc + c;
                    atomicAdd(dst + 0, tile[r * TS + h * 32 + cq + 0]);
                    atomicAdd(dst + 1, tile[r * TS + h * 32 + cq + 1]);
                    atomicAdd(dst + 2, tile[r * TS + h * 32 + cq + 2]);
                    atomicAdd(dst + 3, tile[r * TS + h * 32 + cq + 3]);
                }
            }
            __syncthreads();
        }
    } else {
        // ---- EPI 0/4/5: streaming via smem-staged coalesced store ----
        float ssum = 0.f, ssq = 0.f;
#pragma unroll
        for (int cc = 0; cc < 4; cc++) {
            uint32_t d[32];
            LDTM32(d, tmem + cb + cc * 32);
#pragma unroll
            for (int j = 0; j < 32; j++) {
                float val = __uint_as_float(d[j]);
                if (EPI & 1) val = fmaxf(val + bias[bn + cb + cc * 32 + j], 0.f);
                if (EPI & 4) { ssum += val; ssq += val * val; }
                tile[rl * TS + half * 32 + j] = val;
            }
            __syncthreads();
#pragma unroll
            for (int it2 = 0; it2 < 4; it2++) {
                int r = it2 * 32 + (tid >> 3);
                int cq = (tid & 7) * 4;
                size_t gr = (size_t)(bm + r);
#pragma unroll
                for (int h = 0; h < 2; h++) {
                    int c = bn + h * 128 + cc * 32 + cq;
                    float4 v4;
                    v4.x = tile[r * TS + h * 32 + cq + 0];
                    v4.y = tile[r * TS + h * 32 + cq + 1];
                    v4.z = tile[r * TS + h * 32 + cq + 2];
                    v4.w = tile[r * TS + h * 32 + cq + 3];
                    *(float4*)(C + gr * ldc + c) = v4;
                }
            }
            __syncthreads();
        }
        if (EPI & 4) {
            atomicAdd(rsum + row, ssum);
            atomicAdd(rsq + row, ssq);
        }
    }
    __syncthreads();
    if (wid == 0) {
        asm volatile("tcgen05.dealloc.cta_group::1.sync.aligned.b32 %0, %1;"
                     :: "r"(tmem), "r"(256));
    }
#else
    // -------- legacy fallback (compile-only on non-'a' targets) --------
    float* fsm = (float*)smem;
    constexpr int ABUF = 128 * 36;
    float* As = fsm;
    float* Bs = fsm + 2 * ABUF;
    const int wm = (wid >> 2) * 64, wn = (wid & 3) * 32;
    const int lq = lane >> 2, lr = lane & 3;
    const float* Ab = A + (size_t)batch * sA;
    const float* Bb = B + (size_t)batch * sB;
    for (int hf = 0; hf < 2; hf++) {
        int bnh = bn + hf * 128;
        float acc[4][4][4];
#pragma unroll
        for (int i = 0; i < 4; i++)
#pragma unroll
            for (int j = 0; j < 4; j++)
#pragma unroll
                for (int t = 0; t < 4; t++) acc[i][j][t] = 0.f;
        const int KT = kchunk / 32;
        nt_stage(Ab, lda, Bb, ldb, bm, bnh, kxoff, As, Bs, tid);
        for (int kt = 0; kt < KT; kt++) {
            int buf = kt & 1;
            if (kt + 1 < KT) {
                nt_stage(Ab, lda, Bb, ldb, bm, bnh, kxoff + (kt + 1) * 32,
                         As + ((kt + 1) & 1) * ABUF, Bs + ((kt + 1) & 1) * ABUF, tid);
                cp_wait<1>();
            } else cp_wait<0>();
            __syncthreads();
            const float* as = As + buf * ABUF;
            const float* bs = Bs + buf * ABUF;
#pragma unroll
            for (int kk = 0; kk < 4; kk++) {
                const int k0 = kk * 8;
                uint32_t af[4][4], bf[4][2];
#pragma unroll
                for (int i = 0; i < 4; i++) {
                    const float* p = as + (wm + i * 16 + lq) * 36 + k0 + lr;
                    af[i][0] = cvt_tf32(p[0]);
                    af[i][2] = cvt_tf32(p[4]);
                    const float* p8 = p + 8 * 36;
                    af[i][1] = cvt_tf32(p8[0]);
                    af[i][3] = cvt_tf32(p8[4]);
                }
#pragma unroll
                for (int j = 0; j < 4; j++) {
                    const float* p = bs + (wn + j * 8 + lq) * 36 + k0 + lr;
                    bf[j][0] = cvt_tf32(p[0]);
                    bf[j][1] = cvt_tf32(p[4]);
                }
#pragma unroll
                for (int i = 0; i < 4; i++)
#pragma unroll
                    for (int j = 0; j < 4; j++) mma8(acc[i][j], af[i], bf[j]);
            }
            __syncthreads();
        }
#pragma unroll
        for (int i = 0; i < 4; i++)
#pragma unroll
            for (int j = 0; j < 4; j++) {
                int c = bnh + wn + j * 8 + lr * 2;
#pragma unroll
                for (int rr = 0; rr < 2; rr++) {
                    int r2 = bm + wm + i * 16 + lq + rr * 8;
                    float v0 = acc[i][j][rr * 2 + 0], v1 = acc[i][j][rr * 2 + 1];
                    if (EPI & 1) {
                        v0 = fmaxf(v0 + bias[c], 0.f);
                        v1 = fmaxf(v1 + bias[c + 1], 0.f);
                    }
                    if (EPI == 32) {
                        atomicAdd(C + (size_t)r2 * ldc + c, v0);
                        atomicAdd(C + (size_t)r2 * ldc + c + 1, v1);
                    } else {
                        *(float2*)(C + (size_t)r2 * ldc + c) = make_float2(v0, v1);
                    }
                }
            }
        __syncthreads();
    }
#endif
}

// ================= elementwise kernels =========================================
__global__ void transpose_k(const float* __restrict__ in, float* __restrict__ out,
                            int R, int Cc, int ldin, long long sIn, long long sOut) {
    __shared__ float tile[32][33];
    in += (size_t)blockIdx.z * sIn;
    out += (size_t)blockIdx.z * sOut;
    int c0 = blockIdx.x * 32, r0 = blockIdx.y * 32;
    int tx = threadIdx.x, ty = threadIdx.y;
#pragma unroll
    for (int j = 0; j < 32; j += 8)
        tile[ty + j][tx] = in[(size_t)(r0 + ty + j) * ldin + c0 + tx];
    __syncthreads();
#pragma unroll
    for (int j = 0; j < 32; j += 8)
        out[(size_t)(c0 + ty + j) * R + r0 + tx] = tile[tx][ty + j];
}

__global__ void zero_k(float* __restrict__ p, size_t n4) {
    size_t i = (size_t)blockIdx.x * blockDim.x + threadIdx.x;
    if (i < n4) ((float4*)p)[i] = make_float4(0.f, 0.f, 0.f, 0.f);
}

__global__ void prep_k(const float* __restrict__ Wres, const float* __restrict__ g1,
                       const float* __restrict__ beta1) {
    int c = blockIdx.x * 8 + (threadIdx.x >> 5);
    int lane = threadIdx.x & 31;
    const float* wr = Wres + (size_t)c * C4;
    float s1 = 0.f, s2 = 0.f;
    for (int k = lane; k < C4; k += 32) {
        float w = wr[k], g = g1[k];
        g_Wg[(size_t)c * C4 + k] = g * w;
        s1 += g * w;
        s2 += beta1[k] * w;
    }
#pragma unroll
    for (int o = 16; o; o >>= 1) {
        s1 += __shfl_xor_sync(0xffffffffu, s1, o);
        s2 += __shfl_xor_sync(0xffffffffu, s2, o);
    }
    if (lane == 0) { g_S1[c] = s1; g_S2[c] = s2; }
}

// ================= host launcher ================================================
typedef CUresult (*EncFn)(CUtensorMap*, CUtensorMapDataType, cuuint32_t, void*,
                          const cuuint64_t*, const cuuint64_t*, const cuuint32_t*,
                          const cuuint32_t*, CUtensorMapInterleave, CUtensorMapSwizzle,
                          CUtensorMapL2promotion, CUtensorMapFloatOOBfill);

static void mk_map(EncFn enc, CUtensorMap* m, void* ptr,
                   uint64_t d0, uint64_t d1, uint64_t d2,
                   uint64_t str1B, uint64_t str2B, uint32_t box1) {
    cuuint64_t dims[3] = {d0, d1, d2};
    cuuint64_t strides[2] = {str1B, str2B};
    cuuint32_t box[3] = {32, box1, 1};
    cuuint32_t es[3] = {1, 1, 1};
    enc(m, CU_TENSOR_MAP_DATA_TYPE_FLOAT32, 3, ptr, dims, strides, box, es,
        CU_TENSOR_MAP_INTERLEAVE_NONE, CU_TENSOR_MAP_SWIZZLE_128B,
        CU_TENSOR_MAP_L2_PROMOTION_L2_128B, CU_TENSOR_MAP_FLOAT_OOB_FILL_NONE);
}

extern "C" void kernel_launch(void* const* d_in, const int* in_sizes, int n_in,
                              void* d_out, int out_size) {
    (void)in_sizes; (void)n_in; (void)out_size;
    const float* x     = (const float*)d_in[0];
    const float* Wqkv  = (const float*)d_in[1];
    const float* Wmlp  = (const float*)d_in[2];
    const float* bmlp  = (const float*)d_in[3];
    const float* g1    = (const float*)d_in[4];
    const float* beta1 = (const float*)d_in[5];
    const float* Wres  = (const float*)d_in[6];
    const float* g2    = (const float*)d_in[7];
    const float* beta2 = (const float*)d_in[8];
    float* outp = (float*)d_out;

    float *x1, *sm, *u, *cat2, *ctx, *x1t, *vt, *Wg, *S1, *S2, *stats;
    cudaGetSymbolAddress((void**)&x1, g_x1);
    cudaGetSymbolAddress((void**)&sm, g_sm);
    cudaGetSymbolAddress((void**)&u, g_u);
    cudaGetSymbolAddress((void**)&cat2, g_cat2);
    cudaGetSymbolAddress((void**)&ctx, g_ctx);
    cudaGetSymbolAddress((void**)&x1t, g_x1t);
    cudaGetSymbolAddress((void**)&vt, g_vt);
    cudaGetSymbolAddress((void**)&Wg, g_Wg);
    cudaGetSymbolAddress((void**)&S1, g_S1);
    cudaGetSymbolAddress((void**)&S2, g_S2);
    cudaGetSymbolAddress((void**)&stats, g_stats);
    float* rsum0 = stats;
    float* rsq0  = stats + ROWS;
    float* rsum1 = stats + 2 * ROWS;
    float* rsq1  = stats + 3 * ROWS;

    EncFn enc = nullptr;
    cudaDriverEntryPointQueryResult qr;
    cudaGetDriverEntryPoint("cuTensorMapEncodeTiled", (void**)&enc,
                            cudaEnableDefault, &qr);
    CUtensorMap mU, mWqkv, mSm, mCtx, mCat2, mWmlp, mWg, mVt, mX1t;
    mk_map(enc, &mU, u, 256, 32768, 1, 1024, (uint64_t)32768 * 1024, 128);
    mk_map(enc, &mWqkv, (void*)Wqkv, 256, 256, 1, 1024, 256 * 1024, 256);
    mk_map(enc, &mSm, sm, 256, 4096, 8, 1024, (uint64_t)4096 * 1024, 128);
    mk_map(enc, &mCtx, ctx, 256, 256, 8, 1024, 256 * 1024, 256);
    mk_map(enc, &mCat2, cat2, 1024, 32768, 1, 4096, (uint64_t)32768 * 4096, 128);
    mk_map(enc, &mWmlp, (void*)Wmlp, 512, 512, 1, 2048, 512 * 2048, 256);
    mk_map(enc, &mWg, Wg, 1024, 256, 1, 4096, 256 * 4096, 256);
    mk_map(enc, &mVt, vt, 4096, 256, 8, 16384, (uint64_t)256 * 16384, 128);
    mk_map(enc, &mX1t, x1t, 4096, 256, 8, 16384, (uint64_t)256 * 16384, 256);

    cudaFuncSetAttribute(gemm_t5<8, 1>, cudaFuncAttributeMaxDynamicSharedMemorySize, T5_SMEM);
    cudaFuncSetAttribute(gemm_t5<4, 1>, cudaFuncAttributeMaxDynamicSharedMemorySize, T5_SMEM);
    cudaFuncSetAttribute(gemm_t5<5, 1>, cudaFuncAttributeMaxDynamicSharedMemorySize, T5_SMEM);
    cudaFuncSetAttribute(gemm_t5<16, 1>, cudaFuncAttributeMaxDynamicSharedMemorySize, T5_SMEM);
    cudaFuncSetAttribute(gemm_t5<17, 1>, cudaFuncAttributeMaxDynamicSharedMemorySize, T5_SMEM);
    cudaFuncSetAttribute(gemm_t5<32, 8>, cudaFuncAttributeMaxDynamicSharedMemorySize, T5_SMEM);

    float* vbuf = cat2 + 256;   // v lives in cat2[:,256:512), ld C4

    dim3 ttb(32, 8);
    transpose_k<<<dim3(Ntok / 32, Cdim / 32, Bsz), ttb>>>(
        x, u, Cdim, Ntok, Ntok, (long long)Cdim * Ntok, (long long)Cdim * Ntok);

    zero_k<<<(4 * ROWS / 4 + 255) / 256, 256>>>(stats, 4 * ROWS / 4);
    prep_k<<<Cdim / 8, 256>>>(Wres, g1, beta1);

    // qkv fused: x1, softmax->sm, v->cat2, LN1 stats (buf0)
    gemm_t5<8, 1><<<dim3(1, ROWS / 128, 1), 256, T5_SMEM>>>(
        mU, mWqkv, u, Cdim, 0, Wqkv, Cdim, 0, x1, Cdim, 0, Cdim,
        nullptr, nullptr, 0, nullptr, nullptr, nullptr, nullptr,
        rsum0, rsq0, 0, sm, vbuf, nullptr, nullptr, nullptr);

    // x1T (loop-invariant)
    transpose_k<<<dim3(Cdim / 32, Ntok / 32, Bsz), ttb>>>(
        x1, x1t, Ntok, Cdim, Cdim, (long long)Ntok * Cdim, (long long)Cdim * Ntok);

    for (int it = 0; it < 2; ++it) {
        float* rs = it == 0 ? rsum0 : rsum1;
        float* rq = it == 0 ? rsq0 : rsq1;

        // vT from cat2[:,256:512)
        transpose_k<<<dim3(Cdim / 32, Ntok / 32, Bsz), ttb>>>(
            vbuf, vt, Ntok, Cdim, C4, (long long)Ntok * C4, (long long)Cdim * Ntok);

        // g_ctx[d][c] = sum_n vT[d][n] * x1T[c][n]  (tcgen05 NT, split-K 8, atomic)
        zero_k<<<(Bsz * Cdim * Cdim / 4 + 255) / 256, 256>>>(ctx, (size_t)Bsz * Cdim * Cdim / 4);
        gemm_t5<32, 8><<<dim3(1, 2, Bsz * 8), 256, T5_SMEM>>>(
            mVt, mX1t, vt, Ntok, (long long)Cdim * Ntok, x1t, Ntok, (long long)Cdim * Ntok,
            ctx, Cdim, (long long)Cdim * Cdim, Ntok,
            nullptr, nullptr, 0, nullptr, nullptr, nullptr, nullptr,
            nullptr, nullptr, 0, nullptr, nullptr, nullptr, nullptr, nullptr);

        // out = sm @ ctx -> cat2[:,0:256], + stats
        gemm_t5<4, 1><<<dim3(1, Ntok / 128, Bsz), 256, T5_SMEM>>>(
            mSm, mCtx, sm, Cdim, (long long)Ntok * Cdim, ctx, Cdim, (long long)Cdim * Cdim,
            cat2, C4, (long long)Ntok * C4, Cdim,
            nullptr, nullptr, 0, nullptr, nullptr, nullptr, nullptr,
            rs, rq, Ntok, nullptr, nullptr, nullptr, nullptr, nullptr);

        // mlp = relu(cat1 @ Wmlp^T + b) -> cat2[:,512:1024], + stats (K=512, 2 n-tiles)
        gemm_t5<5, 1><<<dim3(2, ROWS / 128, 1), 256, T5_SMEM>>>(
            mCat2, mWmlp, cat2, C4, 0, Wmlp, 512, 0, cat2 + 512, C4, 0, 512,
            bmlp, nullptr, 0, nullptr, nullptr, nullptr, nullptr,
            rs, rq, 0, nullptr, nullptr, nullptr, nullptr, nullptr);

        // res + LN2 fused (K=1024); rs/rq passed via mu/rinv slots, finalized inline
        if (it == 0) {
            gemm_t5<16, 1><<<dim3(1, ROWS / 128, 1), 256, T5_SMEM>>>(
                mCat2, mWg, cat2, C4, 0, Wg, C4, 0, u, Cdim, 0, C4,
                nullptr, x1, Cdim, rs, rq, S1, S2,
                rsum1, rsq1, 0, nullptr, vbuf, g2, beta2, nullptr);
        } else {
            gemm_t5<17, 1><<<dim3(1, ROWS / 128, 1), 256, T5_SMEM>>>(
                mCat2, mWg, cat2, C4, 0, Wg, C4, 0, u, Cdim, 0, C4,
                nullptr, x1, Cdim, rs, rq, S1, S2,
                nullptr, nullptr, 0, nullptr, nullptr, g2, beta2, outp);
        }
    }
}

// round 13
// speedup vs baseline: 1.3191x; 1.2823x over previous
#include <cuda_runtime.h>
#include <cuda.h>
#include <cuda_fp16.h>
#include <math.h>
#include <stdint.h>

#define Bsz  8
#define Cdim 256
#define Ntok 4096
#define ROWS (Bsz * Ntok)          // 32768 token rows
#define C4   (4 * Cdim)            // 1024

// ---------------- scratch (static device arrays; no allocation) ----------------
__device__ float g_x1[(size_t)ROWS * Cdim];
__device__ float g_sm[(size_t)ROWS * Cdim];
__device__ float g_u[(size_t)ROWS * Cdim];          // transpose scratch
__device__ __half g_cat2[(size_t)ROWS * C4];        // [out | v | mlp], ld=1024, fp16
__device__ float g_ctx[(size_t)Bsz * Cdim * Cdim];  // g_ctx[d][c]
__device__ float g_x1t[(size_t)ROWS * Cdim];        // x1T[b][c][n]
__device__ float g_vt[(size_t)ROWS * Cdim];         // vT[b][c][n]
__device__ __half g_Wg16[(size_t)Cdim * C4];
__device__ __half g_Wmlp16[(size_t)512 * 512];
__device__ float g_S1[Cdim];
__device__ float g_S2[Cdim];
__device__ float g_stats[4 * ROWS];                 // rsum0|rsq0|rsum1|rsq1

#if defined(__CUDA_ARCH_FEAT_SM103_ALL) || defined(__CUDA_ARCH_FEAT_SM100_ALL)
#define HAS_TCGEN05 1
#else
#define HAS_TCGEN05 0
#endif

// ================= helpers ======================================================
__device__ __forceinline__ uint32_t smem_u32(const void* p) {
    return (uint32_t)__cvta_generic_to_shared(p);
}
__device__ __forceinline__ uint32_t elect1() {
    uint32_t pred;
    asm volatile("{\n\t.reg .pred p;\n\telect.sync _|p, 0xFFFFFFFF;\n\tselp.b32 %0, 1, 0, p;\n\t}"
                 : "=r"(pred));
    return pred;
}
__device__ __forceinline__ void mbar_init(uint32_t a, uint32_t cnt) {
    asm volatile("mbarrier.init.shared.b64 [%0], %1;" :: "r"(a), "r"(cnt) : "memory");
}
__device__ __forceinline__ void mbar_wait(uint32_t a, int ph) {
    asm volatile(
        "{\n\t.reg .pred P;\n\t"
        "WL%=:\n\t"
        "mbarrier.try_wait.parity.acquire.cta.shared::cta.b64 P, [%0], %1, 0x989680;\n\t"
        "@P bra.uni WD%=;\n\t"
        "bra.uni WL%=;\n\t"
        "WD%=:\n\t}"
        :: "r"(a), "r"(ph) : "memory");
}
__device__ __forceinline__ void mbar_expect_tx(uint32_t a, uint32_t bytes) {
    asm volatile("mbarrier.arrive.expect_tx.shared.b64 _, [%0], %1;"
                 :: "r"(a), "r"(bytes) : "memory");
}
__device__ __forceinline__ void tma3d(uint32_t dst, const void* map, int x, int y, int z,
                                      uint32_t mbar) {
    asm volatile(
        "cp.async.bulk.tensor.3d.shared::cta.global.tile.mbarrier::complete_tx::bytes "
        "[%0], [%1, {%2, %3, %4}], [%5];"
        :: "r"(dst), "l"(map), "r"(x), "r"(y), "r"(z), "r"(mbar) : "memory");
}
#define SW128B(o) ((o) ^ (((o) >> 3) & 0x70))

static constexpr unsigned long long DESC_SW128 =
    (2ull << 61) | (1ull << 46) | (64ull << 32) | (1ull << 16);
__device__ __forceinline__ uint64_t mk_desc(uint32_t addr) {
    return DESC_SW128 | ((uint64_t)(addr >> 4) & 0x3FFF);
}

__device__ __forceinline__ uint32_t cvt_tf32(float x) {
    uint32_t r;
    asm("cvt.rna.tf32.f32 %0, %1;" : "=r"(r) : "f"(x));
    return r;
}
__device__ __forceinline__ void cp16(float* s, const float* g) {
    uint32_t sa = smem_u32(s);
    asm volatile("cp.async.cg.shared.global [%0], [%1], 16;" :: "r"(sa), "l"(g));
}
__device__ __forceinline__ void cp_commit() { asm volatile("cp.async.commit_group;" ::); }
template <int N>
__device__ __forceinline__ void cp_wait() { asm volatile("cp.async.wait_group %0;" :: "n"(N)); }

__device__ __forceinline__ void mma8(float* c, const uint32_t* a, const uint32_t* b) {
    asm volatile(
        "mma.sync.aligned.m16n8k8.row.col.f32.tf32.tf32.f32 "
        "{%0,%1,%2,%3}, {%4,%5,%6,%7}, {%8,%9}, {%0,%1,%2,%3};"
        : "+f"(c[0]), "+f"(c[1]), "+f"(c[2]), "+f"(c[3])
        : "r"(a[0]), "r"(a[1]), "r"(a[2]), "r"(a[3]), "r"(b[0]), "r"(b[1]));
}

__device__ __forceinline__ void st_half4(__half* p, float4 v) {
    __half2 lo = __floats2half2_rn(v.x, v.y);
    __half2 hi = __floats2half2_rn(v.z, v.w);
    uint2 o;
    o.x = *(uint32_t*)&lo;
    o.y = *(uint32_t*)&hi;
    *(uint2*)p = o;
}

#define LDTM32(d, addr)                                                          \
    asm volatile(                                                                \
        "tcgen05.ld.sync.aligned.32x32b.x32.b32 "                                \
        "{%0, %1, %2, %3, %4, %5, %6, %7, "                                      \
        " %8, %9, %10, %11, %12, %13, %14, %15, "                                \
        " %16, %17, %18, %19, %20, %21, %22, %23, "                              \
        " %24, %25, %26, %27, %28, %29, %30, %31}, [%32];"                       \
        : "=r"(d[0]), "=r"(d[1]), "=r"(d[2]), "=r"(d[3]),                        \
          "=r"(d[4]), "=r"(d[5]), "=r"(d[6]), "=r"(d[7]),                        \
          "=r"(d[8]), "=r"(d[9]), "=r"(d[10]), "=r"(d[11]),                      \
          "=r"(d[12]), "=r"(d[13]), "=r"(d[14]), "=r"(d[15]),                    \
          "=r"(d[16]), "=r"(d[17]), "=r"(d[18]), "=r"(d[19]),                    \
          "=r"(d[20]), "=r"(d[21]), "=r"(d[22]), "=r"(d[23]),                    \
          "=r"(d[24]), "=r"(d[25]), "=r"(d[26]), "=r"(d[27]),                    \
          "=r"(d[28]), "=r"(d[29]), "=r"(d[30]), "=r"(d[31])                     \
        : "r"(addr));                                                            \
    asm volatile("tcgen05.wait::ld.sync.aligned;" ::: "memory")

// ================= unified NT GEMM, CTA tile 128x256, TMA mainloop =============
// HK=0: fp32 operands (kind::tf32, K-tile 32 floats)
// HK=1: fp16 operands (kind::f16, K-tile 64 halves) — same 128B SW128 rows
// EPI: 4 half-store+stats | 5 relu+bias half-store+stats |
//      8 qkv fused (x1 f32 + softmax f32 + v half + stats) |
//      16 res+LN2 -> half v + next stats | 17 res+LN2 -> transposed f32 outT |
//      32 atomic f32 accumulate (split-K)
// EPI 16/17: `mu` carries rsum, `rinv` carries rsq (stats finalized inline).
#define STG_BYTES 49152               // A 16K + B 32K
#define T5_SMEM (1024 + 2 * STG_BYTES)
#define TS 65                         // epilogue smem tile stride (floats)

__device__ __forceinline__ void nt_stage(const float* __restrict__ A, int lda,
                                         const float* __restrict__ B, int ldb,
                                         int bm, int bn, int k0,
                                         float* as, float* bs, int tid) {
#pragma unroll
    for (int i = 0; i < 4; i++) {
        int idx = tid + i * 256;
        int row = idx >> 3, c4 = (idx & 7) << 2;
        cp16(as + row * 36 + c4, A + (size_t)(bm + row) * lda + k0 + c4);
        cp16(bs + row * 36 + c4, B + (size_t)(bn + row) * ldb + k0 + c4);
    }
    cp_commit();
}

template <int EPI, int SPLITK, int HK>
__global__ __launch_bounds__(256)
void gemm_t5(const __grid_constant__ CUtensorMap tmA,
             const __grid_constant__ CUtensorMap tmB,
             const float* __restrict__ A, int lda, long long sA,
             const float* __restrict__ B, int ldb, long long sB,
             float* __restrict__ C, int ldc, long long sC, int K,
             const float* __restrict__ bias,
             const float* __restrict__ resid, int ldr,
             const float* __restrict__ mu, const float* __restrict__ rinv,
             const float* __restrict__ S1, const float* __restrict__ S2,
             float* __restrict__ rsum, float* __restrict__ rsq, long long sStat,
             float* __restrict__ smx, __half* __restrict__ halfOut,
             const float* __restrict__ g2, const float* __restrict__ b2,
             float* __restrict__ outT) {
    extern __shared__ char smem[];
    const int tid = threadIdx.x, wid = tid >> 5, lane = tid & 31;
    const int bz = blockIdx.z;
    const int batch = bz / SPLITK, ks = bz - batch * SPLITK;
    const int kchunk = K / SPLITK, kxoff = ks * kchunk;
    C += (size_t)batch * sC;
    if (EPI == 4) { halfOut += (size_t)batch * sC; }
    if (EPI == 4 || EPI == 5) { rsum += (size_t)batch * sStat; rsq += (size_t)batch * sStat; }
    const int bm = blockIdx.y * 128, bn = blockIdx.x * 256;
    constexpr int KTILE = HK ? 64 : 32;

#if HAS_TCGEN05
    uint32_t sb = smem_u32(smem);
    if (wid == 0) {
        asm volatile("tcgen05.alloc.cta_group::1.sync.aligned.shared::cta.b32 [%0], %1;"
                     :: "r"(sb), "r"(256) : "memory");
        asm volatile("tcgen05.relinquish_alloc_permit.cta_group::1.sync.aligned;");
    }
    if (tid == 0) {
        mbar_init(sb + 8, 1); mbar_init(sb + 16, 1);
        mbar_init(sb + 24, 1); mbar_init(sb + 32, 1);
    }
    __syncthreads();
    uint32_t tmem;
    asm volatile("ld.shared.b32 %0, [%1];" : "=r"(tmem) : "r"(sb));

    const int KT = kchunk / KTILE;
    const uint32_t IDESC = HK
        ? ((1u << 4) | (32u << 17) | (8u << 24))                          // f16 in, f32 acc
        : ((1u << 4) | (2u << 7) | (2u << 10) | (32u << 17) | (8u << 24)); // tf32

    if (wid == 0 && elect1()) {
#pragma unroll
        for (int s = 0; s < 2; s++) {
            uint32_t full = sb + 8 + s * 8;
            uint32_t dst = sb + 1024 + s * STG_BYTES;
            mbar_expect_tx(full, STG_BYTES);
            tma3d(dst, &tmA, kxoff + s * KTILE, bm, batch, full);
            tma3d(dst + 16384, &tmB, kxoff + s * KTILE, bn, batch, full);
        }
        int fph[2] = {0, 0}, eph[2] = {0, 0};
        for (int kt = 0; kt < KT; kt++) {
            int buf = kt & 1;
            mbar_wait(sb + 8 + buf * 8, fph[buf]); fph[buf] ^= 1;
            uint32_t base = sb + 1024 + buf * STG_BYTES;
            uint64_t ad = mk_desc(base);
            uint64_t bd = mk_desc(base + 16384);
#pragma unroll
            for (int s = 0; s < 4; s++) {
                uint32_t en = (kt > 0 || s > 0) ? 1u : 0u;
                if (HK) {
                    asm volatile(
                        "{\n\t.reg .pred p;\n\tsetp.ne.u32 p, %5, 0;\n\t"
                        "tcgen05.mma.cta_group::1.kind::f16 [%0], %1, %2, %3, {%4,%4,%4,%4}, p;\n\t}"
                        :: "r"(tmem), "l"(ad + s * 2), "l"(bd + s * 2), "r"(IDESC),
                           "r"(0u), "r"(en) : "memory");
                } else {
                    asm volatile(
                        "{\n\t.reg .pred p;\n\tsetp.ne.u32 p, %5, 0;\n\t"
                        "tcgen05.mma.cta_group::1.kind::tf32 [%0], %1, %2, %3, {%4,%4,%4,%4}, p;\n\t}"
                        :: "r"(tmem), "l"(ad + s * 2), "l"(bd + s * 2), "r"(IDESC),
                           "r"(0u), "r"(en) : "memory");
                }
            }
            asm volatile(
                "tcgen05.commit.cta_group::1.mbarrier::arrive::one.shared::cluster.b64 [%0];"
                :: "r"(sb + 24 + buf * 8) : "memory");
            if (kt + 2 < KT) {
                mbar_wait(sb + 24 + buf * 8, eph[buf]); eph[buf] ^= 1;
                uint32_t full = sb + 8 + buf * 8;
                mbar_expect_tx(full, STG_BYTES);
                tma3d(base, &tmA, kxoff + (kt + 2) * KTILE, bm, batch, full);
                tma3d(base + 16384, &tmB, kxoff + (kt + 2) * KTILE, bn, batch, full);
            }
        }
    }
    __syncthreads();
    mbar_wait(sb + 24 + ((KT - 1) & 1) * 8, (KT / 2 - 1) & 1);
    asm volatile("tcgen05.fence::after_thread_sync;" ::: "memory");

    const int rl = (wid & 3) * 32 + lane;     // local row 0..127 (TMEM lane)
    const int row = bm + rl;
    const int half = wid >> 2;
    const int cb = half * 128;
    float* s0 = (float*)(smem + 1024);        // [256] sum partials
    float* s1 = s0 + 256;                     // [256] sumsq partials
    float* s2 = s1 + 256;                     // [256] expsum partials
    float* s3 = s2 + 256;                     // [128] per-row scalar (softmax inv)
    float* tile = s3 + 256;                   // [128][TS] staging tile

    if (EPI == 17) {
        // ---- res+LN2 -> transposed out; stats finalized inline ----
        float mm = mu[row] * (1.f / 1024.f);
        float rv = rsqrtf(rinv[row] * (1.f / 1024.f) - mm * mm + 1e-5f);
        float ps = 0.f, pq = 0.f;
#pragma unroll
        for (int cc = 0; cc < 4; cc++) {
            uint32_t d[32];
            LDTM32(d, tmem + cb + cc * 32);
#pragma unroll
            for (int j = 0; j < 32; j++) {
                int c = cb + cc * 32 + j;
                float val = fmaf(rv, __uint_as_float(d[j]) - mm * S1[c], S2[c]) +
                            2.f * resid[(size_t)row * ldr + c];
                ps += val; pq += val * val;
            }
        }
        s0[half * 128 + rl] = ps;
        s1[half * 128 + rl] = pq;
        __syncthreads();
        float ts = s0[rl] + s0[128 + rl];
        float tq = s1[rl] + s1[128 + rl];
        float mu2 = ts * (1.f / 256.f);
        float r2 = rsqrtf(tq * (1.f / 256.f) - mu2 * mu2 + 1e-5f);
#pragma unroll
        for (int cc = 0; cc < 4; cc++) {
            uint32_t d[32];
            LDTM32(d, tmem + cb + cc * 32);
#pragma unroll
            for (int j = 0; j < 32; j++) {
                int c = cb + cc * 32 + j;
                float val = fmaf(rv, __uint_as_float(d[j]) - mm * S1[c], S2[c]) +
                            2.f * resid[(size_t)row * ldr + c];
                val = (val - mu2) * r2 * g2[c] + b2[c];
                int b = row >> 12, n = row & 4095;
                outT[((size_t)b * Cdim + c) * Ntok + n] = val;
            }
        }
    } else if (EPI == 8 || EPI == 16) {
        // ---- fused two-pass epilogue with smem-staged coalesced stores ----
        float rv = 0.f, mm = 0.f;
        if (EPI == 16) {
            mm = mu[row] * (1.f / 1024.f);
            rv = rsqrtf(rinv[row] * (1.f / 1024.f) - mm * mm + 1e-5f);
        }
        float ps = 0.f, pq = 0.f, pe = 0.f;
#pragma unroll
        for (int cc = 0; cc < 4; cc++) {
            uint32_t d[32];
            LDTM32(d, tmem + cb + cc * 32);
#pragma unroll
            for (int j = 0; j < 32; j++) {
                float val = __uint_as_float(d[j]);
                if (EPI == 16) {
                    int c = cb + cc * 32 + j;
                    val = fmaf(rv, val - mm * S1[c], S2[c]) +
                          2.f * resid[(size_t)row * ldr + c];
                }
                ps += val; pq += val * val;
                if (EPI == 8) pe += __expf(val);
            }
        }
        s0[half * 128 + rl] = ps;
        s1[half * 128 + rl] = pq;
        if (EPI == 8) s2[half * 128 + rl] = pe;
        __syncthreads();
        float ts = s0[rl] + s0[128 + rl];
        float tq = s1[rl] + s1[128 + rl];
        float mu2 = 0.f, r2 = 0.f;
        if (EPI == 8) {
            float inv = 1.f / (s2[rl] + s2[128 + rl]);
            if (half == 0) s3[rl] = inv;
        } else {
            mu2 = ts * (1.f / 256.f);
            r2 = rsqrtf(tq * (1.f / 256.f) - mu2 * mu2 + 1e-5f);
        }
        float vs = 0.f, vq = 0.f;
#pragma unroll
        for (int cc = 0; cc < 4; cc++) {
            uint32_t d[32];
            LDTM32(d, tmem + cb + cc * 32);
#pragma unroll
            for (int j = 0; j < 32; j++) {
                float val = __uint_as_float(d[j]);
                if (EPI == 16) {
                    int c = cb + cc * 32 + j;
                    val = fmaf(rv, val - mm * S1[c], S2[c]) +
                          2.f * resid[(size_t)row * ldr + c];
                    val = (val - mu2) * r2 * g2[c] + b2[c];
                    vs += val; vq += val * val;
                }
                tile[rl * TS + half * 32 + j] = val;
            }
            __syncthreads();
#pragma unroll
            for (int it2 = 0; it2 < 4; it2++) {
                int r = it2 * 32 + (tid >> 3);
                int cq = (tid & 7) * 4;
                size_t gr = (size_t)(bm + r);
#pragma unroll
                for (int h = 0; h < 2; h++) {
                    int c = h * 128 + cc * 32 + cq;
                    float4 v4;
                    v4.x = tile[r * TS + h * 32 + cq + 0];
                    v4.y = tile[r * TS + h * 32 + cq + 1];
                    v4.z = tile[r * TS + h * 32 + cq + 2];
                    v4.w = tile[r * TS + h * 32 + cq + 3];
                    if (EPI == 8) {
                        *(float4*)(C + gr * ldc + c) = v4;
                        st_half4(halfOut + gr * C4 + c, v4);
                        float iv = s3[r];
                        float4 e = make_float4(__expf(v4.x) * iv, __expf(v4.y) * iv,
                                               __expf(v4.z) * iv, __expf(v4.w) * iv);
                        *(float4*)(smx + gr * Cdim + c) = e;
                    } else {
                        st_half4(halfOut + gr * C4 + c, v4);
                    }
                }
            }
            __syncthreads();
        }
        if (EPI == 16) { atomicAdd(rsum + row, vs); atomicAdd(rsq + row, vq); }
        if (EPI == 8 && half == 0) { atomicAdd(rsum + row, ts); atomicAdd(rsq + row, tq); }
    } else if (EPI == 32) {
        // ---- split-K accumulate: staged + coalesced atomicAdd ----
#pragma unroll
        for (int cc = 0; cc < 4; cc++) {
            uint32_t d[32];
            LDTM32(d, tmem + cb + cc * 32);
#pragma unroll
            for (int j = 0; j < 32; j++)
                tile[rl * TS + half * 32 + j] = __uint_as_float(d[j]);
            __syncthreads();
#pragma unroll
            for (int it2 = 0; it2 < 4; it2++) {
                int r = it2 * 32 + (tid >> 3);
                int cq = (tid & 7) * 4;
                size_t gr = (size_t)(bm + r);
#pragma unroll
                for (int h = 0; h < 2; h++) {
                    int c = bn + h * 128 + cc * 32 + cq;
                    float* dst = C + gr * ldc + c;
                    atomicAdd(dst + 0, tile[r * TS + h * 32 + cq + 0]);
                    atomicAdd(dst + 1, tile[r * TS + h * 32 + cq + 1]);
                    atomicAdd(dst + 2, tile[r * TS + h * 32 + cq + 2]);
                    atomicAdd(dst + 3, tile[r * TS + h * 32 + cq + 3]);
                }
            }
            __syncthreads();
        }
    } else {
        // ---- EPI 4/5: streaming half-store via smem-staged coalesced store ----
        float ssum = 0.f, ssq = 0.f;
#pragma unroll
        for (int cc = 0; cc < 4; cc++) {
            uint32_t d[32];
            LDTM32(d, tmem + cb + cc * 32);
#pragma unroll
            for (int j = 0; j < 32; j++) {
                float val = __uint_as_float(d[j]);
                if (EPI & 1) val = fmaxf(val + bias[bn + cb + cc * 32 + j], 0.f);
                ssum += val; ssq += val * val;
                tile[rl * TS + half * 32 + j] = val;
            }
            __syncthreads();
#pragma unroll
            for (int it2 = 0; it2 < 4; it2++) {
                int r = it2 * 32 + (tid >> 3);
                int cq = (tid & 7) * 4;
                size_t gr = (size_t)(bm + r);
#pragma unroll
                for (int h = 0; h < 2; h++) {
                    int c = bn + h * 128 + cc * 32 + cq;
                    float4 v4;
                    v4.x = tile[r * TS + h * 32 + cq + 0];
                    v4.y = tile[r * TS + h * 32 + cq + 1];
                    v4.z = tile[r * TS + h * 32 + cq + 2];
                    v4.w = tile[r * TS + h * 32 + cq + 3];
                    st_half4(halfOut + gr * C4 + c, v4);
                }
            }
            __syncthreads();
        }
        atomicAdd(rsum + row, ssum);
        atomicAdd(rsq + row, ssq);
    }
    __syncthreads();
    if (wid == 0) {
        asm volatile("tcgen05.dealloc.cta_group::1.sync.aligned.b32 %0, %1;"
                     :: "r"(tmem), "r"(256));
    }
#else
    // -------- legacy fallback (compile-only on non-'a' targets; fp32 semantics) ----
    float* fsm = (float*)smem;
    constexpr int ABUF = 128 * 36;
    float* As = fsm;
    float* Bs = fsm + 2 * ABUF;
    const int wm = (wid >> 2) * 64, wn = (wid & 3) * 32;
    const int lq = lane >> 2, lr = lane & 3;
    const float* Ab = A + (size_t)batch * sA;
    const float* Bb = B + (size_t)batch * sB;
    for (int hf = 0; hf < 2; hf++) {
        int bnh = bn + hf * 128;
        float acc[4][4][4];
#pragma unroll
        for (int i = 0; i < 4; i++)
#pragma unroll
            for (int j = 0; j < 4; j++)
#pragma unroll
                for (int t = 0; t < 4; t++) acc[i][j][t] = 0.f;
        const int KT2 = kchunk / 32;
        nt_stage(Ab, lda, Bb, ldb, bm, bnh, kxoff, As, Bs, tid);
        for (int kt = 0; kt < KT2; kt++) {
            int buf = kt & 1;
            if (kt + 1 < KT2) {
                nt_stage(Ab, lda, Bb, ldb, bm, bnh, kxoff + (kt + 1) * 32,
                         As + ((kt + 1) & 1) * ABUF, Bs + ((kt + 1) & 1) * ABUF, tid);
                cp_wait<1>();
            } else cp_wait<0>();
            __syncthreads();
            const float* as = As + buf * ABUF;
            const float* bs = Bs + buf * ABUF;
#pragma unroll
            for (int kk = 0; kk < 4; kk++) {
                const int k0 = kk * 8;
                uint32_t af[4][4], bf[4][2];
#pragma unroll
                for (int i = 0; i < 4; i++) {
                    const float* p = as + (wm + i * 16 + lq) * 36 + k0 + lr;
                    af[i][0] = cvt_tf32(p[0]);
                    af[i][2] = cvt_tf32(p[4]);
                    const float* p8 = p + 8 * 36;
                    af[i][1] = cvt_tf32(p8[0]);
                    af[i][3] = cvt_tf32(p8[4]);
                }
#pragma unroll
                for (int j = 0; j < 4; j++) {
                    const float* p = bs + (wn + j * 8 + lq) * 36 + k0 + lr;
                    bf[j][0] = cvt_tf32(p[0]);
                    bf[j][1] = cvt_tf32(p[4]);
                }
#pragma unroll
                for (int i = 0; i < 4; i++)
#pragma unroll
                    for (int j = 0; j < 4; j++) mma8(acc[i][j], af[i], bf[j]);
            }
            __syncthreads();
        }
#pragma unroll
        for (int i = 0; i < 4; i++)
#pragma unroll
            for (int j = 0; j < 4; j++) {
                int c = bnh + wn + j * 8 + lr * 2;
#pragma unroll
                for (int rr = 0; rr < 2; rr++) {
                    int r2 = bm + wm + i * 16 + lq + rr * 8;
                    float v0 = acc[i][j][rr * 2 + 0], v1 = acc[i][j][rr * 2 + 1];
                    if (EPI & 1) {
                        v0 = fmaxf(v0 + bias[c], 0.f);
                        v1 = fmaxf(v1 + bias[c + 1], 0.f);
                    }
                    if (EPI == 32) {
                        atomicAdd(C + (size_t)r2 * ldc + c, v0);
                        atomicAdd(C + (size_t)r2 * ldc + c + 1, v1);
                    } else if (EPI == 4 || EPI == 5) {
                        halfOut[(size_t)r2 * C4 + c] = __float2half(v0);
                        halfOut[(size_t)r2 * C4 + c + 1] = __float2half(v1);
                    } else {
                        *(float2*)(C + (size_t)r2 * ldc + c) = make_float2(v0, v1);
                    }
                }
            }
        __syncthreads();
    }
#endif
}

// ================= elementwise kernels =========================================
__global__ void transpose_k(const float* __restrict__ in, float* __restrict__ out,
                            int R, int Cc, int ldin, long long sIn, long long sOut) {
    __shared__ float tile[32][33];
    in += (size_t)blockIdx.z * sIn;
    out += (size_t)blockIdx.z * sOut;
    int c0 = blockIdx.x * 32, r0 = blockIdx.y * 32;
    int tx = threadIdx.x, ty = threadIdx.y;
#pragma unroll
    for (int j = 0; j < 32; j += 8)
        tile[ty + j][tx] = in[(size_t)(r0 + ty + j) * ldin + c0 + tx];
    __syncthreads();
#pragma unroll
    for (int j = 0; j < 32; j += 8)
        out[(size_t)(c0 + ty + j) * R + r0 + tx] = tile[tx][ty + j];
}

// half in -> float out transpose
__global__ void transpose_h2f_k(const __half* __restrict__ in, float* __restrict__ out,
                                int R, int Cc, int ldin, long long sIn, long long sOut) {
    __shared__ float tile[32][33];
    in += (size_t)blockIdx.z * sIn;
    out += (size_t)blockIdx.z * sOut;
    int c0 = blockIdx.x * 32, r0 = blockIdx.y * 32;
    int tx = threadIdx.x, ty = threadIdx.y;
#pragma unroll
    for (int j = 0; j < 32; j += 8)
        tile[ty + j][tx] = __half2float(in[(size_t)(r0 + ty + j) * ldin + c0 + tx]);
    __syncthreads();
#pragma unroll
    for (int j = 0; j < 32; j += 8)
        out[(size_t)(c0 + ty + j) * R + r0 + tx] = tile[tx][ty + j];
}

__global__ void zero_k(float* __restrict__ p, size_t n4) {
    size_t i = (size_t)blockIdx.x * blockDim.x + threadIdx.x;
    if (i < n4) ((float4*)p)[i] = make_float4(0.f, 0.f, 0.f, 0.f);
}

__global__ void prep_k(const float* __restrict__ Wres, const float* __restrict__ g1,
                       const float* __restrict__ beta1) {
    int c = blockIdx.x * 8 + (threadIdx.x >> 5);
    int lane = threadIdx.x & 31;
    const float* wr = Wres + (size_t)c * C4;
    float s1 = 0.f, s2 = 0.f;
    for (int k = lane; k < C4; k += 32) {
        float w = wr[k], g = g1[k];
        __half hw = __float2half(g * w);
        g_Wg16[(size_t)c * C4 + k] = hw;
        s1 += __half2float(hw);       // match fp16-rounded GEMM weight exactly
        s2 += beta1[k] * w;
    }
#pragma unroll
    for (int o = 16; o; o >>= 1) {
        s1 += __shfl_xor_sync(0xffffffffu, s1, o);
        s2 += __shfl_xor_sync(0xffffffffu, s2, o);
    }
    if (lane == 0) { g_S1[c] = s1; g_S2[c] = s2; }
}

__global__ void cvt_wmlp_k(const float* __restrict__ w) {
    int i = blockIdx.x * 256 + threadIdx.x;
    g_Wmlp16[i] = __float2half(w[i]);
}

// ================= host launcher ================================================
typedef CUresult (*EncFn)(CUtensorMap*, CUtensorMapDataType, cuuint32_t, void*,
                          const cuuint64_t*, const cuuint64_t*, const cuuint32_t*,
                          const cuuint32_t*, CUtensorMapInterleave, CUtensorMapSwizzle,
                          CUtensorMapL2promotion, CUtensorMapFloatOOBfill);

static void mk_map(EncFn enc, CUtensorMap* m, void* ptr,
                   uint64_t d0, uint64_t d1, uint64_t d2,
                   uint64_t str1B, uint64_t str2B,
                   uint32_t box0, uint32_t box1, CUtensorMapDataType dt) {
    cuuint64_t dims[3] = {d0, d1, d2};
    cuuint64_t strides[2] = {str1B, str2B};
    cuuint32_t box[3] = {box0, box1, 1};
    cuuint32_t es[3] = {1, 1, 1};
    enc(m, dt, 3, ptr, dims, strides, box, es,
        CU_TENSOR_MAP_INTERLEAVE_NONE, CU_TENSOR_MAP_SWIZZLE_128B,
        CU_TENSOR_MAP_L2_PROMOTION_L2_128B, CU_TENSOR_MAP_FLOAT_OOB_FILL_NONE);
}

extern "C" void kernel_launch(void* const* d_in, const int* in_sizes, int n_in,
                              void* d_out, int out_size) {
    (void)in_sizes; (void)n_in; (void)out_size;
    const float* x     = (const float*)d_in[0];
    const float* Wqkv  = (const float*)d_in[1];
    const float* Wmlp  = (const float*)d_in[2];
    const float* bmlp  = (const float*)d_in[3];
    const float* g1    = (const float*)d_in[4];
    const float* beta1 = (const float*)d_in[5];
    const float* Wres  = (const float*)d_in[6];
    const float* g2    = (const float*)d_in[7];
    const float* beta2 = (const float*)d_in[8];
    float* outp = (float*)d_out;

    float *x1, *sm, *u, *ctx, *x1t, *vt, *S1, *S2, *stats;
    __half *cat2h, *wg16, *wmlp16;
    cudaGetSymbolAddress((void**)&x1, g_x1);
    cudaGetSymbolAddress((void**)&sm, g_sm);
    cudaGetSymbolAddress((void**)&u, g_u);
    cudaGetSymbolAddress((void**)&cat2h, g_cat2);
    cudaGetSymbolAddress((void**)&ctx, g_ctx);
    cudaGetSymbolAddress((void**)&x1t, g_x1t);
    cudaGetSymbolAddress((void**)&vt, g_vt);
    cudaGetSymbolAddress((void**)&wg16, g_Wg16);
    cudaGetSymbolAddress((void**)&wmlp16, g_Wmlp16);
    cudaGetSymbolAddress((void**)&S1, g_S1);
    cudaGetSymbolAddress((void**)&S2, g_S2);
    cudaGetSymbolAddress((void**)&stats, g_stats);
    float* rsum0 = stats;
    float* rsq0  = stats + ROWS;
    float* rsum1 = stats + 2 * ROWS;
    float* rsq1  = stats + 3 * ROWS;

    EncFn enc = nullptr;
    cudaDriverEntryPointQueryResult qr;
    cudaGetDriverEntryPoint("cuTensorMapEncodeTiled", (void**)&enc,
                            cudaEnableDefault, &qr);
    CUtensorMap mU, mWqkv, mSm, mCtx, mCat2h, mWmlp16, mWg16, mVt, mX1t;
    mk_map(enc, &mU, u, 256, 32768, 1, 1024, (uint64_t)32768 * 1024, 32, 128,
           CU_TENSOR_MAP_DATA_TYPE_FLOAT32);
    mk_map(enc, &mWqkv, (void*)Wqkv, 256, 256, 1, 1024, 256 * 1024, 32, 256,
           CU_TENSOR_MAP_DATA_TYPE_FLOAT32);
    mk_map(enc, &mSm, sm, 256, 4096, 8, 1024, (uint64_t)4096 * 1024, 32, 128,
           CU_TENSOR_MAP_DATA_TYPE_FLOAT32);
    mk_map(enc, &mCtx, ctx, 256, 256, 8, 1024, 256 * 1024, 32, 256,
           CU_TENSOR_MAP_DATA_TYPE_FLOAT32);
    mk_map(enc, &mCat2h, cat2h, 1024, 32768, 1, 2048, (uint64_t)32768 * 2048, 64, 128,
           CU_TENSOR_MAP_DATA_TYPE_FLOAT16);
    mk_map(enc, &mWmlp16, wmlp16, 512, 512, 1, 1024, 512 * 1024, 64, 256,
           CU_TENSOR_MAP_DATA_TYPE_FLOAT16);
    mk_map(enc, &mWg16, wg16, 1024, 256, 1, 2048, 256 * 2048, 64, 256,
           CU_TENSOR_MAP_DATA_TYPE_FLOAT16);
    mk_map(enc, &mVt, vt, 4096, 256, 8, 16384, (uint64_t)256 * 16384, 32, 128,
           CU_TENSOR_MAP_DATA_TYPE_FLOAT32);
    mk_map(enc, &mX1t, x1t, 4096, 256, 8, 16384, (uint64_t)256 * 16384, 32, 256,
           CU_TENSOR_MAP_DATA_TYPE_FLOAT32);

    cudaFuncSetAttribute(gemm_t5<8, 1, 0>, cudaFuncAttributeMaxDynamicSharedMemorySize, T5_SMEM);
    cudaFuncSetAttribute(gemm_t5<4, 1, 0>, cudaFuncAttributeMaxDynamicSharedMemorySize, T5_SMEM);
    cudaFuncSetAttribute(gemm_t5<5, 1, 1>, cudaFuncAttributeMaxDynamicSharedMemorySize, T5_SMEM);
    cudaFuncSetAttribute(gemm_t5<16, 1, 1>, cudaFuncAttributeMaxDynamicSharedMemorySize, T5_SMEM);
    cudaFuncSetAttribute(gemm_t5<17, 1, 1>, cudaFuncAttributeMaxDynamicSharedMemorySize, T5_SMEM);
    cudaFuncSetAttribute(gemm_t5<32, 8, 0>, cudaFuncAttributeMaxDynamicSharedMemorySize, T5_SMEM);

    __half* vbufh = cat2h + 256;   // v lives in cat2[:,256:512), ld C4, fp16

    dim3 ttb(32, 8);
    transpose_k<<<dim3(Ntok / 32, Cdim / 32, Bsz), ttb>>>(
        x, u, Cdim, Ntok, Ntok, (long long)Cdim * Ntok, (long long)Cdim * Ntok);

    zero_k<<<(4 * ROWS / 4 + 255) / 256, 256>>>(stats, 4 * ROWS / 4);
    prep_k<<<Cdim / 8, 256>>>(Wres, g1, beta1);
    cvt_wmlp_k<<<512 * 512 / 256, 256>>>(Wmlp);

    // qkv fused: x1 f32, softmax->sm f32, v->cat2 f16, LN1 stats (buf0)
    gemm_t5<8, 1, 0><<<dim3(1, ROWS / 128, 1), 256, T5_SMEM>>>(
        mU, mWqkv, u, Cdim, 0, Wqkv, Cdim, 0, x1, Cdim, 0, Cdim,
        nullptr, nullptr, 0, nullptr, nullptr, nullptr, nullptr,
        rsum0, rsq0, 0, sm, vbufh, nullptr, nullptr, nullptr);

    // x1T (loop-invariant)
    transpose_k<<<dim3(Cdim / 32, Ntok / 32, Bsz), ttb>>>(
        x1, x1t, Ntok, Cdim, Cdim, (long long)Ntok * Cdim, (long long)Cdim * Ntok);

    for (int it = 0; it < 2; ++it) {
        float* rs = it == 0 ? rsum0 : rsum1;
        float* rq = it == 0 ? rsq0 : rsq1;

        // vT (f32) from fp16 cat2[:,256:512)
        transpose_h2f_k<<<dim3(Cdim / 32, Ntok / 32, Bsz), ttb>>>(
            vbufh, vt, Ntok, Cdim, C4, (long long)Ntok * C4, (long long)Cdim * Ntok);

        // g_ctx[d][c] = sum_n vT[d][n] * x1T[c][n]  (tcgen05 NT, split-K 8, atomic)
        zero_k<<<(Bsz * Cdim * Cdim / 4 + 255) / 256, 256>>>(ctx, (size_t)Bsz * Cdim * Cdim / 4);
        gemm_t5<32, 8, 0><<<dim3(1, 2, Bsz * 8), 256, T5_SMEM>>>(
            mVt, mX1t, vt, Ntok, (long long)Cdim * Ntok, x1t, Ntok, (long long)Cdim * Ntok,
            ctx, Cdim, (long long)Cdim * Cdim, Ntok,
            nullptr, nullptr, 0, nullptr, nullptr, nullptr, nullptr,
            nullptr, nullptr, 0, nullptr, nullptr, nullptr, nullptr, nullptr);

        // out = sm @ ctx -> cat2[:,0:256] (f16), + stats
        gemm_t5<4, 1, 0><<<dim3(1, Ntok / 128, Bsz), 256, T5_SMEM>>>(
            mSm, mCtx, sm, Cdim, (long long)Ntok * Cdim, ctx, Cdim, (long long)Cdim * Cdim,
            u, Cdim, (long long)Ntok * C4, Cdim,
            nullptr, nullptr, 0, nullptr, nullptr, nullptr, nullptr,
            rs, rq, Ntok, nullptr, cat2h, nullptr, nullptr, nullptr);

        // mlp = relu(cat1 @ Wmlp16^T + b) -> cat2[:,512:1024] (f16), K=512 halves
        gemm_t5<5, 1, 1><<<dim3(2, ROWS / 128, 1), 256, T5_SMEM>>>(
            mCat2h, mWmlp16, nullptr, 0, 0, nullptr, 0, 0, u, Cdim, 0, 512,
            bmlp, nullptr, 0, nullptr, nullptr, nullptr, nullptr,
            rs, rq, 0, nullptr, cat2h + 512, nullptr, nullptr, nullptr);

        // res + LN2 fused (K=1024 halves); rs/rq via mu/rinv slots
        if (it == 0) {
            gemm_t5<16, 1, 1><<<dim3(1, ROWS / 128, 1), 256, T5_SMEM>>>(
                mCat2h, mWg16, nullptr, 0, 0, nullptr, 0, 0, u, Cdim, 0, C4,
                nullptr, x1, Cdim, rs, rq, S1, S2,
                rsum1, rsq1, 0, nullptr, vbufh, g2, beta2, nullptr);
        } else {
            gemm_t5<17, 1, 1><<<dim3(1, ROWS / 128, 1), 256, T5_SMEM>>>(
                mCat2h, mWg16, nullptr, 0, 0, nullptr, 0, 0, u, Cdim, 0, C4,
                nullptr, x1, Cdim, rs, rq, S1, S2,
                nullptr, nullptr, 0, nullptr, nullptr, g2, beta2, outp);
        }
    }
}

// round 14
// speedup vs baseline: 1.4110x; 1.0697x over previous
#include <cuda_runtime.h>
#include <cuda.h>
#include <cuda_fp16.h>
#include <math.h>
#include <stdint.h>

#define Bsz  8
#define Cdim 256
#define Ntok 4096
#define ROWS (Bsz * Ntok)          // 32768 token rows
#define C4   (4 * Cdim)            // 1024

// ---------------- scratch (static device arrays; no allocation) ----------------
__device__ float g_x1[(size_t)ROWS * Cdim];
__device__ __half g_sm16[(size_t)ROWS * Cdim];
__device__ float g_u[(size_t)ROWS * Cdim];          // transpose scratch
__device__ __half g_cat2[(size_t)ROWS * C4];        // [out | v | mlp], ld=1024, fp16
__device__ float g_ctx[(size_t)Bsz * Cdim * Cdim];  // fp32 split-K accumulator
__device__ __half g_ctx16[(size_t)Bsz * Cdim * Cdim];
__device__ __half g_x1t16[(size_t)ROWS * Cdim];     // x1T[b][c][n] fp16
__device__ __half g_vt16[(size_t)ROWS * Cdim];      // vT[b][c][n] fp16
__device__ __half g_Wg16[(size_t)Cdim * C4];
__device__ __half g_Wmlp16[(size_t)512 * 512];
__device__ float g_S1[Cdim];
__device__ float g_S2[Cdim];
__device__ float g_stats[4 * ROWS];                 // rsum0|rsq0|rsum1|rsq1

#if defined(__CUDA_ARCH_FEAT_SM103_ALL) || defined(__CUDA_ARCH_FEAT_SM100_ALL)
#define HAS_TCGEN05 1
#else
#define HAS_TCGEN05 0
#endif

// ================= helpers ======================================================
__device__ __forceinline__ uint32_t smem_u32(const void* p) {
    return (uint32_t)__cvta_generic_to_shared(p);
}
__device__ __forceinline__ uint32_t elect1() {
    uint32_t pred;
    asm volatile("{\n\t.reg .pred p;\n\telect.sync _|p, 0xFFFFFFFF;\n\tselp.b32 %0, 1, 0, p;\n\t}"
                 : "=r"(pred));
    return pred;
}
__device__ __forceinline__ void mbar_init(uint32_t a, uint32_t cnt) {
    asm volatile("mbarrier.init.shared.b64 [%0], %1;" :: "r"(a), "r"(cnt) : "memory");
}
__device__ __forceinline__ void mbar_wait(uint32_t a, int ph) {
    asm volatile(
        "{\n\t.reg .pred P;\n\t"
        "WL%=:\n\t"
        "mbarrier.try_wait.parity.acquire.cta.shared::cta.b64 P, [%0], %1, 0x989680;\n\t"
        "@P bra.uni WD%=;\n\t"
        "bra.uni WL%=;\n\t"
        "WD%=:\n\t}"
        :: "r"(a), "r"(ph) : "memory");
}
__device__ __forceinline__ void mbar_expect_tx(uint32_t a, uint32_t bytes) {
    asm volatile("mbarrier.arrive.expect_tx.shared.b64 _, [%0], %1;"
                 :: "r"(a), "r"(bytes) : "memory");
}
__device__ __forceinline__ void tma3d(uint32_t dst, const void* map, int x, int y, int z,
                                      uint32_t mbar) {
    asm volatile(
        "cp.async.bulk.tensor.3d.shared::cta.global.tile.mbarrier::complete_tx::bytes "
        "[%0], [%1, {%2, %3, %4}], [%5];"
        :: "r"(dst), "l"(map), "r"(x), "r"(y), "r"(z), "r"(mbar) : "memory");
}
#define SW128B(o) ((o) ^ (((o) >> 3) & 0x70))

static constexpr unsigned long long DESC_SW128 =
    (2ull << 61) | (1ull << 46) | (64ull << 32) | (1ull << 16);
__device__ __forceinline__ uint64_t mk_desc(uint32_t addr) {
    return DESC_SW128 | ((uint64_t)(addr >> 4) & 0x3FFF);
}

__device__ __forceinline__ uint32_t cvt_tf32(float x) {
    uint32_t r;
    asm("cvt.rna.tf32.f32 %0, %1;" : "=r"(r) : "f"(x));
    return r;
}
__device__ __forceinline__ void cp16(float* s, const float* g) {
    uint32_t sa = smem_u32(s);
    asm volatile("cp.async.cg.shared.global [%0], [%1], 16;" :: "r"(sa), "l"(g));
}
__device__ __forceinline__ void cp_commit() { asm volatile("cp.async.commit_group;" ::); }
template <int N>
__device__ __forceinline__ void cp_wait() { asm volatile("cp.async.wait_group %0;" :: "n"(N)); }

__device__ __forceinline__ void mma8(float* c, const uint32_t* a, const uint32_t* b) {
    asm volatile(
        "mma.sync.aligned.m16n8k8.row.col.f32.tf32.tf32.f32 "
        "{%0,%1,%2,%3}, {%4,%5,%6,%7}, {%8,%9}, {%0,%1,%2,%3};"
        : "+f"(c[0]), "+f"(c[1]), "+f"(c[2]), "+f"(c[3])
        : "r"(a[0]), "r"(a[1]), "r"(a[2]), "r"(a[3]), "r"(b[0]), "r"(b[1]));
}

__device__ __forceinline__ void st_half4(__half* p, float4 v) {
    __half2 lo = __floats2half2_rn(v.x, v.y);
    __half2 hi = __floats2half2_rn(v.z, v.w);
    uint2 o;
    o.x = *(uint32_t*)&lo;
    o.y = *(uint32_t*)&hi;
    *(uint2*)p = o;
}

#define LDTM32(d, addr)                                                          \
    asm volatile(                                                                \
        "tcgen05.ld.sync.aligned.32x32b.x32.b32 "                                \
        "{%0, %1, %2, %3, %4, %5, %6, %7, "                                      \
        " %8, %9, %10, %11, %12, %13, %14, %15, "                                \
        " %16, %17, %18, %19, %20, %21, %22, %23, "                              \
        " %24, %25, %26, %27, %28, %29, %30, %31}, [%32];"                       \
        : "=r"(d[0]), "=r"(d[1]), "=r"(d[2]), "=r"(d[3]),                        \
          "=r"(d[4]), "=r"(d[5]), "=r"(d[6]), "=r"(d[7]),                        \
          "=r"(d[8]), "=r"(d[9]), "=r"(d[10]), "=r"(d[11]),                      \
          "=r"(d[12]), "=r"(d[13]), "=r"(d[14]), "=r"(d[15]),                    \
          "=r"(d[16]), "=r"(d[17]), "=r"(d[18]), "=r"(d[19]),                    \
          "=r"(d[20]), "=r"(d[21]), "=r"(d[22]), "=r"(d[23]),                    \
          "=r"(d[24]), "=r"(d[25]), "=r"(d[26]), "=r"(d[27]),                    \
          "=r"(d[28]), "=r"(d[29]), "=r"(d[30]), "=r"(d[31])                     \
        : "r"(addr));                                                            \
    asm volatile("tcgen05.wait::ld.sync.aligned;" ::: "memory")

// ================= unified NT GEMM, CTA tile 128x256, TMA mainloop =============
// HK=0: fp32 operands (kind::tf32, K-tile 32 floats)
// HK=1: fp16 operands (kind::f16, K-tile 64 halves) — same 128B SW128 rows
// EPI: 4 half-store+stats | 5 relu+bias half-store+stats |
//      8 qkv fused (x1 f32 + softmax f16 + v half + stats) |
//      16 res+LN2 -> half v + next stats | 17 res+LN2 -> transposed f32 outT |
//      32 atomic f32 accumulate (split-K)
// EPI 16/17: `mu` carries rsum, `rinv` carries rsq (stats finalized inline).
#define STG_BYTES 49152               // A 16K + B 32K
#define T5_SMEM (1024 + 2 * STG_BYTES)
#define TS 65                         // epilogue smem tile stride (floats)

__device__ __forceinline__ void nt_stage(const float* __restrict__ A, int lda,
                                         const float* __restrict__ B, int ldb,
                                         int bm, int bn, int k0,
                                         float* as, float* bs, int tid) {
#pragma unroll
    for (int i = 0; i < 4; i++) {
        int idx = tid + i * 256;
        int row = idx >> 3, c4 = (idx & 7) << 2;
        cp16(as + row * 36 + c4, A + (size_t)(bm + row) * lda + k0 + c4);
        cp16(bs + row * 36 + c4, B + (size_t)(bn + row) * ldb + k0 + c4);
    }
    cp_commit();
}

template <int EPI, int SPLITK, int HK>
__global__ __launch_bounds__(256)
void gemm_t5(const __grid_constant__ CUtensorMap tmA,
             const __grid_constant__ CUtensorMap tmB,
             const float* __restrict__ A, int lda, long long sA,
             const float* __restrict__ B, int ldb, long long sB,
             float* __restrict__ C, int ldc, long long sC, int K,
             const float* __restrict__ bias,
             const float* __restrict__ resid, int ldr,
             const float* __restrict__ mu, const float* __restrict__ rinv,
             const float* __restrict__ S1, const float* __restrict__ S2,
             float* __restrict__ rsum, float* __restrict__ rsq, long long sStat,
             __half* __restrict__ smx, __half* __restrict__ halfOut,
             const float* __restrict__ g2, const float* __restrict__ b2,
             float* __restrict__ outT) {
    extern __shared__ char smem[];
    const int tid = threadIdx.x, wid = tid >> 5, lane = tid & 31;
    const int bz = blockIdx.z;
    const int batch = bz / SPLITK, ks = bz - batch * SPLITK;
    const int kchunk = K / SPLITK, kxoff = ks * kchunk;
    C += (size_t)batch * sC;
    if (EPI == 4) { halfOut += (size_t)batch * sC; }
    if (EPI == 4 || EPI == 5) { rsum += (size_t)batch * sStat; rsq += (size_t)batch * sStat; }
    const int bm = blockIdx.y * 128, bn = blockIdx.x * 256;
    constexpr int KTILE = HK ? 64 : 32;

#if HAS_TCGEN05
    uint32_t sb = smem_u32(smem);
    if (wid == 0) {
        asm volatile("tcgen05.alloc.cta_group::1.sync.aligned.shared::cta.b32 [%0], %1;"
                     :: "r"(sb), "r"(256) : "memory");
        asm volatile("tcgen05.relinquish_alloc_permit.cta_group::1.sync.aligned;");
    }
    if (tid == 0) {
        mbar_init(sb + 8, 1); mbar_init(sb + 16, 1);
        mbar_init(sb + 24, 1); mbar_init(sb + 32, 1);
    }
    __syncthreads();
    uint32_t tmem;
    asm volatile("ld.shared.b32 %0, [%1];" : "=r"(tmem) : "r"(sb));

    const int KT = kchunk / KTILE;
    const uint32_t IDESC = HK
        ? ((1u << 4) | (32u << 17) | (8u << 24))                          // f16 in, f32 acc
        : ((1u << 4) | (2u << 7) | (2u << 10) | (32u << 17) | (8u << 24)); // tf32

    if (wid == 0 && elect1()) {
#pragma unroll
        for (int s = 0; s < 2; s++) {
            uint32_t full = sb + 8 + s * 8;
            uint32_t dst = sb + 1024 + s * STG_BYTES;
            mbar_expect_tx(full, STG_BYTES);
            tma3d(dst, &tmA, kxoff + s * KTILE, bm, batch, full);
            tma3d(dst + 16384, &tmB, kxoff + s * KTILE, bn, batch, full);
        }
        int fph[2] = {0, 0}, eph[2] = {0, 0};
        for (int kt = 0; kt < KT; kt++) {
            int buf = kt & 1;
            mbar_wait(sb + 8 + buf * 8, fph[buf]); fph[buf] ^= 1;
            uint32_t base = sb + 1024 + buf * STG_BYTES;
            uint64_t ad = mk_desc(base);
            uint64_t bd = mk_desc(base + 16384);
#pragma unroll
            for (int s = 0; s < 4; s++) {
                uint32_t en = (kt > 0 || s > 0) ? 1u : 0u;
                if (HK) {
                    asm volatile(
                        "{\n\t.reg .pred p;\n\tsetp.ne.u32 p, %5, 0;\n\t"
                        "tcgen05.mma.cta_group::1.kind::f16 [%0], %1, %2, %3, {%4,%4,%4,%4}, p;\n\t}"
                        :: "r"(tmem), "l"(ad + s * 2), "l"(bd + s * 2), "r"(IDESC),
                           "r"(0u), "r"(en) : "memory");
                } else {
                    asm volatile(
                        "{\n\t.reg .pred p;\n\tsetp.ne.u32 p, %5, 0;\n\t"
                        "tcgen05.mma.cta_group::1.kind::tf32 [%0], %1, %2, %3, {%4,%4,%4,%4}, p;\n\t}"
                        :: "r"(tmem), "l"(ad + s * 2), "l"(bd + s * 2), "r"(IDESC),
                           "r"(0u), "r"(en) : "memory");
                }
            }
            asm volatile(
                "tcgen05.commit.cta_group::1.mbarrier::arrive::one.shared::cluster.b64 [%0];"
                :: "r"(sb + 24 + buf * 8) : "memory");
            if (kt + 2 < KT) {
                mbar_wait(sb + 24 + buf * 8, eph[buf]); eph[buf] ^= 1;
                uint32_t full = sb + 8 + buf * 8;
                mbar_expect_tx(full, STG_BYTES);
                tma3d(base, &tmA, kxoff + (kt + 2) * KTILE, bm, batch, full);
                tma3d(base + 16384, &tmB, kxoff + (kt + 2) * KTILE, bn, batch, full);
            }
        }
    }
    __syncthreads();
    mbar_wait(sb + 24 + ((KT - 1) & 1) * 8, (KT / 2 - 1) & 1);
    asm volatile("tcgen05.fence::after_thread_sync;" ::: "memory");

    const int rl = (wid & 3) * 32 + lane;     // local row 0..127 (TMEM lane)
    const int row = bm + rl;
    const int half = wid >> 2;
    const int cb = half * 128;
    float* s0 = (float*)(smem + 1024);        // [256] sum partials
    float* s1 = s0 + 256;                     // [256] sumsq partials
    float* s2 = s1 + 256;                     // [256] expsum partials
    float* s3 = s2 + 256;                     // [128] per-row scalar (softmax inv)
    float* tile = s3 + 256;                   // [128][TS] staging tile

    if (EPI == 17) {
        // ---- res+LN2 -> transposed out; stats finalized inline ----
        float mm = mu[row] * (1.f / 1024.f);
        float rv = rsqrtf(rinv[row] * (1.f / 1024.f) - mm * mm + 1e-5f);
        float ps = 0.f, pq = 0.f;
#pragma unroll
        for (int cc = 0; cc < 4; cc++) {
            uint32_t d[32];
            LDTM32(d, tmem + cb + cc * 32);
#pragma unroll
            for (int j = 0; j < 32; j++) {
                int c = cb + cc * 32 + j;
                float val = fmaf(rv, __uint_as_float(d[j]) - mm * S1[c], S2[c]) +
                            2.f * resid[(size_t)row * ldr + c];
                ps += val; pq += val * val;
            }
        }
        s0[half * 128 + rl] = ps;
        s1[half * 128 + rl] = pq;
        __syncthreads();
        float ts = s0[rl] + s0[128 + rl];
        float tq = s1[rl] + s1[128 + rl];
        float mu2 = ts * (1.f / 256.f);
        float r2 = rsqrtf(tq * (1.f / 256.f) - mu2 * mu2 + 1e-5f);
#pragma unroll
        for (int cc = 0; cc < 4; cc++) {
            uint32_t d[32];
            LDTM32(d, tmem + cb + cc * 32);
#pragma unroll
            for (int j = 0; j < 32; j++) {
                int c = cb + cc * 32 + j;
                float val = fmaf(rv, __uint_as_float(d[j]) - mm * S1[c], S2[c]) +
                            2.f * resid[(size_t)row * ldr + c];
                val = (val - mu2) * r2 * g2[c] + b2[c];
                int b = row >> 12, n = row & 4095;
                outT[((size_t)b * Cdim + c) * Ntok + n] = val;
            }
        }
    } else if (EPI == 8 || EPI == 16) {
        // ---- fused two-pass epilogue with smem-staged coalesced stores ----
        float rv = 0.f, mm = 0.f;
        if (EPI == 16) {
            mm = mu[row] * (1.f / 1024.f);
            rv = rsqrtf(rinv[row] * (1.f / 1024.f) - mm * mm + 1e-5f);
        }
        float ps = 0.f, pq = 0.f, pe = 0.f;
#pragma unroll
        for (int cc = 0; cc < 4; cc++) {
            uint32_t d[32];
            LDTM32(d, tmem + cb + cc * 32);
#pragma unroll
            for (int j = 0; j < 32; j++) {
                float val = __uint_as_float(d[j]);
                if (EPI == 16) {
                    int c = cb + cc * 32 + j;
                    val = fmaf(rv, val - mm * S1[c], S2[c]) +
                          2.f * resid[(size_t)row * ldr + c];
                }
                ps += val; pq += val * val;
                if (EPI == 8) pe += __expf(val);
            }
        }
        s0[half * 128 + rl] = ps;
        s1[half * 128 + rl] = pq;
        if (EPI == 8) s2[half * 128 + rl] = pe;
        __syncthreads();
        float ts = s0[rl] + s0[128 + rl];
        float tq = s1[rl] + s1[128 + rl];
        float mu2 = 0.f, r2 = 0.f;
        if (EPI == 8) {
            float inv = 1.f / (s2[rl] + s2[128 + rl]);
            if (half == 0) s3[rl] = inv;
        } else {
            mu2 = ts * (1.f / 256.f);
            r2 = rsqrtf(tq * (1.f / 256.f) - mu2 * mu2 + 1e-5f);
        }
        float vs = 0.f, vq = 0.f;
#pragma unroll
        for (int cc = 0; cc < 4; cc++) {
            uint32_t d[32];
            LDTM32(d, tmem + cb + cc * 32);
#pragma unroll
            for (int j = 0; j < 32; j++) {
                float val = __uint_as_float(d[j]);
                if (EPI == 16) {
                    int c = cb + cc * 32 + j;
                    val = fmaf(rv, val - mm * S1[c], S2[c]) +
                          2.f * resid[(size_t)row * ldr + c];
                    val = (val - mu2) * r2 * g2[c] + b2[c];
                    vs += val; vq += val * val;
                }
                tile[rl * TS + half * 32 + j] = val;
            }
            __syncthreads();
#pragma unroll
            for (int it2 = 0; it2 < 4; it2++) {
                int r = it2 * 32 + (tid >> 3);
                int cq = (tid & 7) * 4;
                size_t gr = (size_t)(bm + r);
#pragma unroll
                for (int h = 0; h < 2; h++) {
                    int c = h * 128 + cc * 32 + cq;
                    float4 v4;
                    v4.x = tile[r * TS + h * 32 + cq + 0];
                    v4.y = tile[r * TS + h * 32 + cq + 1];
                    v4.z = tile[r * TS + h * 32 + cq + 2];
                    v4.w = tile[r * TS + h * 32 + cq + 3];
                    if (EPI == 8) {
                        *(float4*)(C + gr * ldc + c) = v4;
                        st_half4(halfOut + gr * C4 + c, v4);
                        float iv = s3[r];
                        float4 e = make_float4(__expf(v4.x) * iv, __expf(v4.y) * iv,
                                               __expf(v4.z) * iv, __expf(v4.w) * iv);
                        st_half4(smx + gr * Cdim + c, e);
                    } else {
                        st_half4(halfOut + gr * C4 + c, v4);
                    }
                }
            }
            __syncthreads();
        }
        if (EPI == 16) { atomicAdd(rsum + row, vs); atomicAdd(rsq + row, vq); }
        if (EPI == 8 && half == 0) { atomicAdd(rsum + row, ts); atomicAdd(rsq + row, tq); }
    } else if (EPI == 32) {
        // ---- split-K accumulate: staged + coalesced atomicAdd ----
#pragma unroll
        for (int cc = 0; cc < 4; cc++) {
            uint32_t d[32];
            LDTM32(d, tmem + cb + cc * 32);
#pragma unroll
            for (int j = 0; j < 32; j++)
                tile[rl * TS + half * 32 + j] = __uint_as_float(d[j]);
            __syncthreads();
#pragma unroll
            for (int it2 = 0; it2 < 4; it2++) {
                int r = it2 * 32 + (tid >> 3);
                int cq = (tid & 7) * 4;
                size_t gr = (size_t)(bm + r);
#pragma unroll
                for (int h = 0; h < 2; h++) {
                    int c = bn + h * 128 + cc * 32 + cq;
                    float* dst = C + gr * ldc + c;
                    atomicAdd(dst + 0, tile[r * TS + h * 32 + cq + 0]);
                    atomicAdd(dst + 1, tile[r * TS + h * 32 + cq + 1]);
                    atomicAdd(dst + 2, tile[r * TS + h * 32 + cq + 2]);
                    atomicAdd(dst + 3, tile[r * TS + h * 32 + cq + 3]);
                }
            }
            __syncthreads();
        }
    } else {
        // ---- EPI 4/5: streaming half-store via smem-staged coalesced store ----
        float ssum = 0.f, ssq = 0.f;
#pragma unroll
        for (int cc = 0; cc < 4; cc++) {
            uint32_t d[32];
            LDTM32(d, tmem + cb + cc * 32);
#pragma unroll
            for (int j = 0; j < 32; j++) {
                float val = __uint_as_float(d[j]);
                if (EPI & 1) val = fmaxf(val + bias[bn + cb + cc * 32 + j], 0.f);
                ssum += val; ssq += val * val;
                tile[rl * TS + half * 32 + j] = val;
            }
            __syncthreads();
#pragma unroll
            for (int it2 = 0; it2 < 4; it2++) {
                int r = it2 * 32 + (tid >> 3);
                int cq = (tid & 7) * 4;
                size_t gr = (size_t)(bm + r);
#pragma unroll
                for (int h = 0; h < 2; h++) {
                    int c = bn + h * 128 + cc * 32 + cq;
                    float4 v4;
                    v4.x = tile[r * TS + h * 32 + cq + 0];
                    v4.y = tile[r * TS + h * 32 + cq + 1];
                    v4.z = tile[r * TS + h * 32 + cq + 2];
                    v4.w = tile[r * TS + h * 32 + cq + 3];
                    st_half4(halfOut + gr * C4 + c, v4);
                }
            }
            __syncthreads();
        }
        atomicAdd(rsum + row, ssum);
        atomicAdd(rsq + row, ssq);
    }
    __syncthreads();
    if (wid == 0) {
        asm volatile("tcgen05.dealloc.cta_group::1.sync.aligned.b32 %0, %1;"
                     :: "r"(tmem), "r"(256));
    }
#else
    // -------- legacy fallback (compile-only on non-'a' targets; fp32 semantics) ----
    float* fsm = (float*)smem;
    constexpr int ABUF = 128 * 36;
    float* As = fsm;
    float* Bs = fsm + 2 * ABUF;
    const int wm = (wid >> 2) * 64, wn = (wid & 3) * 32;
    const int lq = lane >> 2, lr = lane & 3;
    const float* Ab = A + (size_t)batch * sA;
    const float* Bb = B + (size_t)batch * sB;
    for (int hf = 0; hf < 2; hf++) {
        int bnh = bn + hf * 128;
        float acc[4][4][4];
#pragma unroll
        for (int i = 0; i < 4; i++)
#pragma unroll
            for (int j = 0; j < 4; j++)
#pragma unroll
                for (int t = 0; t < 4; t++) acc[i][j][t] = 0.f;
        const int KT2 = kchunk / 32;
        nt_stage(Ab, lda, Bb, ldb, bm, bnh, kxoff, As, Bs, tid);
        for (int kt = 0; kt < KT2; kt++) {
            int buf = kt & 1;
            if (kt + 1 < KT2) {
                nt_stage(Ab, lda, Bb, ldb, bm, bnh, kxoff + (kt + 1) * 32,
                         As + ((kt + 1) & 1) * ABUF, Bs + ((kt + 1) & 1) * ABUF, tid);
                cp_wait<1>();
            } else cp_wait<0>();
            __syncthreads();
            const float* as = As + buf * ABUF;
            const float* bs = Bs + buf * ABUF;
#pragma unroll
            for (int kk = 0; kk < 4; kk++) {
                const int k0 = kk * 8;
                uint32_t af[4][4], bf[4][2];
#pragma unroll
                for (int i = 0; i < 4; i++) {
                    const float* p = as + (wm + i * 16 + lq) * 36 + k0 + lr;
                    af[i][0] = cvt_tf32(p[0]);
                    af[i][2] = cvt_tf32(p[4]);
                    const float* p8 = p + 8 * 36;
                    af[i][1] = cvt_tf32(p8[0]);
                    af[i][3] = cvt_tf32(p8[4]);
                }
#pragma unroll
                for (int j = 0; j < 4; j++) {
                    const float* p = bs + (wn + j * 8 + lq) * 36 + k0 + lr;
                    bf[j][0] = cvt_tf32(p[0]);
                    bf[j][1] = cvt_tf32(p[4]);
                }
#pragma unroll
                for (int i = 0; i < 4; i++)
#pragma unroll
                    for (int j = 0; j < 4; j++) mma8(acc[i][j], af[i], bf[j]);
            }
            __syncthreads();
        }
#pragma unroll
        for (int i = 0; i < 4; i++)
#pragma unroll
            for (int j = 0; j < 4; j++) {
                int c = bnh + wn + j * 8 + lr * 2;
#pragma unroll
                for (int rr = 0; rr < 2; rr++) {
                    int r2 = bm + wm + i * 16 + lq + rr * 8;
                    float v0 = acc[i][j][rr * 2 + 0], v1 = acc[i][j][rr * 2 + 1];
                    if (EPI & 1) {
                        v0 = fmaxf(v0 + bias[c], 0.f);
                        v1 = fmaxf(v1 + bias[c + 1], 0.f);
                    }
                    if (EPI == 32) {
                        atomicAdd(C + (size_t)r2 * ldc + c, v0);
                        atomicAdd(C + (size_t)r2 * ldc + c + 1, v1);
                    } else if (EPI == 4 || EPI == 5) {
                        halfOut[(size_t)r2 * C4 + c] = __float2half(v0);
                        halfOut[(size_t)r2 * C4 + c + 1] = __float2half(v1);
                    } else {
                        *(float2*)(C + (size_t)r2 * ldc + c) = make_float2(v0, v1);
                    }
                }
            }
        __syncthreads();
    }
#endif
}

// ================= elementwise kernels =========================================
__global__ void transpose_k(const float* __restrict__ in, float* __restrict__ out,
                            int R, int Cc, int ldin, long long sIn, long long sOut) {
    __shared__ float tile[32][33];
    in += (size_t)blockIdx.z * sIn;
    out += (size_t)blockIdx.z * sOut;
    int c0 = blockIdx.x * 32, r0 = blockIdx.y * 32;
    int tx = threadIdx.x, ty = threadIdx.y;
#pragma unroll
    for (int j = 0; j < 32; j += 8)
        tile[ty + j][tx] = in[(size_t)(r0 + ty + j) * ldin + c0 + tx];
    __syncthreads();
#pragma unroll
    for (int j = 0; j < 32; j += 8)
        out[(size_t)(c0 + ty + j) * R + r0 + tx] = tile[tx][ty + j];
}

// float in -> half out transpose
__global__ void transpose_f2h_k(const float* __restrict__ in, __half* __restrict__ out,
                                int R, int Cc, int ldin, long long sIn, long long sOut) {
    __shared__ float tile[32][33];
    in += (size_t)blockIdx.z * sIn;
    out += (size_t)blockIdx.z * sOut;
    int c0 = blockIdx.x * 32, r0 = blockIdx.y * 32;
    int tx = threadIdx.x, ty = threadIdx.y;
#pragma unroll
    for (int j = 0; j < 32; j += 8)
        tile[ty + j][tx] = in[(size_t)(r0 + ty + j) * ldin + c0 + tx];
    __syncthreads();
#pragma unroll
    for (int j = 0; j < 32; j += 8)
        out[(size_t)(c0 + ty + j) * R + r0 + tx] = __float2half(tile[tx][ty + j]);
}

// half in -> half out transpose
__global__ void transpose_h2h_k(const __half* __restrict__ in, __half* __restrict__ out,
                                int R, int Cc, int ldin, long long sIn, long long sOut) {
    __shared__ __half tile[32][34];
    in += (size_t)blockIdx.z * sIn;
    out += (size_t)blockIdx.z * sOut;
    int c0 = blockIdx.x * 32, r0 = blockIdx.y * 32;
    int tx = threadIdx.x, ty = threadIdx.y;
#pragma unroll
    for (int j = 0; j < 32; j += 8)
        tile[ty + j][tx] = in[(size_t)(r0 + ty + j) * ldin + c0 + tx];
    __syncthreads();
#pragma unroll
    for (int j = 0; j < 32; j += 8)
        out[(size_t)(c0 + ty + j) * R + r0 + tx] = tile[tx][ty + j];
}

__global__ void zero_k(float* __restrict__ p, size_t n4) {
    size_t i = (size_t)blockIdx.x * blockDim.x + threadIdx.x;
    if (i < n4) ((float4*)p)[i] = make_float4(0.f, 0.f, 0.f, 0.f);
}

__global__ void cvt_ctx_k(const float* __restrict__ in, __half* __restrict__ out) {
    int i = blockIdx.x * 256 + threadIdx.x;
    float2 v = ((const float2*)in)[i];
    __half2 h = __floats2half2_rn(v.x, v.y);
    ((__half2*)out)[i] = h;
}

__global__ void prep_k(const float* __restrict__ Wres, const float* __restrict__ g1,
                       const float* __restrict__ beta1) {
    int c = blockIdx.x * 8 + (threadIdx.x >> 5);
    int lane = threadIdx.x & 31;
    const float* wr = Wres + (size_t)c * C4;
    float s1 = 0.f, s2 = 0.f;
    for (int k = lane; k < C4; k += 32) {
        float w = wr[k], g = g1[k];
        __half hw = __float2half(g * w);
        g_Wg16[(size_t)c * C4 + k] = hw;
        s1 += __half2float(hw);       // match fp16-rounded GEMM weight exactly
        s2 += beta1[k] * w;
    }
#pragma unroll
    for (int o = 16; o; o >>= 1) {
        s1 += __shfl_xor_sync(0xffffffffu, s1, o);
        s2 += __shfl_xor_sync(0xffffffffu, s2, o);
    }
    if (lane == 0) { g_S1[c] = s1; g_S2[c] = s2; }
}

__global__ void cvt_wmlp_k(const float* __restrict__ w) {
    int i = blockIdx.x * 256 + threadIdx.x;
    g_Wmlp16[i] = __float2half(w[i]);
}

// ================= host launcher ================================================
typedef CUresult (*EncFn)(CUtensorMap*, CUtensorMapDataType, cuuint32_t, void*,
                          const cuuint64_t*, const cuuint64_t*, const cuuint32_t*,
                          const cuuint32_t*, CUtensorMapInterleave, CUtensorMapSwizzle,
                          CUtensorMapL2promotion, CUtensorMapFloatOOBfill);

static void mk_map(EncFn enc, CUtensorMap* m, void* ptr,
                   uint64_t d0, uint64_t d1, uint64_t d2,
                   uint64_t str1B, uint64_t str2B,
                   uint32_t box0, uint32_t box1, CUtensorMapDataType dt) {
    cuuint64_t dims[3] = {d0, d1, d2};
    cuuint64_t strides[2] = {str1B, str2B};
    cuuint32_t box[3] = {box0, box1, 1};
    cuuint32_t es[3] = {1, 1, 1};
    enc(m, dt, 3, ptr, dims, strides, box, es,
        CU_TENSOR_MAP_INTERLEAVE_NONE, CU_TENSOR_MAP_SWIZZLE_128B,
        CU_TENSOR_MAP_L2_PROMOTION_L2_128B, CU_TENSOR_MAP_FLOAT_OOB_FILL_NONE);
}

extern "C" void kernel_launch(void* const* d_in, const int* in_sizes, int n_in,
                              void* d_out, int out_size) {
    (void)in_sizes; (void)n_in; (void)out_size;
    const float* x     = (const float*)d_in[0];
    const float* Wqkv  = (const float*)d_in[1];
    const float* Wmlp  = (const float*)d_in[2];
    const float* bmlp  = (const float*)d_in[3];
    const float* g1    = (const float*)d_in[4];
    const float* beta1 = (const float*)d_in[5];
    const float* Wres  = (const float*)d_in[6];
    const float* g2    = (const float*)d_in[7];
    const float* beta2 = (const float*)d_in[8];
    float* outp = (float*)d_out;

    float *x1, *u, *ctx, *S1, *S2, *stats;
    __half *sm16, *cat2h, *ctx16, *x1t16, *vt16, *wg16, *wmlp16;
    cudaGetSymbolAddress((void**)&x1, g_x1);
    cudaGetSymbolAddress((void**)&sm16, g_sm16);
    cudaGetSymbolAddress((void**)&u, g_u);
    cudaGetSymbolAddress((void**)&cat2h, g_cat2);
    cudaGetSymbolAddress((void**)&ctx, g_ctx);
    cudaGetSymbolAddress((void**)&ctx16, g_ctx16);
    cudaGetSymbolAddress((void**)&x1t16, g_x1t16);
    cudaGetSymbolAddress((void**)&vt16, g_vt16);
    cudaGetSymbolAddress((void**)&wg16, g_Wg16);
    cudaGetSymbolAddress((void**)&wmlp16, g_Wmlp16);
    cudaGetSymbolAddress((void**)&S1, g_S1);
    cudaGetSymbolAddress((void**)&S2, g_S2);
    cudaGetSymbolAddress((void**)&stats, g_stats);
    float* rsum0 = stats;
    float* rsq0  = stats + ROWS;
    float* rsum1 = stats + 2 * ROWS;
    float* rsq1  = stats + 3 * ROWS;

    EncFn enc = nullptr;
    cudaDriverEntryPointQueryResult qr;
    cudaGetDriverEntryPoint("cuTensorMapEncodeTiled", (void**)&enc,
                            cudaEnableDefault, &qr);
    CUtensorMap mU, mWqkv, mSm16, mCtx16, mCat2h, mWmlp16, mWg16, mVt16, mX1t16;
    mk_map(enc, &mU, u, 256, 32768, 1, 1024, (uint64_t)32768 * 1024, 32, 128,
           CU_TENSOR_MAP_DATA_TYPE_FLOAT32);
    mk_map(enc, &mWqkv, (void*)Wqkv, 256, 256, 1, 1024, 256 * 1024, 32, 256,
           CU_TENSOR_MAP_DATA_TYPE_FLOAT32);
    mk_map(enc, &mSm16, sm16, 256, 4096, 8, 512, (uint64_t)4096 * 512, 64, 128,
           CU_TENSOR_MAP_DATA_TYPE_FLOAT16);
    mk_map(enc, &mCtx16, ctx16, 256, 256, 8, 512, 256 * 512, 64, 256,
           CU_TENSOR_MAP_DATA_TYPE_FLOAT16);
    mk_map(enc, &mCat2h, cat2h, 1024, 32768, 1, 2048, (uint64_t)32768 * 2048, 64, 128,
           CU_TENSOR_MAP_DATA_TYPE_FLOAT16);
    mk_map(enc, &mWmlp16, wmlp16, 512, 512, 1, 1024, 512 * 1024, 64, 256,
           CU_TENSOR_MAP_DATA_TYPE_FLOAT16);
    mk_map(enc, &mWg16, wg16, 1024, 256, 1, 2048, 256 * 2048, 64, 256,
           CU_TENSOR_MAP_DATA_TYPE_FLOAT16);
    mk_map(enc, &mVt16, vt16, 4096, 256, 8, 8192, (uint64_t)256 * 8192, 64, 128,
           CU_TENSOR_MAP_DATA_TYPE_FLOAT16);
    mk_map(enc, &mX1t16, x1t16, 4096, 256, 8, 8192, (uint64_t)256 * 8192, 64, 256,
           CU_TENSOR_MAP_DATA_TYPE_FLOAT16);

    cudaFuncSetAttribute(gemm_t5<8, 1, 0>, cudaFuncAttributeMaxDynamicSharedMemorySize, T5_SMEM);
    cudaFuncSetAttribute(gemm_t5<4, 1, 1>, cudaFuncAttributeMaxDynamicSharedMemorySize, T5_SMEM);
    cudaFuncSetAttribute(gemm_t5<5, 1, 1>, cudaFuncAttributeMaxDynamicSharedMemorySize, T5_SMEM);
    cudaFuncSetAttribute(gemm_t5<16, 1, 1>, cudaFuncAttributeMaxDynamicSharedMemorySize, T5_SMEM);
    cudaFuncSetAttribute(gemm_t5<17, 1, 1>, cudaFuncAttributeMaxDynamicSharedMemorySize, T5_SMEM);
    cudaFuncSetAttribute(gemm_t5<32, 8, 1>, cudaFuncAttributeMaxDynamicSharedMemorySize, T5_SMEM);

    __half* vbufh = cat2h + 256;   // v lives in cat2[:,256:512), ld C4, fp16

    dim3 ttb(32, 8);
    transpose_k<<<dim3(Ntok / 32, Cdim / 32, Bsz), ttb>>>(
        x, u, Cdim, Ntok, Ntok, (long long)Cdim * Ntok, (long long)Cdim * Ntok);

    zero_k<<<(4 * ROWS / 4 + 255) / 256, 256>>>(stats, 4 * ROWS / 4);
    prep_k<<<Cdim / 8, 256>>>(Wres, g1, beta1);
    cvt_wmlp_k<<<512 * 512 / 256, 256>>>(Wmlp);

    // qkv fused: x1 f32, softmax->sm16 f16, v->cat2 f16, LN1 stats (buf0)
    gemm_t5<8, 1, 0><<<dim3(1, ROWS / 128, 1), 256, T5_SMEM>>>(
        mU, mWqkv, u, Cdim, 0, Wqkv, Cdim, 0, x1, Cdim, 0, Cdim,
        nullptr, nullptr, 0, nullptr, nullptr, nullptr, nullptr,
        rsum0, rsq0, 0, sm16, vbufh, nullptr, nullptr, nullptr);

    // x1T fp16 (loop-invariant)
    transpose_f2h_k<<<dim3(Cdim / 32, Ntok / 32, Bsz), ttb>>>(
        x1, x1t16, Ntok, Cdim, Cdim, (long long)Ntok * Cdim, (long long)Cdim * Ntok);

    for (int it = 0; it < 2; ++it) {
        float* rs = it == 0 ? rsum0 : rsum1;
        float* rq = it == 0 ? rsq0 : rsq1;

        // vT fp16 from fp16 cat2[:,256:512)
        transpose_h2h_k<<<dim3(Cdim / 32, Ntok / 32, Bsz), ttb>>>(
            vbufh, vt16, Ntok, Cdim, C4, (long long)Ntok * C4, (long long)Cdim * Ntok);

        // g_ctx[d][c] = sum_n vT[d][n] * x1T[c][n]  (f16 tcgen05 NT, split-K 8, atomic f32)
        zero_k<<<(Bsz * Cdim * Cdim / 4 + 255) / 256, 256>>>(ctx, (size_t)Bsz * Cdim * Cdim / 4);
        gemm_t5<32, 8, 1><<<dim3(1, 2, Bsz * 8), 256, T5_SMEM>>>(
            mVt16, mX1t16, nullptr, 0, 0, nullptr, 0, 0,
            ctx, Cdim, (long long)Cdim * Cdim, Ntok,
            nullptr, nullptr, 0, nullptr, nullptr, nullptr, nullptr,
            nullptr, nullptr, 0, nullptr, nullptr, nullptr, nullptr, nullptr);
        cvt_ctx_k<<<Bsz * Cdim * Cdim / 2 / 256, 256>>>(ctx, ctx16);

        // out = sm16 @ ctx16 -> cat2[:,0:256] (f16), + stats (K=256 halves)
        gemm_t5<4, 1, 1><<<dim3(1, Ntok / 128, Bsz), 256, T5_SMEM>>>(
            mSm16, mCtx16, nullptr, 0, 0, nullptr, 0, 0,
            u, Cdim, (long long)Ntok * C4, Cdim,
            nullptr, nullptr, 0, nullptr, nullptr, nullptr, nullptr,
            rs, rq, Ntok, nullptr, cat2h, nullptr, nullptr, nullptr);

        // mlp = relu(cat1 @ Wmlp16^T + b) -> cat2[:,512:1024] (f16), K=512 halves
        gemm_t5<5, 1, 1><<<dim3(2, ROWS / 128, 1), 256, T5_SMEM>>>(
            mCat2h, mWmlp16, nullptr, 0, 0, nullptr, 0, 0, u, Cdim, 0, 512,
            bmlp, nullptr, 0, nullptr, nullptr, nullptr, nullptr,
            rs, rq, 0, nullptr, cat2h + 512, nullptr, nullptr, nullptr);

        // res + LN2 fused (K=1024 halves); rs/rq via mu/rinv slots
        if (it == 0) {
            gemm_t5<16, 1, 1><<<dim3(1, ROWS / 128, 1), 256, T5_SMEM>>>(
                mCat2h, mWg16, nullptr, 0, 0, nullptr, 0, 0, u, Cdim, 0, C4,
                nullptr, x1, Cdim, rs, rq, S1, S2,
                rsum1, rsq1, 0, nullptr, vbufh, g2, beta2, nullptr);
        } else {
            gemm_t5<17, 1, 1><<<dim3(1, ROWS / 128, 1), 256, T5_SMEM>>>(
                mCat2h, mWg16, nullptr, 0, 0, nullptr, 0, 0, u, Cdim, 0, C4,
                nullptr, x1, Cdim, rs, rq, S1, S2,
                nullptr, nullptr, 0, nullptr, nullptr, g2, beta2, outp);
        }
    }
}

// round 16
// speedup vs baseline: 1.4282x; 1.0121x over previous
#include <cuda_runtime.h>
#include <cuda.h>
#include <cuda_fp16.h>
#include <math.h>
#include <stdint.h>

#define Bsz  8
#define Cdim 256
#define Ntok 4096
#define ROWS (Bsz * Ntok)          // 32768 token rows
#define C4   (4 * Cdim)            // 1024

// ---------------- scratch (static device arrays; no allocation) ----------------
__device__ __half g_x1h[(size_t)ROWS * Cdim];       // x1 fp16 (residual + ctx source)
__device__ __half g_sm16[(size_t)ROWS * Cdim];
__device__ float g_u[(size_t)ROWS * Cdim];          // transpose scratch
__device__ __half g_cat2[(size_t)ROWS * C4];        // [out | v | mlp], ld=1024, fp16
__device__ float g_ctx[(size_t)Bsz * Cdim * Cdim];  // fp32 split-K accumulator
__device__ __half g_ctx16[(size_t)Bsz * Cdim * Cdim];
__device__ __half g_x1t16[(size_t)ROWS * Cdim];     // x1T[b][c][n] fp16
__device__ __half g_vt16[(size_t)ROWS * Cdim];      // vT[b][c][n] fp16
__device__ __half g_Wg16[(size_t)Cdim * C4];
__device__ __half g_Wmlp16[(size_t)512 * 512];
__device__ float g_S1[Cdim];
__device__ float g_S2[Cdim];
__device__ float g_stats[4 * ROWS];                 // rsum0|rsq0|rsum1|rsq1

#if defined(__CUDA_ARCH_FEAT_SM103_ALL) || defined(__CUDA_ARCH_FEAT_SM100_ALL)
#define HAS_TCGEN05 1
#else
#define HAS_TCGEN05 0
#endif

// ================= helpers ======================================================
__device__ __forceinline__ uint32_t smem_u32(const void* p) {
    return (uint32_t)__cvta_generic_to_shared(p);
}
__device__ __forceinline__ uint32_t elect1() {
    uint32_t pred;
    asm volatile("{\n\t.reg .pred p;\n\telect.sync _|p, 0xFFFFFFFF;\n\tselp.b32 %0, 1, 0, p;\n\t}"
                 : "=r"(pred));
    return pred;
}
__device__ __forceinline__ void mbar_init(uint32_t a, uint32_t cnt) {
    asm volatile("mbarrier.init.shared.b64 [%0], %1;" :: "r"(a), "r"(cnt) : "memory");
}
__device__ __forceinline__ void mbar_wait(uint32_t a, int ph) {
    asm volatile(
        "{\n\t.reg .pred P;\n\t"
        "WL%=:\n\t"
        "mbarrier.try_wait.parity.acquire.cta.shared::cta.b64 P, [%0], %1, 0x989680;\n\t"
        "@P bra.uni WD%=;\n\t"
        "bra.uni WL%=;\n\t"
        "WD%=:\n\t}"
        :: "r"(a), "r"(ph) : "memory");
}
__device__ __forceinline__ void mbar_expect_tx(uint32_t a, uint32_t bytes) {
    asm volatile("mbarrier.arrive.expect_tx.shared.b64 _, [%0], %1;"
                 :: "r"(a), "r"(bytes) : "memory");
}
__device__ __forceinline__ void tma3d(uint32_t dst, const void* map, int x, int y, int z,
                                      uint32_t mbar) {
    asm volatile(
        "cp.async.bulk.tensor.3d.shared::cta.global.tile.mbarrier::complete_tx::bytes "
        "[%0], [%1, {%2, %3, %4}], [%5];"
        :: "r"(dst), "l"(map), "r"(x), "r"(y), "r"(z), "r"(mbar) : "memory");
}
#define SW128B(o) ((o) ^ (((o) >> 3) & 0x70))

static constexpr unsigned long long DESC_SW128 =
    (2ull << 61) | (1ull << 46) | (64ull << 32) | (1ull << 16);
__device__ __forceinline__ uint64_t mk_desc(uint32_t addr) {
    return DESC_SW128 | ((uint64_t)(addr >> 4) & 0x3FFF);
}

__device__ __forceinline__ uint32_t cvt_tf32(float x) {
    uint32_t r;
    asm("cvt.rna.tf32.f32 %0, %1;" : "=r"(r) : "f"(x));
    return r;
}
__device__ __forceinline__ void cp16(float* s, const float* g) {
    uint32_t sa = smem_u32(s);
    asm volatile("cp.async.cg.shared.global [%0], [%1], 16;" :: "r"(sa), "l"(g));
}
__device__ __forceinline__ void cp_commit() { asm volatile("cp.async.commit_group;" ::); }
template <int N>
__device__ __forceinline__ void cp_wait() { asm volatile("cp.async.wait_group %0;" :: "n"(N)); }

__device__ __forceinline__ void mma8(float* c, const uint32_t* a, const uint32_t* b) {
    asm volatile(
        "mma.sync.aligned.m16n8k8.row.col.f32.tf32.tf32.f32 "
        "{%0,%1,%2,%3}, {%4,%5,%6,%7}, {%8,%9}, {%0,%1,%2,%3};"
        : "+f"(c[0]), "+f"(c[1]), "+f"(c[2]), "+f"(c[3])
        : "r"(a[0]), "r"(a[1]), "r"(a[2]), "r"(a[3]), "r"(b[0]), "r"(b[1]));
}

__device__ __forceinline__ void st_half4(__half* p, float4 v) {
    __half2 lo = __floats2half2_rn(v.x, v.y);
    __half2 hi = __floats2half2_rn(v.z, v.w);
    uint2 o;
    o.x = *(uint32_t*)&lo;
    o.y = *(uint32_t*)&hi;
    *(uint2*)p = o;
}

#define LDTM32(d, addr)                                                          \
    asm volatile(                                                                \
        "tcgen05.ld.sync.aligned.32x32b.x32.b32 "                                \
        "{%0, %1, %2, %3, %4, %5, %6, %7, "                                      \
        " %8, %9, %10, %11, %12, %13, %14, %15, "                                \
        " %16, %17, %18, %19, %20, %21, %22, %23, "                              \
        " %24, %25, %26, %27, %28, %29, %30, %31}, [%32];"                       \
        : "=r"(d[0]), "=r"(d[1]), "=r"(d[2]), "=r"(d[3]),                        \
          "=r"(d[4]), "=r"(d[5]), "=r"(d[6]), "=r"(d[7]),                        \
          "=r"(d[8]), "=r"(d[9]), "=r"(d[10]), "=r"(d[11]),                      \
          "=r"(d[12]), "=r"(d[13]), "=r"(d[14]), "=r"(d[15]),                    \
          "=r"(d[16]), "=r"(d[17]), "=r"(d[18]), "=r"(d[19]),                    \
          "=r"(d[20]), "=r"(d[21]), "=r"(d[22]), "=r"(d[23]),                    \
          "=r"(d[24]), "=r"(d[25]), "=r"(d[26]), "=r"(d[27]),                    \
          "=r"(d[28]), "=r"(d[29]), "=r"(d[30]), "=r"(d[31])                     \
        : "r"(addr));                                                            \
    asm volatile("tcgen05.wait::ld.sync.aligned;" ::: "memory")

// ================= unified NT GEMM, CTA tile 128x256, TMA mainloop =============
// HK=0: fp32 operands (kind::tf32, K-tile 32 floats)
// HK=1: fp16 operands (kind::f16, K-tile 64 halves)
// EPI: 4 half-store+stats | 5 relu+bias half-store+stats |
//      8 qkv fused (x1 f16 + softmax f16 + v half + stats); C is __half* (ld 256) |
//      16 res+LN2 -> half v + next stats | 17 res+LN2 -> transposed f32 outT |
//      32 atomic f32 accumulate (split-K)
// EPI 16/17: `mu` carries rsum, `rinv` carries rsq; `resid` is __half* x1h.
#define STG_BYTES 49152               // A 16K + B 32K
#define T5_SMEM (1024 + 2 * STG_BYTES)
#define TS 65                         // epilogue smem tile stride (floats)

__device__ __forceinline__ void nt_stage(const float* __restrict__ A, int lda,
                                         const float* __restrict__ B, int ldb,
                                         int bm, int bn, int k0,
                                         float* as, float* bs, int tid) {
#pragma unroll
    for (int i = 0; i < 4; i++) {
        int idx = tid + i * 256;
        int row = idx >> 3, c4 = (idx & 7) << 2;
        cp16(as + row * 36 + c4, A + (size_t)(bm + row) * lda + k0 + c4);
        cp16(bs + row * 36 + c4, B + (size_t)(bn + row) * ldb + k0 + c4);
    }
    cp_commit();
}

template <int EPI, int SPLITK, int HK>
__global__ __launch_bounds__(256)
void gemm_t5(const __grid_constant__ CUtensorMap tmA,
             const __grid_constant__ CUtensorMap tmB,
             const float* __restrict__ A, int lda, long long sA,
             const float* __restrict__ B, int ldb, long long sB,
             float* __restrict__ C, int ldc, long long sC, int K,
             const float* __restrict__ bias,
             const __half* __restrict__ resid, int ldr,
             const float* __restrict__ mu, const float* __restrict__ rinv,
             const float* __restrict__ S1, const float* __restrict__ S2,
             float* __restrict__ rsum, float* __restrict__ rsq, long long sStat,
             __half* __restrict__ smx, __half* __restrict__ halfOut,
             const float* __restrict__ g2, const float* __restrict__ b2,
             float* __restrict__ outT) {
    extern __shared__ char smem[];
    const int tid = threadIdx.x, wid = tid >> 5, lane = tid & 31;
    const int bz = blockIdx.z;
    const int batch = bz / SPLITK, ks = bz - batch * SPLITK;
    const int kchunk = K / SPLITK, kxoff = ks * kchunk;
    C += (size_t)batch * sC;
    if (EPI == 4) { halfOut += (size_t)batch * sC; }
    if (EPI == 4 || EPI == 5) { rsum += (size_t)batch * sStat; rsq += (size_t)batch * sStat; }
    const int bm = blockIdx.y * 128, bn = blockIdx.x * 256;
    constexpr int KTILE = HK ? 64 : 32;

#if HAS_TCGEN05
    uint32_t sb = smem_u32(smem);
    if (wid == 0) {
        asm volatile("tcgen05.alloc.cta_group::1.sync.aligned.shared::cta.b32 [%0], %1;"
                     :: "r"(sb), "r"(256) : "memory");
        asm volatile("tcgen05.relinquish_alloc_permit.cta_group::1.sync.aligned;");
    }
    if (tid == 0) {
        mbar_init(sb + 8, 1); mbar_init(sb + 16, 1);
        mbar_init(sb + 24, 1); mbar_init(sb + 32, 1);
    }
    __syncthreads();
    uint32_t tmem;
    asm volatile("ld.shared.b32 %0, [%1];" : "=r"(tmem) : "r"(sb));

    const int KT = kchunk / KTILE;
    const uint32_t IDESC = HK
        ? ((1u << 4) | (32u << 17) | (8u << 24))                          // f16 in, f32 acc
        : ((1u << 4) | (2u << 7) | (2u << 10) | (32u << 17) | (8u << 24)); // tf32

    if (wid == 0 && elect1()) {
#pragma unroll
        for (int s = 0; s < 2; s++) {
            uint32_t full = sb + 8 + s * 8;
            uint32_t dst = sb + 1024 + s * STG_BYTES;
            mbar_expect_tx(full, STG_BYTES);
            tma3d(dst, &tmA, kxoff + s * KTILE, bm, batch, full);
            tma3d(dst + 16384, &tmB, kxoff + s * KTILE, bn, batch, full);
        }
        int fph[2] = {0, 0}, eph[2] = {0, 0};
        for (int kt = 0; kt < KT; kt++) {
            int buf = kt & 1;
            mbar_wait(sb + 8 + buf * 8, fph[buf]); fph[buf] ^= 1;
            uint32_t base = sb + 1024 + buf * STG_BYTES;
            uint64_t ad = mk_desc(base);
            uint64_t bd = mk_desc(base + 16384);
#pragma unroll
            for (int s = 0; s < 4; s++) {
                uint32_t en = (kt > 0 || s > 0) ? 1u : 0u;
                if (HK) {
                    asm volatile(
                        "{\n\t.reg .pred p;\n\tsetp.ne.u32 p, %5, 0;\n\t"
                        "tcgen05.mma.cta_group::1.kind::f16 [%0], %1, %2, %3, {%4,%4,%4,%4}, p;\n\t}"
                        :: "r"(tmem), "l"(ad + s * 2), "l"(bd + s * 2), "r"(IDESC),
                           "r"(0u), "r"(en) : "memory");
                } else {
                    asm volatile(
                        "{\n\t.reg .pred p;\n\tsetp.ne.u32 p, %5, 0;\n\t"
                        "tcgen05.mma.cta_group::1.kind::tf32 [%0], %1, %2, %3, {%4,%4,%4,%4}, p;\n\t}"
                        :: "r"(tmem), "l"(ad + s * 2), "l"(bd + s * 2), "r"(IDESC),
                           "r"(0u), "r"(en) : "memory");
                }
            }
            asm volatile(
                "tcgen05.commit.cta_group::1.mbarrier::arrive::one.shared::cluster.b64 [%0];"
                :: "r"(sb + 24 + buf * 8) : "memory");
            if (kt + 2 < KT) {
                mbar_wait(sb + 24 + buf * 8, eph[buf]); eph[buf] ^= 1;
                uint32_t full = sb + 8 + buf * 8;
                mbar_expect_tx(full, STG_BYTES);
                tma3d(base, &tmA, kxoff + (kt + 2) * KTILE, bm, batch, full);
                tma3d(base + 16384, &tmB, kxoff + (kt + 2) * KTILE, bn, batch, full);
            }
        }
    }
    __syncthreads();
    mbar_wait(sb + 24 + ((KT - 1) & 1) * 8, (KT / 2 - 1) & 1);
    asm volatile("tcgen05.fence::after_thread_sync;" ::: "memory");

    const int rl = (wid & 3) * 32 + lane;     // local row 0..127 (TMEM lane)
    const int row = bm + rl;
    const int half = wid >> 2;
    const int cb = half * 128;
    float* s0 = (float*)(smem + 1024);        // [256] sum partials
    float* s1 = s0 + 256;                     // [256] sumsq partials
    float* s2 = s1 + 256;                     // [256] expsum partials
    float* s3 = s2 + 256;                     // [128] per-row scalar (softmax inv)
    float* tile = s3 + 256;                   // [128][TS] staging tile

    if (EPI == 17) {
        // ---- res+LN2 -> transposed out; stats finalized inline ----
        float mm = mu[row] * (1.f / 1024.f);
        float rv = rsqrtf(rinv[row] * (1.f / 1024.f) - mm * mm + 1e-5f);
        float ps = 0.f, pq = 0.f;
#pragma unroll
        for (int cc = 0; cc < 4; cc++) {
            uint32_t d[32];
            LDTM32(d, tmem + cb + cc * 32);
#pragma unroll
            for (int j = 0; j < 32; j++) {
                int c = cb + cc * 32 + j;
                float val = fmaf(rv, __uint_as_float(d[j]) - mm * S1[c], S2[c]) +
                            2.f * __half2float(resid[(size_t)row * ldr + c]);
                ps += val; pq += val * val;
            }
        }
        s0[half * 128 + rl] = ps;
        s1[half * 128 + rl] = pq;
        __syncthreads();
        float ts = s0[rl] + s0[128 + rl];
        float tq = s1[rl] + s1[128 + rl];
        float mu2 = ts * (1.f / 256.f);
        float r2 = rsqrtf(tq * (1.f / 256.f) - mu2 * mu2 + 1e-5f);
#pragma unroll
        for (int cc = 0; cc < 4; cc++) {
            uint32_t d[32];
            LDTM32(d, tmem + cb + cc * 32);
#pragma unroll
            for (int j = 0; j < 32; j++) {
                int c = cb + cc * 32 + j;
                float val = fmaf(rv, __uint_as_float(d[j]) - mm * S1[c], S2[c]) +
                            2.f * __half2float(resid[(size_t)row * ldr + c]);
                val = (val - mu2) * r2 * g2[c] + b2[c];
                int b = row >> 12, n = row & 4095;
                outT[((size_t)b * Cdim + c) * Ntok + n] = val;
            }
        }
    } else if (EPI == 8 || EPI == 16) {
        // ---- fused two-pass epilogue with smem-staged coalesced stores ----
        float rv = 0.f, mm = 0.f;
        if (EPI == 16) {
            mm = mu[row] * (1.f / 1024.f);
            rv = rsqrtf(rinv[row] * (1.f / 1024.f) - mm * mm + 1e-5f);
        }
        float ps = 0.f, pq = 0.f, pe = 0.f;
#pragma unroll
        for (int cc = 0; cc < 4; cc++) {
            uint32_t d[32];
            LDTM32(d, tmem + cb + cc * 32);
#pragma unroll
            for (int j = 0; j < 32; j++) {
                float val = __uint_as_float(d[j]);
                if (EPI == 16) {
                    int c = cb + cc * 32 + j;
                    val = fmaf(rv, val - mm * S1[c], S2[c]) +
                          2.f * __half2float(resid[(size_t)row * ldr + c]);
                }
                ps += val; pq += val * val;
                if (EPI == 8) pe += __expf(val);
            }
        }
        s0[half * 128 + rl] = ps;
        s1[half * 128 + rl] = pq;
        if (EPI == 8) s2[half * 128 + rl] = pe;
        __syncthreads();
        float ts = s0[rl] + s0[128 + rl];
        float tq = s1[rl] + s1[128 + rl];
        float mu2 = 0.f, r2 = 0.f;
        if (EPI == 8) {
            float inv = 1.f / (s2[rl] + s2[128 + rl]);
            if (half == 0) s3[rl] = inv;
        } else {
            mu2 = ts * (1.f / 256.f);
            r2 = rsqrtf(tq * (1.f / 256.f) - mu2 * mu2 + 1e-5f);
        }
        float vs = 0.f, vq = 0.f;
#pragma unroll
        for (int cc = 0; cc < 4; cc++) {
            uint32_t d[32];
            LDTM32(d, tmem + cb + cc * 32);
#pragma unroll
            for (int j = 0; j < 32; j++) {
                float val = __uint_as_float(d[j]);
                if (EPI == 16) {
                    int c = cb + cc * 32 + j;
                    val = fmaf(rv, val - mm * S1[c], S2[c]) +
                          2.f * __half2float(resid[(size_t)row * ldr + c]);
                    val = (val - mu2) * r2 * g2[c] + b2[c];
                    vs += val; vq += val * val;
                }
                tile[rl * TS + half * 32 + j] = val;
            }
            __syncthreads();
#pragma unroll
            for (int it2 = 0; it2 < 4; it2++) {
                int r = it2 * 32 + (tid >> 3);
                int cq = (tid & 7) * 4;
                size_t gr = (size_t)(bm + r);
#pragma unroll
                for (int h = 0; h < 2; h++) {
                    int c = h * 128 + cc * 32 + cq;
                    float4 v4;
                    v4.x = tile[r * TS + h * 32 + cq + 0];
                    v4.y = tile[r * TS + h * 32 + cq + 1];
                    v4.z = tile[r * TS + h * 32 + cq + 2];
                    v4.w = tile[r * TS + h * 32 + cq + 3];
                    if (EPI == 8) {
                        st_half4((__half*)C + gr * ldc + c, v4);   // x1 fp16
                        st_half4(halfOut + gr * C4 + c, v4);       // v in cat2
                        float iv = s3[r];
                        float4 e = make_float4(__expf(v4.x) * iv, __expf(v4.y) * iv,
                                               __expf(v4.z) * iv, __expf(v4.w) * iv);
                        st_half4(smx + gr * Cdim + c, e);
                    } else {
                        st_half4(halfOut + gr * C4 + c, v4);
                    }
                }
            }
            __syncthreads();
        }
        if (EPI == 16) { atomicAdd(rsum + row, vs); atomicAdd(rsq + row, vq); }
        if (EPI == 8 && half == 0) { atomicAdd(rsum + row, ts); atomicAdd(rsq + row, tq); }
    } else if (EPI == 32) {
        // ---- split-K accumulate: staged + coalesced atomicAdd ----
#pragma unroll
        for (int cc = 0; cc < 4; cc++) {
            uint32_t d[32];
            LDTM32(d, tmem + cb + cc * 32);
#pragma unroll
            for (int j = 0; j < 32; j++)
                tile[rl * TS + half * 32 + j] = __uint_as_float(d[j]);
            __syncthreads();
#pragma unroll
            for (int it2 = 0; it2 < 4; it2++) {
                int r = it2 * 32 + (tid >> 3);
                int cq = (tid & 7) * 4;
                size_t gr = (size_t)(bm + r);
#pragma unroll
                for (int h = 0; h < 2; h++) {
                    int c = bn + h * 128 + cc * 32 + cq;
                    float* dst = C + gr * ldc + c;
                    atomicAdd(dst + 0, tile[r * TS + h * 32 + cq + 0]);
                    atomicAdd(dst + 1, tile[r * TS + h * 32 + cq + 1]);
                    atomicAdd(dst + 2, tile[r * TS + h * 32 + cq + 2]);
                    atomicAdd(dst + 3, tile[r * TS + h * 32 + cq + 3]);
                }
            }
            __syncthreads();
        }
    } else {
        // ---- EPI 4/5: streaming half-store via smem-staged coalesced store ----
        float ssum = 0.f, ssq = 0.f;
#pragma unroll
        for (int cc = 0; cc < 4; cc++) {
            uint32_t d[32];
            LDTM32(d, tmem + cb + cc * 32);
#pragma unroll
            for (int j = 0; j < 32; j++) {
                float val = __uint_as_float(d[j]);
                if (EPI & 1) val = fmaxf(val + bias[bn + cb + cc * 32 + j], 0.f);
                ssum += val; ssq += val * val;
                tile[rl * TS + half * 32 + j] = val;
            }
            __syncthreads();
#pragma unroll
            for (int it2 = 0; it2 < 4; it2++) {
                int r = it2 * 32 + (tid >> 3);
                int cq = (tid & 7) * 4;
                size_t gr = (size_t)(bm + r);
#pragma unroll
                for (int h = 0; h < 2; h++) {
                    int c = bn + h * 128 + cc * 32 + cq;
                    float4 v4;
                    v4.x = tile[r * TS + h * 32 + cq + 0];
                    v4.y = tile[r * TS + h * 32 + cq + 1];
                    v4.z = tile[r * TS + h * 32 + cq + 2];
                    v4.w = tile[r * TS + h * 32 + cq + 3];
                    st_half4(halfOut + gr * C4 + c, v4);
                }
            }
            __syncthreads();
        }
        atomicAdd(rsum + row, ssum);
        atomicAdd(rsq + row, ssq);
    }
    __syncthreads();
    if (wid == 0) {
        asm volatile("tcgen05.dealloc.cta_group::1.sync.aligned.b32 %0, %1;"
                     :: "r"(tmem), "r"(256));
    }
#else
    // -------- legacy fallback (compile-only on non-'a' targets) --------
    float* fsm = (float*)smem;
    constexpr int ABUF = 128 * 36;
    float* As = fsm;
    float* Bs = fsm + 2 * ABUF;
    const int wm = (wid >> 2) * 64, wn = (wid & 3) * 32;
    const int lq = lane >> 2, lr = lane & 3;
    const float* Ab = A + (size_t)batch * sA;
    const float* Bb = B + (size_t)batch * sB;
    for (int hf = 0; hf < 2; hf++) {
        int bnh = bn + hf * 128;
        float acc[4][4][4];
#pragma unroll
        for (int i = 0; i < 4; i++)
#pragma unroll
            for (int j = 0; j < 4; j++)
#pragma unroll
                for (int t = 0; t < 4; t++) acc[i][j][t] = 0.f;
        const int KT2 = kchunk / 32;
        nt_stage(Ab, lda, Bb, ldb, bm, bnh, kxoff, As, Bs, tid);
        for (int kt = 0; kt < KT2; kt++) {
            int buf = kt & 1;
            if (kt + 1 < KT2) {
                nt_stage(Ab, lda, Bb, ldb, bm, bnh, kxoff + (kt + 1) * 32,
                         As + ((kt + 1) & 1) * ABUF, Bs + ((kt + 1) & 1) * ABUF, tid);
                cp_wait<1>();
            } else cp_wait<0>();
            __syncthreads();
            const float* as = As + buf * ABUF;
            const float* bs = Bs + buf * ABUF;
#pragma unroll
            for (int kk = 0; kk < 4; kk++) {
                const int k0 = kk * 8;
                uint32_t af[4][4], bf[4][2];
#pragma unroll
                for (int i = 0; i < 4; i++) {
                    const float* p = as + (wm + i * 16 + lq) * 36 + k0 + lr;
                    af[i][0] = cvt_tf32(p[0]);
                    af[i][2] = cvt_tf32(p[4]);
                    const float* p8 = p + 8 * 36;
                    af[i][1] = cvt_tf32(p8[0]);
                    af[i][3] = cvt_tf32(p8[4]);
                }
#pragma unroll
                for (int j = 0; j < 4; j++) {
                    const float* p = bs + (wn + j * 8 + lq) * 36 + k0 + lr;
                    bf[j][0] = cvt_tf32(p[0]);
                    bf[j][1] = cvt_tf32(p[4]);
                }
#pragma unroll
                for (int i = 0; i < 4; i++)
#pragma unroll
                    for (int j = 0; j < 4; j++) mma8(acc[i][j], af[i], bf[j]);
            }
            __syncthreads();
        }
#pragma unroll
        for (int i = 0; i < 4; i++)
#pragma unroll
            for (int j = 0; j < 4; j++) {
                int c = bnh + wn + j * 8 + lr * 2;
#pragma unroll
                for (int rr = 0; rr < 2; rr++) {
                    int r2 = bm + wm + i * 16 + lq + rr * 8;
                    float v0 = acc[i][j][rr * 2 + 0], v1 = acc[i][j][rr * 2 + 1];
                    if (EPI & 1) {
                        v0 = fmaxf(v0 + bias[c], 0.f);
                        v1 = fmaxf(v1 + bias[c + 1], 0.f);
                    }
                    if (EPI == 32) {
                        atomicAdd(C + (size_t)r2 * ldc + c, v0);
                        atomicAdd(C + (size_t)r2 * ldc + c + 1, v1);
                    } else if (EPI == 4 || EPI == 5) {
                        halfOut[(size_t)r2 * C4 + c] = __float2half(v0);
                        halfOut[(size_t)r2 * C4 + c + 1] = __float2half(v1);
                    } else {
                        *(float2*)(C + (size_t)r2 * ldc + c) = make_float2(v0, v1);
                    }
                }
            }
        __syncthreads();
    }
#endif
}

// ================= elementwise kernels =========================================
__global__ void transpose_k(const float* __restrict__ in, float* __restrict__ out,
                            int R, int Cc, int ldin, long long sIn, long long sOut) {
    __shared__ float tile[32][33];
    in += (size_t)blockIdx.z * sIn;
    out += (size_t)blockIdx.z * sOut;
    int c0 = blockIdx.x * 32, r0 = blockIdx.y * 32;
    int tx = threadIdx.x, ty = threadIdx.y;
#pragma unroll
    for (int j = 0; j < 32; j += 8)
        tile[ty + j][tx] = in[(size_t)(r0 + ty + j) * ldin + c0 + tx];
    __syncthreads();
#pragma unroll
    for (int j = 0; j < 32; j += 8)
        out[(size_t)(c0 + ty + j) * R + r0 + tx] = tile[tx][ty + j];
}

// half in -> half out transpose
__global__ void transpose_h2h_k(const __half* __restrict__ in, __half* __restrict__ out,
                                int R, int Cc, int ldin, long long sIn, long long sOut) {
    __shared__ __half tile[32][34];
    in += (size_t)blockIdx.z * sIn;
    out += (size_t)blockIdx.z * sOut;
    int c0 = blockIdx.x * 32, r0 = blockIdx.y * 32;
    int tx = threadIdx.x, ty = threadIdx.y;
#pragma unroll
    for (int j = 0; j < 32; j += 8)
        tile[ty + j][tx] = in[(size_t)(r0 + ty + j) * ldin + c0 + tx];
    __syncthreads();
#pragma unroll
    for (int j = 0; j < 32; j += 8)
        out[(size_t)(c0 + ty + j) * R + r0 + tx] = tile[tx][ty + j];
}

__global__ void zero_k(float* __restrict__ p, size_t n4) {
    size_t i = (size_t)blockIdx.x * blockDim.x + threadIdx.x;
    if (i < n4) ((float4*)p)[i] = make_float4(0.f, 0.f, 0.f, 0.f);
}

__global__ void cvt_ctx_k(const float* __restrict__ in, __half* __restrict__ out) {
    int i = blockIdx.x * 256 + threadIdx.x;
    float2 v = ((const float2*)in)[i];
    __half2 h = __floats2half2_rn(v.x, v.y);
    ((__half2*)out)[i] = h;
}

__global__ void prep_k(const float* __restrict__ Wres, const float* __restrict__ g1,
                       const float* __restrict__ beta1) {
    int c = blockIdx.x * 8 + (threadIdx.x >> 5);
    int lane = threadIdx.x & 31;
    const float* wr = Wres + (size_t)c * C4;
    float s1 = 0.f, s2 = 0.f;
    for (int k = lane; k < C4; k += 32) {
        float w = wr[k], g = g1[k];
        __half hw = __float2half(g * w);
        g_Wg16[(size_t)c * C4 + k] = hw;
        s1 += __half2float(hw);       // match fp16-rounded GEMM weight exactly
        s2 += beta1[k] * w;
    }
#pragma unroll
    for (int o = 16; o; o >>= 1) {
        s1 += __shfl_xor_sync(0xffffffffu, s1, o);
        s2 += __shfl_xor_sync(0xffffffffu, s2, o);
    }
    if (lane == 0) { g_S1[c] = s1; g_S2[c] = s2; }
}

__global__ void cvt_wmlp_k(const float* __restrict__ w) {
    int i = blockIdx.x * 256 + threadIdx.x;
    g_Wmlp16[i] = __float2half(w[i]);
}

// ================= host launcher ================================================
typedef CUresult (*EncFn)(CUtensorMap*, CUtensorMapDataType, cuuint32_t, void*,
                          const cuuint64_t*, const cuuint64_t*, const cuuint32_t*,
                          const cuuint32_t*, CUtensorMapInterleave, CUtensorMapSwizzle,
                          CUtensorMapL2promotion, CUtensorMapFloatOOBfill);

static void mk_map(EncFn enc, CUtensorMap* m, void* ptr,
                   uint64_t d0, uint64_t d1, uint64_t d2,
                   uint64_t str1B, uint64_t str2B,
                   uint32_t box0, uint32_t box1, CUtensorMapDataType dt) {
    cuuint64_t dims[3] = {d0, d1, d2};
    cuuint64_t strides[2] = {str1B, str2B};
    cuuint32_t box[3] = {box0, box1, 1};
    cuuint32_t es[3] = {1, 1, 1};
    enc(m, dt, 3, ptr, dims, strides, box, es,
        CU_TENSOR_MAP_INTERLEAVE_NONE, CU_TENSOR_MAP_SWIZZLE_128B,
        CU_TENSOR_MAP_L2_PROMOTION_L2_128B, CU_TENSOR_MAP_FLOAT_OOB_FILL_NONE);
}

extern "C" void kernel_launch(void* const* d_in, const int* in_sizes, int n_in,
                              void* d_out, int out_size) {
    (void)in_sizes; (void)n_in; (void)out_size;
    const float* x     = (const float*)d_in[0];
    const float* Wqkv  = (const float*)d_in[1];
    const float* Wmlp  = (const float*)d_in[2];
    const float* bmlp  = (const float*)d_in[3];
    const float* g1    = (const float*)d_in[4];
    const float* beta1 = (const float*)d_in[5];
    const float* Wres  = (const float*)d_in[6];
    const float* g2    = (const float*)d_in[7];
    const float* beta2 = (const float*)d_in[8];
    float* outp = (float*)d_out;

    float *u, *ctx, *S1, *S2, *stats;
    __half *x1h, *sm16, *cat2h, *ctx16, *x1t16, *vt16, *wg16, *wmlp16;
    cudaGetSymbolAddress((void**)&x1h, g_x1h);
    cudaGetSymbolAddress((void**)&sm16, g_sm16);
    cudaGetSymbolAddress((void**)&u, g_u);
    cudaGetSymbolAddress((void**)&cat2h, g_cat2);
    cudaGetSymbolAddress((void**)&ctx, g_ctx);
    cudaGetSymbolAddress((void**)&ctx16, g_ctx16);
    cudaGetSymbolAddress((void**)&x1t16, g_x1t16);
    cudaGetSymbolAddress((void**)&vt16, g_vt16);
    cudaGetSymbolAddress((void**)&wg16, g_Wg16);
    cudaGetSymbolAddress((void**)&wmlp16, g_Wmlp16);
    cudaGetSymbolAddress((void**)&S1, g_S1);
    cudaGetSymbolAddress((void**)&S2, g_S2);
    cudaGetSymbolAddress((void**)&stats, g_stats);
    float* rsum0 = stats;
    float* rsq0  = stats + ROWS;
    float* rsum1 = stats + 2 * ROWS;
    float* rsq1  = stats + 3 * ROWS;

    EncFn enc = nullptr;
    cudaDriverEntryPointQueryResult qr;
    cudaGetDriverEntryPoint("cuTensorMapEncodeTiled", (void**)&enc,
                            cudaEnableDefault, &qr);
    CUtensorMap mU, mWqkv, mSm16, mCtx16, mCat2h, mWmlp16, mWg16, mVt16, mX1t16;
    mk_map(enc, &mU, u, 256, 32768, 1, 1024, (uint64_t)32768 * 1024, 32, 128,
           CU_TENSOR_MAP_DATA_TYPE_FLOAT32);
    mk_map(enc, &mWqkv, (void*)Wqkv, 256, 256, 1, 1024, 256 * 1024, 32, 256,
           CU_TENSOR_MAP_DATA_TYPE_FLOAT32);
    mk_map(enc, &mSm16, sm16, 256, 4096, 8, 512, (uint64_t)4096 * 512, 64, 128,
           CU_TENSOR_MAP_DATA_TYPE_FLOAT16);
    mk_map(enc, &mCtx16, ctx16, 256, 256, 8, 512, 256 * 512, 64, 256,
           CU_TENSOR_MAP_DATA_TYPE_FLOAT16);
    mk_map(enc, &mCat2h, cat2h, 1024, 32768, 1, 2048, (uint64_t)32768 * 2048, 64, 128,
           CU_TENSOR_MAP_DATA_TYPE_FLOAT16);
    mk_map(enc, &mWmlp16, wmlp16, 512, 512, 1, 1024, 512 * 1024, 64, 256,
           CU_TENSOR_MAP_DATA_TYPE_FLOAT16);
    mk_map(enc, &mWg16, wg16, 1024, 256, 1, 2048, 256 * 2048, 64, 256,
           CU_TENSOR_MAP_DATA_TYPE_FLOAT16);
    mk_map(enc, &mVt16, vt16, 4096, 256, 8, 8192, (uint64_t)256 * 8192, 64, 128,
           CU_TENSOR_MAP_DATA_TYPE_FLOAT16);
    mk_map(enc, &mX1t16, x1t16, 4096, 256, 8, 8192, (uint64_t)256 * 8192, 64, 256,
           CU_TENSOR_MAP_DATA_TYPE_FLOAT16);

    cudaFuncSetAttribute(gemm_t5<8, 1, 0>, cudaFuncAttributeMaxDynamicSharedMemorySize, T5_SMEM);
    cudaFuncSetAttribute(gemm_t5<4, 1, 1>, cudaFuncAttributeMaxDynamicSharedMemorySize, T5_SMEM);
    cudaFuncSetAttribute(gemm_t5<5, 1, 1>, cudaFuncAttributeMaxDynamicSharedMemorySize, T5_SMEM);
    cudaFuncSetAttribute(gemm_t5<16, 1, 1>, cudaFuncAttributeMaxDynamicSharedMemorySize, T5_SMEM);
    cudaFuncSetAttribute(gemm_t5<17, 1, 1>, cudaFuncAttributeMaxDynamicSharedMemorySize, T5_SMEM);
    cudaFuncSetAttribute(gemm_t5<32, 8, 1>, cudaFuncAttributeMaxDynamicSharedMemorySize, T5_SMEM);

    __half* vbufh = cat2h + 256;   // v lives in cat2[:,256:512), ld C4, fp16

    dim3 ttb(32, 8);
    transpose_k<<<dim3(Ntok / 32, Cdim / 32, Bsz), ttb>>>(
        x, u, Cdim, Ntok, Ntok, (long long)Cdim * Ntok, (long long)Cdim * Ntok);

    zero_k<<<(4 * ROWS / 4 + 255) / 256, 256>>>(stats, 4 * ROWS / 4);
    prep_k<<<Cdim / 8, 256>>>(Wres, g1, beta1);
    cvt_wmlp_k<<<512 * 512 / 256, 256>>>(Wmlp);

    // qkv fused: x1 f16, softmax->sm16 f16, v->cat2 f16, LN1 stats (buf0)
    gemm_t5<8, 1, 0><<<dim3(1, ROWS / 128, 1), 256, T5_SMEM>>>(
        mU, mWqkv, u, Cdim, 0, Wqkv, Cdim, 0, (float*)x1h, Cdim, 0, Cdim,
        nullptr, nullptr, 0, nullptr, nullptr, nullptr, nullptr,
        rsum0, rsq0, 0, sm16, vbufh, nullptr, nullptr, nullptr);

    // x1T fp16 (loop-invariant)
    transpose_h2h_k<<<dim3(Cdim / 32, Ntok / 32, Bsz), ttb>>>(
        x1h, x1t16, Ntok, Cdim, Cdim, (long long)Ntok * Cdim, (long long)Cdim * Ntok);

    for (int it = 0; it < 2; ++it) {
        float* rs = it == 0 ? rsum0 : rsum1;
        float* rq = it == 0 ? rsq0 : rsq1;

        // vT fp16 from fp16 cat2[:,256:512)
        transpose_h2h_k<<<dim3(Cdim / 32, Ntok / 32, Bsz), ttb>>>(
            vbufh, vt16, Ntok, Cdim, C4, (long long)Ntok * C4, (long long)Cdim * Ntok);

        // g_ctx[d][c] = sum_n vT[d][n] * x1T[c][n]  (f16 tcgen05 NT, split-K 8, atomic f32)
        zero_k<<<(Bsz * Cdim * Cdim / 4 + 255) / 256, 256>>>(ctx, (size_t)Bsz * Cdim * Cdim / 4);
        gemm_t5<32, 8, 1><<<dim3(1, 2, Bsz * 8), 256, T5_SMEM>>>(
            mVt16, mX1t16, nullptr, 0, 0, nullptr, 0, 0,
            ctx, Cdim, (long long)Cdim * Cdim, Ntok,
            nullptr, nullptr, 0, nullptr, nullptr, nullptr, nullptr,
            nullptr, nullptr, 0, nullptr, nullptr, nullptr, nullptr, nullptr);
        cvt_ctx_k<<<Bsz * Cdim * Cdim / 2 / 256, 256>>>(ctx, ctx16);

        // out = sm16 @ ctx16 -> cat2[:,0:256] (f16), + stats (K=256 halves)
        gemm_t5<4, 1, 1><<<dim3(1, Ntok / 128, Bsz), 256, T5_SMEM>>>(
            mSm16, mCtx16, nullptr, 0, 0, nullptr, 0, 0,
            u, Cdim, (long long)Ntok * C4, Cdim,
            nullptr, nullptr, 0, nullptr, nullptr, nullptr, nullptr,
            rs, rq, Ntok, nullptr, cat2h, nullptr, nullptr, nullptr);

        // mlp = relu(cat1 @ Wmlp16^T + b) -> cat2[:,512:1024] (f16), K=512 halves
        gemm_t5<5, 1, 1><<<dim3(2, ROWS / 128, 1), 256, T5_SMEM>>>(
            mCat2h, mWmlp16, nullptr, 0, 0, nullptr, 0, 0, u, Cdim, 0, 512,
            bmlp, nullptr, 0, nullptr, nullptr, nullptr, nullptr,
            rs, rq, 0, nullptr, cat2h + 512, nullptr, nullptr, nullptr);

        // res + LN2 fused (K=1024 halves); rs/rq via mu/rinv slots, resid = x1h f16
        if (it == 0) {
            gemm_t5<16, 1, 1><<<dim3(1, ROWS / 128, 1), 256, T5_SMEM>>>(
                mCat2h, mWg16, nullptr, 0, 0, nullptr, 0, 0, u, Cdim, 0, C4,
                nullptr, x1h, Cdim, rs, rq, S1, S2,
                rsum1, rsq1, 0, nullptr, vbufh, g2, beta2, nullptr);
        } else {
            gemm_t5<17, 1, 1><<<dim3(1, ROWS / 128, 1), 256, T5_SMEM>>>(
                mCat2h, mWg16, nullptr, 0, 0, nullptr, 0, 0, u, Cdim, 0, C4,
                nullptr, x1h, Cdim, rs, rq, S1, S2,
                nullptr, nullptr, 0, nullptr, nullptr, g2, beta2, outp);
        }
    }
}

// round 17
// speedup vs baseline: 1.4725x; 1.0311x over previous
#include <cuda_runtime.h>
#include <cuda.h>
#include <cuda_fp16.h>
#include <math.h>
#include <stdint.h>

#define Bsz  8
#define Cdim 256
#define Ntok 4096
#define ROWS (Bsz * Ntok)          // 32768 token rows
#define C4   (4 * Cdim)            // 1024

// ---------------- scratch (static device arrays; no allocation) ----------------
__device__ __half g_x1h[(size_t)ROWS * Cdim];       // x1 fp16 (residual)
__device__ __half g_sm16[(size_t)ROWS * Cdim];
__device__ float g_u[(size_t)ROWS * Cdim];          // transpose scratch
__device__ __half g_cat2[(size_t)ROWS * C4];        // [out | v | mlp], ld=1024, fp16
__device__ float g_ctx[(size_t)Bsz * Cdim * Cdim];  // fp32 split-K accumulator
__device__ __half g_ctx16[(size_t)Bsz * Cdim * Cdim];
__device__ __half g_x1t16[(size_t)ROWS * Cdim];     // x1T[b][c][n] fp16
__device__ __half g_vt16[(size_t)ROWS * Cdim];      // vT[b][c][n] fp16
__device__ __half g_Wg16[(size_t)Cdim * C4];
__device__ __half g_Wmlp16[(size_t)512 * 512];
__device__ float g_S1[Cdim];
__device__ float g_S2[Cdim];
__device__ float g_stats[4 * ROWS];                 // rsum0|rsq0|rsum1|rsq1

#if defined(__CUDA_ARCH_FEAT_SM103_ALL) || defined(__CUDA_ARCH_FEAT_SM100_ALL)
#define HAS_TCGEN05 1
#else
#define HAS_TCGEN05 0
#endif

// ================= helpers ======================================================
__device__ __forceinline__ uint32_t smem_u32(const void* p) {
    return (uint32_t)__cvta_generic_to_shared(p);
}
__device__ __forceinline__ uint32_t elect1() {
    uint32_t pred;
    asm volatile("{\n\t.reg .pred p;\n\telect.sync _|p, 0xFFFFFFFF;\n\tselp.b32 %0, 1, 0, p;\n\t}"
                 : "=r"(pred));
    return pred;
}
__device__ __forceinline__ void mbar_init(uint32_t a, uint32_t cnt) {
    asm volatile("mbarrier.init.shared.b64 [%0], %1;" :: "r"(a), "r"(cnt) : "memory");
}
__device__ __forceinline__ void mbar_wait(uint32_t a, int ph) {
    asm volatile(
        "{\n\t.reg .pred P;\n\t"
        "WL%=:\n\t"
        "mbarrier.try_wait.parity.acquire.cta.shared::cta.b64 P, [%0], %1, 0x989680;\n\t"
        "@P bra.uni WD%=;\n\t"
        "bra.uni WL%=;\n\t"
        "WD%=:\n\t}"
        :: "r"(a), "r"(ph) : "memory");
}
__device__ __forceinline__ void mbar_expect_tx(uint32_t a, uint32_t bytes) {
    asm volatile("mbarrier.arrive.expect_tx.shared.b64 _, [%0], %1;"
                 :: "r"(a), "r"(bytes) : "memory");
}
__device__ __forceinline__ void tma3d(uint32_t dst, const void* map, int x, int y, int z,
                                      uint32_t mbar) {
    asm volatile(
        "cp.async.bulk.tensor.3d.shared::cta.global.tile.mbarrier::complete_tx::bytes "
        "[%0], [%1, {%2, %3, %4}], [%5];"
        :: "r"(dst), "l"(map), "r"(x), "r"(y), "r"(z), "r"(mbar) : "memory");
}
#define SW128B(o) ((o) ^ (((o) >> 3) & 0x70))

static constexpr unsigned long long DESC_SW128 =
    (2ull << 61) | (1ull << 46) | (64ull << 32) | (1ull << 16);
__device__ __forceinline__ uint64_t mk_desc(uint32_t addr) {
    return DESC_SW128 | ((uint64_t)(addr >> 4) & 0x3FFF);
}

__device__ __forceinline__ uint32_t cvt_tf32(float x) {
    uint32_t r;
    asm("cvt.rna.tf32.f32 %0, %1;" : "=r"(r) : "f"(x));
    return r;
}
__device__ __forceinline__ void cp16(float* s, const float* g) {
    uint32_t sa = smem_u32(s);
    asm volatile("cp.async.cg.shared.global [%0], [%1], 16;" :: "r"(sa), "l"(g));
}
__device__ __forceinline__ void cp_commit() { asm volatile("cp.async.commit_group;" ::); }
template <int N>
__device__ __forceinline__ void cp_wait() { asm volatile("cp.async.wait_group %0;" :: "n"(N)); }

__device__ __forceinline__ void mma8(float* c, const uint32_t* a, const uint32_t* b) {
    asm volatile(
        "mma.sync.aligned.m16n8k8.row.col.f32.tf32.tf32.f32 "
        "{%0,%1,%2,%3}, {%4,%5,%6,%7}, {%8,%9}, {%0,%1,%2,%3};"
        : "+f"(c[0]), "+f"(c[1]), "+f"(c[2]), "+f"(c[3])
        : "r"(a[0]), "r"(a[1]), "r"(a[2]), "r"(a[3]), "r"(b[0]), "r"(b[1]));
}

__device__ __forceinline__ void st_half4(__half* p, float4 v) {
    __half2 lo = __floats2half2_rn(v.x, v.y);
    __half2 hi = __floats2half2_rn(v.z, v.w);
    uint2 o;
    o.x = *(uint32_t*)&lo;
    o.y = *(uint32_t*)&hi;
    *(uint2*)p = o;
}

#define LDTM32(d, addr)                                                          \
    asm volatile(                                                                \
        "tcgen05.ld.sync.aligned.32x32b.x32.b32 "                                \
        "{%0, %1, %2, %3, %4, %5, %6, %7, "                                      \
        " %8, %9, %10, %11, %12, %13, %14, %15, "                                \
        " %16, %17, %18, %19, %20, %21, %22, %23, "                              \
        " %24, %25, %26, %27, %28, %29, %30, %31}, [%32];"                       \
        : "=r"(d[0]), "=r"(d[1]), "=r"(d[2]), "=r"(d[3]),                        \
          "=r"(d[4]), "=r"(d[5]), "=r"(d[6]), "=r"(d[7]),                        \
          "=r"(d[8]), "=r"(d[9]), "=r"(d[10]), "=r"(d[11]),                      \
          "=r"(d[12]), "=r"(d[13]), "=r"(d[14]), "=r"(d[15]),                    \
          "=r"(d[16]), "=r"(d[17]), "=r"(d[18]), "=r"(d[19]),                    \
          "=r"(d[20]), "=r"(d[21]), "=r"(d[22]), "=r"(d[23]),                    \
          "=r"(d[24]), "=r"(d[25]), "=r"(d[26]), "=r"(d[27]),                    \
          "=r"(d[28]), "=r"(d[29]), "=r"(d[30]), "=r"(d[31])                     \
        : "r"(addr));                                                            \
    asm volatile("tcgen05.wait::ld.sync.aligned;" ::: "memory")

// ================= unified NT GEMM, CTA tile 128x256, TMA mainloop =============
// HK=0: fp32 operands (kind::tf32, K-tile 32 floats)
// HK=1: fp16 operands (kind::f16, K-tile 64 halves)
// EPI: 4 half-store+stats | 5 relu+bias half-store+stats |
//      8 qkv fused (x1 f16 + softmax f16 + v half + x1T/vT drains + stats) |
//      16 res+LN2 -> half v + vT drain + next stats | 17 res+LN2 -> transposed outT |
//      32 atomic f32 accumulate (split-K)
// EPI 16/17: `mu` carries rsum, `rinv` carries rsq; `resid` is __half* x1h.
#define STG_BYTES 49152               // A 16K + B 32K
#define T5_SMEM (1024 + 2 * STG_BYTES)
#define TS 65                         // epilogue smem tile stride (floats)

__device__ __forceinline__ void nt_stage(const float* __restrict__ A, int lda,
                                         const float* __restrict__ B, int ldb,
                                         int bm, int bn, int k0,
                                         float* as, float* bs, int tid) {
#pragma unroll
    for (int i = 0; i < 4; i++) {
        int idx = tid + i * 256;
        int row = idx >> 3, c4 = (idx & 7) << 2;
        cp16(as + row * 36 + c4, A + (size_t)(bm + row) * lda + k0 + c4);
        cp16(bs + row * 36 + c4, B + (size_t)(bn + row) * ldb + k0 + c4);
    }
    cp_commit();
}

template <int EPI, int SPLITK, int HK>
__global__ __launch_bounds__(256)
void gemm_t5(const __grid_constant__ CUtensorMap tmA,
             const __grid_constant__ CUtensorMap tmB,
             const float* __restrict__ A, int lda, long long sA,
             const float* __restrict__ B, int ldb, long long sB,
             float* __restrict__ C, int ldc, long long sC, int K,
             const float* __restrict__ bias,
             const __half* __restrict__ resid, int ldr,
             const float* __restrict__ mu, const float* __restrict__ rinv,
             const float* __restrict__ S1, const float* __restrict__ S2,
             float* __restrict__ rsum, float* __restrict__ rsq, long long sStat,
             __half* __restrict__ smx, __half* __restrict__ halfOut,
             const float* __restrict__ g2, const float* __restrict__ b2,
             float* __restrict__ outT,
             __half* __restrict__ xtp, __half* __restrict__ vtp) {
    extern __shared__ char smem[];
    const int tid = threadIdx.x, wid = tid >> 5, lane = tid & 31;
    const int bz = blockIdx.z;
    const int batch = bz / SPLITK, ks = bz - batch * SPLITK;
    const int kchunk = K / SPLITK, kxoff = ks * kchunk;
    C += (size_t)batch * sC;
    if (EPI == 4) { halfOut += (size_t)batch * sC; }
    if (EPI == 4 || EPI == 5) { rsum += (size_t)batch * sStat; rsq += (size_t)batch * sStat; }
    const int bm = blockIdx.y * 128, bn = blockIdx.x * 256;
    constexpr int KTILE = HK ? 64 : 32;

#if HAS_TCGEN05
    uint32_t sb = smem_u32(smem);
    if (wid == 0) {
        asm volatile("tcgen05.alloc.cta_group::1.sync.aligned.shared::cta.b32 [%0], %1;"
                     :: "r"(sb), "r"(256) : "memory");
        asm volatile("tcgen05.relinquish_alloc_permit.cta_group::1.sync.aligned;");
    }
    if (tid == 0) {
        mbar_init(sb + 8, 1); mbar_init(sb + 16, 1);
        mbar_init(sb + 24, 1); mbar_init(sb + 32, 1);
    }
    __syncthreads();
    uint32_t tmem;
    asm volatile("ld.shared.b32 %0, [%1];" : "=r"(tmem) : "r"(sb));

    const int KT = kchunk / KTILE;
    const uint32_t IDESC = HK
        ? ((1u << 4) | (32u << 17) | (8u << 24))                          // f16 in, f32 acc
        : ((1u << 4) | (2u << 7) | (2u << 10) | (32u << 17) | (8u << 24)); // tf32

    if (wid == 0 && elect1()) {
#pragma unroll
        for (int s = 0; s < 2; s++) {
            uint32_t full = sb + 8 + s * 8;
            uint32_t dst = sb + 1024 + s * STG_BYTES;
            mbar_expect_tx(full, STG_BYTES);
            tma3d(dst, &tmA, kxoff + s * KTILE, bm, batch, full);
            tma3d(dst + 16384, &tmB, kxoff + s * KTILE, bn, batch, full);
        }
        int fph[2] = {0, 0}, eph[2] = {0, 0};
        for (int kt = 0; kt < KT; kt++) {
            int buf = kt & 1;
            mbar_wait(sb + 8 + buf * 8, fph[buf]); fph[buf] ^= 1;
            uint32_t base = sb + 1024 + buf * STG_BYTES;
            uint64_t ad = mk_desc(base);
            uint64_t bd = mk_desc(base + 16384);
#pragma unroll
            for (int s = 0; s < 4; s++) {
                uint32_t en = (kt > 0 || s > 0) ? 1u : 0u;
                if (HK) {
                    asm volatile(
                        "{\n\t.reg .pred p;\n\tsetp.ne.u32 p, %5, 0;\n\t"
                        "tcgen05.mma.cta_group::1.kind::f16 [%0], %1, %2, %3, {%4,%4,%4,%4}, p;\n\t}"
                        :: "r"(tmem), "l"(ad + s * 2), "l"(bd + s * 2), "r"(IDESC),
                           "r"(0u), "r"(en) : "memory");
                } else {
                    asm volatile(
                        "{\n\t.reg .pred p;\n\tsetp.ne.u32 p, %5, 0;\n\t"
                        "tcgen05.mma.cta_group::1.kind::tf32 [%0], %1, %2, %3, {%4,%4,%4,%4}, p;\n\t}"
                        :: "r"(tmem), "l"(ad + s * 2), "l"(bd + s * 2), "r"(IDESC),
                           "r"(0u), "r"(en) : "memory");
                }
            }
            asm volatile(
                "tcgen05.commit.cta_group::1.mbarrier::arrive::one.shared::cluster.b64 [%0];"
                :: "r"(sb + 24 + buf * 8) : "memory");
            if (kt + 2 < KT) {
                mbar_wait(sb + 24 + buf * 8, eph[buf]); eph[buf] ^= 1;
                uint32_t full = sb + 8 + buf * 8;
                mbar_expect_tx(full, STG_BYTES);
                tma3d(base, &tmA, kxoff + (kt + 2) * KTILE, bm, batch, full);
                tma3d(base + 16384, &tmB, kxoff + (kt + 2) * KTILE, bn, batch, full);
            }
        }
    }
    __syncthreads();
    mbar_wait(sb + 24 + ((KT - 1) & 1) * 8, (KT / 2 - 1) & 1);
    asm volatile("tcgen05.fence::after_thread_sync;" ::: "memory");

    const int rl = (wid & 3) * 32 + lane;     // local row 0..127 (TMEM lane)
    const int row = bm + rl;
    const int half = wid >> 2;
    const int cb = half * 128;
    const int bb = bm >> 12, n0 = bm & 4095;  // batch / token base for transposed drains
    float* s0 = (float*)(smem + 1024);        // [256] sum partials
    float* s1 = s0 + 256;                     // [256] sumsq partials
    float* s2 = s1 + 256;                     // [256] expsum partials
    float* s3 = s2 + 256;                     // [128] per-row scalar (softmax inv)
    float* tile = s3 + 256;                   // [128][TS] staging tile

    if (EPI == 17) {
        // ---- res+LN2 -> transposed out; stats finalized inline ----
        float mm = mu[row] * (1.f / 1024.f);
        float rv = rsqrtf(rinv[row] * (1.f / 1024.f) - mm * mm + 1e-5f);
        float ps = 0.f, pq = 0.f;
#pragma unroll
        for (int cc = 0; cc < 4; cc++) {
            uint32_t d[32];
            LDTM32(d, tmem + cb + cc * 32);
#pragma unroll
            for (int j = 0; j < 32; j++) {
                int c = cb + cc * 32 + j;
                float val = fmaf(rv, __uint_as_float(d[j]) - mm * S1[c], S2[c]) +
                            2.f * __half2float(resid[(size_t)row * ldr + c]);
                ps += val; pq += val * val;
            }
        }
        s0[half * 128 + rl] = ps;
        s1[half * 128 + rl] = pq;
        __syncthreads();
        float ts = s0[rl] + s0[128 + rl];
        float tq = s1[rl] + s1[128 + rl];
        float mu2 = ts * (1.f / 256.f);
        float r2 = rsqrtf(tq * (1.f / 256.f) - mu2 * mu2 + 1e-5f);
#pragma unroll
        for (int cc = 0; cc < 4; cc++) {
            uint32_t d[32];
            LDTM32(d, tmem + cb + cc * 32);
#pragma unroll
            for (int j = 0; j < 32; j++) {
                int c = cb + cc * 32 + j;
                float val = fmaf(rv, __uint_as_float(d[j]) - mm * S1[c], S2[c]) +
                            2.f * __half2float(resid[(size_t)row * ldr + c]);
                val = (val - mu2) * r2 * g2[c] + b2[c];
                outT[((size_t)bb * Cdim + c) * Ntok + (row & 4095)] = val;
            }
        }
    } else if (EPI == 8 || EPI == 16) {
        // ---- fused two-pass epilogue with smem-staged coalesced + transposed drains ----
        float rv = 0.f, mm = 0.f;
        if (EPI == 16) {
            mm = mu[row] * (1.f / 1024.f);
            rv = rsqrtf(rinv[row] * (1.f / 1024.f) - mm * mm + 1e-5f);
        }
        float ps = 0.f, pq = 0.f, pe = 0.f;
#pragma unroll
        for (int cc = 0; cc < 4; cc++) {
            uint32_t d[32];
            LDTM32(d, tmem + cb + cc * 32);
#pragma unroll
            for (int j = 0; j < 32; j++) {
                float val = __uint_as_float(d[j]);
                if (EPI == 16) {
                    int c = cb + cc * 32 + j;
                    val = fmaf(rv, val - mm * S1[c], S2[c]) +
                          2.f * __half2float(resid[(size_t)row * ldr + c]);
                }
                ps += val; pq += val * val;
                if (EPI == 8) pe += __expf(val);
            }
        }
        s0[half * 128 + rl] = ps;
        s1[half * 128 + rl] = pq;
        if (EPI == 8) s2[half * 128 + rl] = pe;
        __syncthreads();
        float ts = s0[rl] + s0[128 + rl];
        float tq = s1[rl] + s1[128 + rl];
        float mu2 = 0.f, r2 = 0.f;
        if (EPI == 8) {
            float inv = 1.f / (s2[rl] + s2[128 + rl]);
            if (half == 0) s3[rl] = inv;
        } else {
            mu2 = ts * (1.f / 256.f);
            r2 = rsqrtf(tq * (1.f / 256.f) - mu2 * mu2 + 1e-5f);
        }
        float vs = 0.f, vq = 0.f;
#pragma unroll
        for (int cc = 0; cc < 4; cc++) {
            uint32_t d[32];
            LDTM32(d, tmem + cb + cc * 32);
#pragma unroll
            for (int j = 0; j < 32; j++) {
                float val = __uint_as_float(d[j]);
                if (EPI == 16) {
                    int c = cb + cc * 32 + j;
                    val = fmaf(rv, val - mm * S1[c], S2[c]) +
                          2.f * __half2float(resid[(size_t)row * ldr + c]);
                    val = (val - mu2) * r2 * g2[c] + b2[c];
                    vs += val; vq += val * val;
                }
                tile[rl * TS + half * 32 + j] = val;
            }
            __syncthreads();
            // row-major drain (coalesced)
#pragma unroll
            for (int it2 = 0; it2 < 4; it2++) {
                int r = it2 * 32 + (tid >> 3);
                int cq = (tid & 7) * 4;
                size_t gr = (size_t)(bm + r);
#pragma unroll
                for (int h = 0; h < 2; h++) {
                    int c = h * 128 + cc * 32 + cq;
                    float4 v4;
                    v4.x = tile[r * TS + h * 32 + cq + 0];
                    v4.y = tile[r * TS + h * 32 + cq + 1];
                    v4.z = tile[r * TS + h * 32 + cq + 2];
                    v4.w = tile[r * TS + h * 32 + cq + 3];
                    if (EPI == 8) {
                        st_half4((__half*)C + gr * ldc + c, v4);   // x1 fp16
                        st_half4(halfOut + gr * C4 + c, v4);       // v in cat2
                        float iv = s3[r];
                        float4 e = make_float4(__expf(v4.x) * iv, __expf(v4.y) * iv,
                                               __expf(v4.z) * iv, __expf(v4.w) * iv);
                        st_half4(smx + gr * Cdim + c, e);
                    } else {
                        st_half4(halfOut + gr * C4 + c, v4);
                    }
                }
            }
            // transposed drain -> vt16 (and x1t16 for EPI 8), coalesced along n
#pragma unroll
            for (int it3 = 0; it3 < 8; it3++) {
                int tcol = it3 * 8 + wid;                 // 0..63 tile column
                int h = tcol >> 5, j = tcol & 31;
                int cg = h * 128 + cc * 32 + j;           // global column
                float4 tv;
                tv.x = tile[(lane * 4 + 0) * TS + tcol];
                tv.y = tile[(lane * 4 + 1) * TS + tcol];
                tv.z = tile[(lane * 4 + 2) * TS + tcol];
                tv.w = tile[(lane * 4 + 3) * TS + tcol];
                size_t toff = ((size_t)bb * Cdim + cg) * Ntok + n0 + lane * 4;
                st_half4(vtp + toff, tv);
                if (EPI == 8) st_half4(xtp + toff, tv);
            }
            __syncthreads();
        }
        if (EPI == 16) { atomicAdd(rsum + row, vs); atomicAdd(rsq + row, vq); }
        if (EPI == 8 && half == 0) { atomicAdd(rsum + row, ts); atomicAdd(rsq + row, tq); }
    } else if (EPI == 32) {
        // ---- split-K accumulate: staged + coalesced atomicAdd ----
#pragma unroll
        for (int cc = 0; cc < 4; cc++) {
            uint32_t d[32];
            LDTM32(d, tmem + cb + cc * 32);
#pragma unroll
            for (int j = 0; j < 32; j++)
                tile[rl * TS + half * 32 + j] = __uint_as_float(d[j]);
            __syncthreads();
#pragma unroll
            for (int it2 = 0; it2 < 4; it2++) {
                int r = it2 * 32 + (tid >> 3);
                int cq = (tid & 7) * 4;
                size_t gr = (size_t)(bm + r);
#pragma unroll
                for (int h = 0; h < 2; h++) {
                    int c = bn + h * 128 + cc * 32 + cq;
                    float* dst = C + gr * ldc + c;
                    atomicAdd(dst + 0, tile[r * TS + h * 32 + cq + 0]);
                    atomicAdd(dst + 1, tile[r * TS + h * 32 + cq + 1]);
                    atomicAdd(dst + 2, tile[r * TS + h * 32 + cq + 2]);
                    atomicAdd(dst + 3, tile[r * TS + h * 32 + cq + 3]);
                }
            }
            __syncthreads();
        }
    } else {
        // ---- EPI 4/5: streaming half-store via smem-staged coalesced store ----
        float ssum = 0.f, ssq = 0.f;
#pragma unroll
        for (int cc = 0; cc < 4; cc++) {
            uint32_t d[32];
            LDTM32(d, tmem + cb + cc * 32);
#pragma unroll
            for (int j = 0; j < 32; j++) {
                float val = __uint_as_float(d[j]);
                if (EPI & 1) val = fmaxf(val + bias[bn + cb + cc * 32 + j], 0.f);
                ssum += val; ssq += val * val;
                tile[rl * TS + half * 32 + j] = val;
            }
            __syncthreads();
#pragma unroll
            for (int it2 = 0; it2 < 4; it2++) {
                int r = it2 * 32 + (tid >> 3);
                int cq = (tid & 7) * 4;
                size_t gr = (size_t)(bm + r);
#pragma unroll
                for (int h = 0; h < 2; h++) {
                    int c = bn + h * 128 + cc * 32 + cq;
                    float4 v4;
                    v4.x = tile[r * TS + h * 32 + cq + 0];
                    v4.y = tile[r * TS + h * 32 + cq + 1];
                    v4.z = tile[r * TS + h * 32 + cq + 2];
                    v4.w = tile[r * TS + h * 32 + cq + 3];
                    st_half4(halfOut + gr * C4 + c, v4);
                }
            }
            __syncthreads();
        }
        atomicAdd(rsum + row, ssum);
        atomicAdd(rsq + row, ssq);
    }
    __syncthreads();
    if (wid == 0) {
        asm volatile("tcgen05.dealloc.cta_group::1.sync.aligned.b32 %0, %1;"
                     :: "r"(tmem), "r"(256));
    }
#else
    // -------- legacy fallback (compile-only on non-'a' targets) --------
    float* fsm = (float*)smem;
    constexpr int ABUF = 128 * 36;
    float* As = fsm;
    float* Bs = fsm + 2 * ABUF;
    const int wm = (wid >> 2) * 64, wn = (wid & 3) * 32;
    const int lq = lane >> 2, lr = lane & 3;
    const float* Ab = A + (size_t)batch * sA;
    const float* Bb = B + (size_t)batch * sB;
    for (int hf = 0; hf < 2; hf++) {
        int bnh = bn + hf * 128;
        float acc[4][4][4];
#pragma unroll
        for (int i = 0; i < 4; i++)
#pragma unroll
            for (int j = 0; j < 4; j++)
#pragma unroll
                for (int t = 0; t < 4; t++) acc[i][j][t] = 0.f;
        const int KT2 = kchunk / 32;
        nt_stage(Ab, lda, Bb, ldb, bm, bnh, kxoff, As, Bs, tid);
        for (int kt = 0; kt < KT2; kt++) {
            int buf = kt & 1;
            if (kt + 1 < KT2) {
                nt_stage(Ab, lda, Bb, ldb, bm, bnh, kxoff + (kt + 1) * 32,
                         As + ((kt + 1) & 1) * ABUF, Bs + ((kt + 1) & 1) * ABUF, tid);
                cp_wait<1>();
            } else cp_wait<0>();
            __syncthreads();
            const float* as = As + buf * ABUF;
            const float* bs = Bs + buf * ABUF;
#pragma unroll
            for (int kk = 0; kk < 4; kk++) {
                const int k0 = kk * 8;
                uint32_t af[4][4], bf[4][2];
#pragma unroll
                for (int i = 0; i < 4; i++) {
                    const float* p = as + (wm + i * 16 + lq) * 36 + k0 + lr;
                    af[i][0] = cvt_tf32(p[0]);
                    af[i][2] = cvt_tf32(p[4]);
                    const float* p8 = p + 8 * 36;
                    af[i][1] = cvt_tf32(p8[0]);
                    af[i][3] = cvt_tf32(p8[4]);
                }
#pragma unroll
                for (int j = 0; j < 4; j++) {
                    const float* p = bs + (wn + j * 8 + lq) * 36 + k0 + lr;
                    bf[j][0] = cvt_tf32(p[0]);
                    bf[j][1] = cvt_tf32(p[4]);
                }
#pragma unroll
                for (int i = 0; i < 4; i++)
#pragma unroll
                    for (int j = 0; j < 4; j++) mma8(acc[i][j], af[i], bf[j]);
            }
            __syncthreads();
        }
#pragma unroll
        for (int i = 0; i < 4; i++)
#pragma unroll
            for (int j = 0; j < 4; j++) {
                int c = bnh + wn + j * 8 + lr * 2;
#pragma unroll
                for (int rr = 0; rr < 2; rr++) {
                    int r2 = bm + wm + i * 16 + lq + rr * 8;
                    float v0 = acc[i][j][rr * 2 + 0], v1 = acc[i][j][rr * 2 + 1];
                    if (EPI & 1) {
                        v0 = fmaxf(v0 + bias[c], 0.f);
                        v1 = fmaxf(v1 + bias[c + 1], 0.f);
                    }
                    if (EPI == 32) {
                        atomicAdd(C + (size_t)r2 * ldc + c, v0);
                        atomicAdd(C + (size_t)r2 * ldc + c + 1, v1);
                    } else if (EPI == 4 || EPI == 5) {
                        halfOut[(size_t)r2 * C4 + c] = __float2half(v0);
                        halfOut[(size_t)r2 * C4 + c + 1] = __float2half(v1);
                    } else {
                        *(float2*)(C + (size_t)r2 * ldc + c) = make_float2(v0, v1);
                    }
                }
            }
        __syncthreads();
    }
#endif
}

// ================= elementwise kernels =========================================
__global__ void transpose_k(const float* __restrict__ in, float* __restrict__ out,
                            int R, int Cc, int ldin, long long sIn, long long sOut) {
    __shared__ float tile[32][33];
    in += (size_t)blockIdx.z * sIn;
    out += (size_t)blockIdx.z * sOut;
    int c0 = blockIdx.x * 32, r0 = blockIdx.y * 32;
    int tx = threadIdx.x, ty = threadIdx.y;
#pragma unroll
    for (int j = 0; j < 32; j += 8)
        tile[ty + j][tx] = in[(size_t)(r0 + ty + j) * ldin + c0 + tx];
    __syncthreads();
#pragma unroll
    for (int j = 0; j < 32; j += 8)
        out[(size_t)(c0 + ty + j) * R + r0 + tx] = tile[tx][ty + j];
}

__global__ void zero_k(float* __restrict__ p, size_t n4) {
    size_t i = (size_t)blockIdx.x * blockDim.x + threadIdx.x;
    if (i < n4) ((float4*)p)[i] = make_float4(0.f, 0.f, 0.f, 0.f);
}

__global__ void cvt_ctx_k(const float* __restrict__ in, __half* __restrict__ out) {
    int i = blockIdx.x * 256 + threadIdx.x;
    float2 v = ((const float2*)in)[i];
    __half2 h = __floats2half2_rn(v.x, v.y);
    ((__half2*)out)[i] = h;
}

__global__ void prep_k(const float* __restrict__ Wres, const float* __restrict__ g1,
                       const float* __restrict__ beta1) {
    int c = blockIdx.x * 8 + (threadIdx.x >> 5);
    int lane = threadIdx.x & 31;
    const float* wr = Wres + (size_t)c * C4;
    float s1 = 0.f, s2 = 0.f;
    for (int k = lane; k < C4; k += 32) {
        float w = wr[k], g = g1[k];
        __half hw = __float2half(g * w);
        g_Wg16[(size_t)c * C4 + k] = hw;
        s1 += __half2float(hw);       // match fp16-rounded GEMM weight exactly
        s2 += beta1[k] * w;
    }
#pragma unroll
    for (int o = 16; o; o >>= 1) {
        s1 += __shfl_xor_sync(0xffffffffu, s1, o);
        s2 += __shfl_xor_sync(0xffffffffu, s2, o);
    }
    if (lane == 0) { g_S1[c] = s1; g_S2[c] = s2; }
}

__global__ void cvt_wmlp_k(const float* __restrict__ w) {
    int i = blockIdx.x * 256 + threadIdx.x;
    g_Wmlp16[i] = __float2half(w[i]);
}

// ================= host launcher ================================================
typedef CUresult (*EncFn)(CUtensorMap*, CUtensorMapDataType, cuuint32_t, void*,
                          const cuuint64_t*, const cuuint64_t*, const cuuint32_t*,
                          const cuuint32_t*, CUtensorMapInterleave, CUtensorMapSwizzle,
                          CUtensorMapL2promotion, CUtensorMapFloatOOBfill);

static void mk_map(EncFn enc, CUtensorMap* m, void* ptr,
                   uint64_t d0, uint64_t d1, uint64_t d2,
                   uint64_t str1B, uint64_t str2B,
                   uint32_t box0, uint32_t box1, CUtensorMapDataType dt) {
    cuuint64_t dims[3] = {d0, d1, d2};
    cuuint64_t strides[2] = {str1B, str2B};
    cuuint32_t box[3] = {box0, box1, 1};
    cuuint32_t es[3] = {1, 1, 1};
    enc(m, dt, 3, ptr, dims, strides, box, es,
        CU_TENSOR_MAP_INTERLEAVE_NONE, CU_TENSOR_MAP_SWIZZLE_128B,
        CU_TENSOR_MAP_L2_PROMOTION_L2_128B, CU_TENSOR_MAP_FLOAT_OOB_FILL_NONE);
}

extern "C" void kernel_launch(void* const* d_in, const int* in_sizes, int n_in,
                              void* d_out, int out_size) {
    (void)in_sizes; (void)n_in; (void)out_size;
    const float* x     = (const float*)d_in[0];
    const float* Wqkv  = (const float*)d_in[1];
    const float* Wmlp  = (const float*)d_in[2];
    const float* bmlp  = (const float*)d_in[3];
    const float* g1    = (const float*)d_in[4];
    const float* beta1 = (const float*)d_in[5];
    const float* Wres  = (const float*)d_in[6];
    const float* g2    = (const float*)d_in[7];
    const float* beta2 = (const float*)d_in[8];
    float* outp = (float*)d_out;

    float *u, *ctx, *S1, *S2, *stats;
    __half *x1h, *sm16, *cat2h, *ctx16, *x1t16, *vt16, *wg16, *wmlp16;
    cudaGetSymbolAddress((void**)&x1h, g_x1h);
    cudaGetSymbolAddress((void**)&sm16, g_sm16);
    cudaGetSymbolAddress((void**)&u, g_u);
    cudaGetSymbolAddress((void**)&cat2h, g_cat2);
    cudaGetSymbolAddress((void**)&ctx, g_ctx);
    cudaGetSymbolAddress((void**)&ctx16, g_ctx16);
    cudaGetSymbolAddress((void**)&x1t16, g_x1t16);
    cudaGetSymbolAddress((void**)&vt16, g_vt16);
    cudaGetSymbolAddress((void**)&wg16, g_Wg16);
    cudaGetSymbolAddress((void**)&wmlp16, g_Wmlp16);
    cudaGetSymbolAddress((void**)&S1, g_S1);
    cudaGetSymbolAddress((void**)&S2, g_S2);
    cudaGetSymbolAddress((void**)&stats, g_stats);
    float* rsum0 = stats;
    float* rsq0  = stats + ROWS;
    float* rsum1 = stats + 2 * ROWS;
    float* rsq1  = stats + 3 * ROWS;

    EncFn enc = nullptr;
    cudaDriverEntryPointQueryResult qr;
    cudaGetDriverEntryPoint("cuTensorMapEncodeTiled", (void**)&enc,
                            cudaEnableDefault, &qr);
    CUtensorMap mU, mWqkv, mSm16, mCtx16, mCat2h, mWmlp16, mWg16, mVt16, mX1t16;
    mk_map(enc, &mU, u, 256, 32768, 1, 1024, (uint64_t)32768 * 1024, 32, 128,
           CU_TENSOR_MAP_DATA_TYPE_FLOAT32);
    mk_map(enc, &mWqkv, (void*)Wqkv, 256, 256, 1, 1024, 256 * 1024, 32, 256,
           CU_TENSOR_MAP_DATA_TYPE_FLOAT32);
    mk_map(enc, &mSm16, sm16, 256, 4096, 8, 512, (uint64_t)4096 * 512, 64, 128,
           CU_TENSOR_MAP_DATA_TYPE_FLOAT16);
    mk_map(enc, &mCtx16, ctx16, 256, 256, 8, 512, 256 * 512, 64, 256,
           CU_TENSOR_MAP_DATA_TYPE_FLOAT16);
    mk_map(enc, &mCat2h, cat2h, 1024, 32768, 1, 2048, (uint64_t)32768 * 2048, 64, 128,
           CU_TENSOR_MAP_DATA_TYPE_FLOAT16);
    mk_map(enc, &mWmlp16, wmlp16, 512, 512, 1, 1024, 512 * 1024, 64, 256,
           CU_TENSOR_MAP_DATA_TYPE_FLOAT16);
    mk_map(enc, &mWg16, wg16, 1024, 256, 1, 2048, 256 * 2048, 64, 256,
           CU_TENSOR_MAP_DATA_TYPE_FLOAT16);
    mk_map(enc, &mVt16, vt16, 4096, 256, 8, 8192, (uint64_t)256 * 8192, 64, 128,
           CU_TENSOR_MAP_DATA_TYPE_FLOAT16);
    mk_map(enc, &mX1t16, x1t16, 4096, 256, 8, 8192, (uint64_t)256 * 8192, 64, 256,
           CU_TENSOR_MAP_DATA_TYPE_FLOAT16);

    cudaFuncSetAttribute(gemm_t5<8, 1, 0>, cudaFuncAttributeMaxDynamicSharedMemorySize, T5_SMEM);
    cudaFuncSetAttribute(gemm_t5<4, 1, 1>, cudaFuncAttributeMaxDynamicSharedMemorySize, T5_SMEM);
    cudaFuncSetAttribute(gemm_t5<5, 1, 1>, cudaFuncAttributeMaxDynamicSharedMemorySize, T5_SMEM);
    cudaFuncSetAttribute(gemm_t5<16, 1, 1>, cudaFuncAttributeMaxDynamicSharedMemorySize, T5_SMEM);
    cudaFuncSetAttribute(gemm_t5<17, 1, 1>, cudaFuncAttributeMaxDynamicSharedMemorySize, T5_SMEM);
    cudaFuncSetAttribute(gemm_t5<32, 8, 1>, cudaFuncAttributeMaxDynamicSharedMemorySize, T5_SMEM);

    __half* vbufh = cat2h + 256;   // v lives in cat2[:,256:512), ld C4, fp16

    dim3 ttb(32, 8);
    transpose_k<<<dim3(Ntok / 32, Cdim / 32, Bsz), ttb>>>(
        x, u, Cdim, Ntok, Ntok, (long long)Cdim * Ntok, (long long)Cdim * Ntok);

    zero_k<<<(4 * ROWS / 4 + 255) / 256, 256>>>(stats, 4 * ROWS / 4);
    prep_k<<<Cdim / 8, 256>>>(Wres, g1, beta1);
    cvt_wmlp_k<<<512 * 512 / 256, 256>>>(Wmlp);

    // qkv fused: x1 f16, softmax->sm16 f16, v->cat2 f16, x1T/vT drains, LN1 stats
    gemm_t5<8, 1, 0><<<dim3(1, ROWS / 128, 1), 256, T5_SMEM>>>(
        mU, mWqkv, u, Cdim, 0, Wqkv, Cdim, 0, (float*)x1h, Cdim, 0, Cdim,
        nullptr, nullptr, 0, nullptr, nullptr, nullptr, nullptr,
        rsum0, rsq0, 0, sm16, vbufh, nullptr, nullptr, nullptr, x1t16, vt16);

    for (int it = 0; it < 2; ++it) {
        float* rs = it == 0 ? rsum0 : rsum1;
        float* rq = it == 0 ? rsq0 : rsq1;

        // g_ctx[d][c] = sum_n vT[d][n] * x1T[c][n]  (f16 tcgen05 NT, split-K 8, atomic f32)
        zero_k<<<(Bsz * Cdim * Cdim / 4 + 255) / 256, 256>>>(ctx, (size_t)Bsz * Cdim * Cdim / 4);
        gemm_t5<32, 8, 1><<<dim3(1, 2, Bsz * 8), 256, T5_SMEM>>>(
            mVt16, mX1t16, nullptr, 0, 0, nullptr, 0, 0,
            ctx, Cdim, (long long)Cdim * Cdim, Ntok,
            nullptr, nullptr, 0, nullptr, nullptr, nullptr, nullptr,
            nullptr, nullptr, 0, nullptr, nullptr, nullptr, nullptr, nullptr,
            nullptr, nullptr);
        cvt_ctx_k<<<Bsz * Cdim * Cdim / 2 / 256, 256>>>(ctx, ctx16);

        // out = sm16 @ ctx16 -> cat2[:,0:256] (f16), + stats (K=256 halves)
        gemm_t5<4, 1, 1><<<dim3(1, Ntok / 128, Bsz), 256, T5_SMEM>>>(
            mSm16, mCtx16, nullptr, 0, 0, nullptr, 0, 0,
            u, Cdim, (long long)Ntok * C4, Cdim,
            nullptr, nullptr, 0, nullptr, nullptr, nullptr, nullptr,
            rs, rq, Ntok, nullptr, cat2h, nullptr, nullptr, nullptr,
            nullptr, nullptr);

        // mlp = relu(cat1 @ Wmlp16^T + b) -> cat2[:,512:1024] (f16), K=512 halves
        gemm_t5<5, 1, 1><<<dim3(2, ROWS / 128, 1), 256, T5_SMEM>>>(
            mCat2h, mWmlp16, nullptr, 0, 0, nullptr, 0, 0, u, Cdim, 0, 512,
            bmlp, nullptr, 0, nullptr, nullptr, nullptr, nullptr,
            rs, rq, 0, nullptr, cat2h + 512, nullptr, nullptr, nullptr,
            nullptr, nullptr);

        // res + LN2 fused (K=1024 halves); rs/rq via mu/rinv slots, resid = x1h f16
        if (it == 0) {
            gemm_t5<16, 1, 1><<<dim3(1, ROWS / 128, 1), 256, T5_SMEM>>>(
                mCat2h, mWg16, nullptr, 0, 0, nullptr, 0, 0, u, Cdim, 0, C4,
                nullptr, x1h, Cdim, rs, rq, S1, S2,
                rsum1, rsq1, 0, nullptr, vbufh, g2, beta2, nullptr,
                nullptr, vt16);
        } else {
            gemm_t5<17, 1, 1><<<dim3(1, ROWS / 128, 1), 256, T5_SMEM>>>(
                mCat2h, mWg16, nullptr, 0, 0, nullptr, 0, 0, u, Cdim, 0, C4,
                nullptr, x1h, Cdim, rs, rq, S1, S2,
                nullptr, nullptr, 0, nullptr, nullptr, g2, beta2, outp,
                nullptr, nullptr);
        }
    }
}